// round 5
// baseline (speedup 1.0000x reference)
#include <cuda_runtime.h>
#include <math.h>

// ---------------------------------------------------------------------------
// Problem constants
// ---------------------------------------------------------------------------
#define NNODES  10000
#define NHEDGES 512
#define EDIM    128
#define TOPK    32
#define ALPHA   3.0f

// ---------------------------------------------------------------------------
// Scratch (device globals -- no runtime allocation allowed)
// ---------------------------------------------------------------------------
__device__ float g_nv1[NNODES * EDIM];
__device__ float g_nv2[NHEDGES * EDIM];
__device__ float g_H[NNODES * NHEDGES];

// packed fp32x2 FMA: two independent IEEE fma.rn.f32 -> bit-identical to fmaf
#define FMA_F32X2(d, a, b) \
    asm("fma.rn.f32x2 %0, %1, %2, %0;" : "+l"(d) : "l"(a), "l"(b))
#define DUP_F32X2(d, x) \
    asm("mov.b64 %0, {%1, %1};" : "=l"(d) : "r"(x))
#define UNPK_F32X2(lo, hi, in) \
    asm("mov.b64 {%0, %1}, %2;" : "=r"(lo), "=r"(hi) : "l"(in))

// ---------------------------------------------------------------------------
// Kernel 1: nodevec = tanh(ALPHA*(emb[row]@W + b))
// ---------------------------------------------------------------------------
__global__ void __launch_bounds__(EDIM) nodevec_kernel(
    const float* __restrict__ emb,
    const int*   __restrict__ idx,
    const float* __restrict__ W,
    const float* __restrict__ b,
    float*       __restrict__ out)
{
    __shared__ float s_in[EDIM];
    const int r   = blockIdx.x;
    const int d   = threadIdx.x;
    const int src = idx ? idx[r] : r;
    s_in[d] = emb[(size_t)src * EDIM + d];
    __syncthreads();

    float acc = b[d];
#pragma unroll 8
    for (int k = 0; k < EDIM; k++)
        acc = fmaf(s_in[k], W[k * EDIM + d], acc);

    out[(size_t)r * EDIM + d] = tanhf(ALPHA * acc);
}

// ---------------------------------------------------------------------------
// Kernel 2: H = relu(tanh(3 * nv1 @ nv2^T))  -- unchanged (proven bit-path).
// ---------------------------------------------------------------------------
#define GT_TM 128
#define GT_BK 16

__global__ void __launch_bounds__(256, 2) h_gemm_kernel(
    const float* __restrict__ A,
    const float* __restrict__ B,
    float*       __restrict__ C,
    int M, int N, int Kd)
{
    __shared__ __align__(16) float As[2][GT_BK][GT_TM];
    __shared__ __align__(16) float Bs[2][GT_BK][GT_TM];

    const int tid = threadIdx.x;
    const int bm  = blockIdx.y * GT_TM;
    const int bn  = blockIdx.x * GT_TM;
    const int tx  = tid & 15;
    const int ty  = tid >> 4;

    float acc[8][8];
#pragma unroll
    for (int i = 0; i < 8; i++)
#pragma unroll
        for (int j = 0; j < 8; j++) acc[i][j] = 0.0f;

    auto stage = [&](int buf, int k0) {
#pragma unroll
        for (int s = 0; s < 2; s++) {
            const int f  = tid + s * 256;
            const int r  = f >> 2;
            const int kq = (f & 3) << 2;
            const int ga = bm + r;
            float4 va = make_float4(0.f, 0.f, 0.f, 0.f);
            if (ga < M)
                va = *reinterpret_cast<const float4*>(A + (size_t)ga * Kd + k0 + kq);
            As[buf][kq + 0][r] = va.x; As[buf][kq + 1][r] = va.y;
            As[buf][kq + 2][r] = va.z; As[buf][kq + 3][r] = va.w;

            const int gb = bn + r;
            float4 vb = make_float4(0.f, 0.f, 0.f, 0.f);
            if (gb < N)
                vb = *reinterpret_cast<const float4*>(B + (size_t)gb * Kd + k0 + kq);
            Bs[buf][kq + 0][r] = vb.x; Bs[buf][kq + 1][r] = vb.y;
            Bs[buf][kq + 2][r] = vb.z; Bs[buf][kq + 3][r] = vb.w;
        }
    };

    stage(0, 0);
    __syncthreads();

    const int nk = Kd / GT_BK;
    for (int kt = 0; kt < nk; kt++) {
        const int cur = kt & 1;
        if (kt + 1 < nk) stage(cur ^ 1, (kt + 1) * GT_BK);

#pragma unroll
        for (int kk = 0; kk < GT_BK; kk++) {
            float a[8], b[8];
#pragma unroll
            for (int i = 0; i < 8; i += 4)
                *reinterpret_cast<float4*>(&a[i]) =
                    *reinterpret_cast<const float4*>(&As[cur][kk][ty * 8 + i]);
#pragma unroll
            for (int j = 0; j < 8; j += 4)
                *reinterpret_cast<float4*>(&b[j]) =
                    *reinterpret_cast<const float4*>(&Bs[cur][kk][tx * 8 + j]);
#pragma unroll
            for (int i = 0; i < 8; i++)
#pragma unroll
                for (int j = 0; j < 8; j++)
                    acc[i][j] = fmaf(a[i], b[j], acc[i][j]);
        }
        __syncthreads();
    }

#pragma unroll
    for (int i = 0; i < 8; i++) {
        const int gr = bm + ty * 8 + i;
        if (gr >= M) continue;
        float* crow = C + (size_t)gr * N;
#pragma unroll
        for (int j = 0; j < 8; j += 4) {
            const int gc = bn + tx * 8 + j;
            float4 v;
            v.x = fmaxf(tanhf(ALPHA * acc[i][j + 0]), 0.0f);
            v.y = fmaxf(tanhf(ALPHA * acc[i][j + 1]), 0.0f);
            v.z = fmaxf(tanhf(ALPHA * acc[i][j + 2]), 0.0f);
            v.w = fmaxf(tanhf(ALPHA * acc[i][j + 3]), 0.0f);
            if (gc + 3 < N) {
                *reinterpret_cast<float4*>(crow + gc) = v;
            } else {
                const float vv[4] = {v.x, v.y, v.z, v.w};
                for (int q = 0; q < 4; q++)
                    if (gc + q < N) crow[gc + q] = vv[q];
            }
        }
    }
}

// ---------------------------------------------------------------------------
// Kernel 3: adj = H @ H^T, packed fma.rn.f32x2 (bit-identical to scalar fmaf,
// each accumulator keeps sequential-k order). Symmetric: bx >= by tiles only;
// mirror tile written via padded SMEM transpose.
// ---------------------------------------------------------------------------
#define ADJ_SMEM_BYTES (128 * 133 * 4)   // epilogue union >= 32KB mainloop

__global__ void __launch_bounds__(256, 2) adj_sym_kernel(
    const float* __restrict__ A,
    float*       __restrict__ C,
    int M, int Kd)
{
    extern __shared__ __align__(16) float smem_pool[];

    const int by = blockIdx.y, bx = blockIdx.x;
    if (bx < by) return;

    float (*As)[GT_BK][GT_TM] = reinterpret_cast<float (*)[GT_BK][GT_TM]>(smem_pool);
    float (*Bs)[GT_BK][GT_TM] =
        reinterpret_cast<float (*)[GT_BK][GT_TM]>(smem_pool + 2 * GT_BK * GT_TM);

    const int tid = threadIdx.x;
    const int bm  = by * GT_TM;
    const int bn  = bx * GT_TM;
    const int tx  = tid & 15;
    const int ty  = tid >> 4;

    // packed accumulators: acc2[i][jp] = (acc[i][2jp], acc[i][2jp+1])
    unsigned long long acc2[8][4];
#pragma unroll
    for (int i = 0; i < 8; i++)
#pragma unroll
        for (int jp = 0; jp < 4; jp++) acc2[i][jp] = 0ull;

    auto stage = [&](int buf, int k0) {
#pragma unroll
        for (int s = 0; s < 2; s++) {
            const int f  = tid + s * 256;
            const int r  = f >> 2;
            const int kq = (f & 3) << 2;
            const int ga = bm + r;
            float4 va = make_float4(0.f, 0.f, 0.f, 0.f);
            if (ga < M)
                va = *reinterpret_cast<const float4*>(A + (size_t)ga * Kd + k0 + kq);
            As[buf][kq + 0][r] = va.x; As[buf][kq + 1][r] = va.y;
            As[buf][kq + 2][r] = va.z; As[buf][kq + 3][r] = va.w;

            const int gb = bn + r;
            float4 vb = make_float4(0.f, 0.f, 0.f, 0.f);
            if (gb < M)
                vb = *reinterpret_cast<const float4*>(A + (size_t)gb * Kd + k0 + kq);
            Bs[buf][kq + 0][r] = vb.x; Bs[buf][kq + 1][r] = vb.y;
            Bs[buf][kq + 2][r] = vb.z; Bs[buf][kq + 3][r] = vb.w;
        }
    };

    stage(0, 0);
    __syncthreads();

    const int nk = Kd / GT_BK;
    for (int kt = 0; kt < nk; kt++) {
        const int cur = kt & 1;
        if (kt + 1 < nk) stage(cur ^ 1, (kt + 1) * GT_BK);

#pragma unroll
        for (int kk = 0; kk < GT_BK; kk++) {
            float a[8];
#pragma unroll
            for (int i = 0; i < 8; i += 4)
                *reinterpret_cast<float4*>(&a[i]) =
                    *reinterpret_cast<const float4*>(&As[cur][kk][ty * 8 + i]);

            // b pairs read directly as packed u64 (contiguous, 16B-aligned)
            unsigned long long bb[4];
            const unsigned long long* bp =
                reinterpret_cast<const unsigned long long*>(&Bs[cur][kk][tx * 8]);
#pragma unroll
            for (int jp = 0; jp < 4; jp++) bb[jp] = bp[jp];

            unsigned long long ad[8];
#pragma unroll
            for (int i = 0; i < 8; i++)
                DUP_F32X2(ad[i], __float_as_uint(a[i]));

#pragma unroll
            for (int i = 0; i < 8; i++)
#pragma unroll
                for (int jp = 0; jp < 4; jp++)
                    FMA_F32X2(acc2[i][jp], ad[i], bb[jp]);
        }
        __syncthreads();
    }

    // ---- epilogue: direct tile (coalesced) + mirror via SMEM transpose ----
    float* Ct = smem_pool;                       // [128][133]
#define CT(r, c) Ct[(r) * 133 + (c)]

#pragma unroll
    for (int i = 0; i < 8; i++) {
        const int r0 = ty * 8 + i;
        const int gr = bm + r0;
#pragma unroll
        for (int jp = 0; jp < 4; jp += 2) {
            const int c0 = tx * 8 + jp * 2;
            unsigned u0, u1, u2, u3;
            UNPK_F32X2(u0, u1, acc2[i][jp]);
            UNPK_F32X2(u2, u3, acc2[i][jp + 1]);
            const float v0 = __uint_as_float(u0), v1 = __uint_as_float(u1);
            const float v2 = __uint_as_float(u2), v3 = __uint_as_float(u3);

            CT(r0, c0 + 0) = v0; CT(r0, c0 + 1) = v1;
            CT(r0, c0 + 2) = v2; CT(r0, c0 + 3) = v3;

            if (gr < M) {
                const int gc = bn + c0;
                if (gc + 3 < M) {
                    *reinterpret_cast<float4*>(C + (size_t)gr * M + gc) =
                        make_float4(v0, v1, v2, v3);
                } else {
                    const float vv[4] = {v0, v1, v2, v3};
                    for (int q = 0; q < 4; q++)
                        if (gc + q < M) C[(size_t)gr * M + gc + q] = vv[q];
                }
            }
        }
    }
    __syncthreads();

    for (int i = tid; i < 128 * 128; i += 256) {
        const int r2 = i >> 7;
        const int c2 = i & 127;
        const int gR = bn + r2, gC = bm + c2;
        if (gR < M && gC < M)
            C[(size_t)gR * M + gC] = CT(c2, r2);
    }
#undef CT
}

// ---------------------------------------------------------------------------
// Kernel 4: per-row top-K mask. Warp-aggregated histogram atomics
// (__match_any_sync) + parallel suffix-scan bucket search. Exact jax ties.
// ---------------------------------------------------------------------------
__global__ void __launch_bounds__(256) topk_mask_kernel(float* __restrict__ adj, int N)
{
    __shared__ float    s_val[NNODES];
    __shared__ unsigned s_hist[256];
    __shared__ unsigned s_scan[256];
    __shared__ unsigned s_prefix;
    __shared__ int      s_rank, s_cnt;

    const int    tid  = threadIdx.x;
    const size_t base = (size_t)blockIdx.x * N;

    for (int j = tid; j < N; j += 256) s_val[j] = adj[base + j];
    __syncthreads();

    unsigned prefix = 0u;
    int      rank   = TOPK;
    int      cnt_eq = 0;

    for (int shift = 24; shift >= 0; shift -= 8) {
        s_hist[tid] = 0;
        __syncthreads();

        const unsigned hmask = (shift == 24) ? 0u : (0xFFFFFFFFu << (shift + 8));
        for (int j0 = 0; j0 < N; j0 += 256) {       // convergent: all threads
            const int j = j0 + tid;
            bool pred = false;
            unsigned k = 0u, bin = 0u;
            if (j < N) {
                k    = __float_as_uint(s_val[j]);
                pred = ((k & hmask) == prefix);
                bin  = (k >> shift) & 0xFFu;
            }
            const unsigned ballot = __ballot_sync(0xFFFFFFFFu, pred);
            if (pred) {
                const unsigned peers = __match_any_sync(ballot, bin);
                if ((tid & 31) == (__ffs(peers) - 1))
                    atomicAdd(&s_hist[bin], __popc(peers));
            }
        }
        __syncthreads();

        // parallel suffix sum: s_scan[b] = sum_{b' >= b} hist[b']
        const unsigned h = s_hist[tid];
        s_scan[tid] = h;
        __syncthreads();
#pragma unroll
        for (int off = 1; off < 256; off <<= 1) {
            const unsigned v   = s_scan[tid];
            const unsigned add = (tid + off < 256) ? s_scan[tid + off] : 0u;
            __syncthreads();
            s_scan[tid] = v + add;
            __syncthreads();
        }
        const unsigned Sb  = s_scan[tid];
        const unsigned Sb1 = (tid < 255) ? s_scan[tid + 1] : 0u;
        if ((int)Sb >= rank && (int)Sb1 < rank) {
            s_prefix = prefix | ((unsigned)tid << shift);
            s_rank   = rank - (int)Sb1;
            s_cnt    = (int)(Sb - Sb1);
        }
        __syncthreads();
        prefix = s_prefix;
        rank   = s_rank;
        cnt_eq = s_cnt;
        __syncthreads();
    }

    const float Tval = __uint_as_float(prefix);

    if (cnt_eq > rank) {
        // ties at the threshold: keep only the first `rank` by index (rare).
        if (tid == 0) {
            int kept = 0;
            for (int j = 0; j < N; j++) {
                if (__float_as_uint(s_val[j]) == prefix) {
                    kept++;
                    if (kept > rank) s_val[j] = -1.0f;
                }
            }
        }
        __syncthreads();
    }

    for (int j = tid; j < N; j += 256) {
        const float v = s_val[j];
        adj[base + j] = (v >= Tval) ? v : 0.0f;
    }
}

// ---------------------------------------------------------------------------
// kernel_launch
// ---------------------------------------------------------------------------
extern "C" void kernel_launch(void* const* d_in, const int* in_sizes, int n_in,
                              void* d_out, int out_size)
{
    (void)in_sizes; (void)n_in; (void)out_size;

    const int*   idx   = (const int*)  d_in[0];
    const float* embn  = (const float*)d_in[1];
    const float* embhe = (const float*)d_in[2];
    const float* W1    = (const float*)d_in[3];
    const float* b1    = (const float*)d_in[4];
    const float* W2    = (const float*)d_in[5];
    const float* b2    = (const float*)d_in[6];
    float*       out   = (float*)d_out;

    float *p_nv1 = nullptr, *p_nv2 = nullptr, *p_H = nullptr;
    cudaGetSymbolAddress((void**)&p_nv1, g_nv1);
    cudaGetSymbolAddress((void**)&p_nv2, g_nv2);
    cudaGetSymbolAddress((void**)&p_H,   g_H);

    cudaFuncSetAttribute(adj_sym_kernel,
                         cudaFuncAttributeMaxDynamicSharedMemorySize,
                         ADJ_SMEM_BYTES);

    // 1) nodevecs
    nodevec_kernel<<<NNODES, EDIM>>>(embn, idx, W1, b1, p_nv1);
    nodevec_kernel<<<NHEDGES, EDIM>>>(embhe, nullptr, W2, b2, p_nv2);

    // 2) H = relu(tanh(3 * nv1 @ nv2^T))   [10000,512]
    {
        dim3 grid((NHEDGES + GT_TM - 1) / GT_TM, (NNODES + GT_TM - 1) / GT_TM);
        h_gemm_kernel<<<grid, 256>>>(p_nv1, p_nv2, p_H, NNODES, NHEDGES, EDIM);
    }

    // 3) adj = H @ H^T (fma.rn.f32x2, bit-identical; symmetric tiles)
    {
        const int nt = (NNODES + GT_TM - 1) / GT_TM;
        dim3 grid(nt, nt);
        adj_sym_kernel<<<grid, 256, ADJ_SMEM_BYTES>>>(p_H, out, NNODES, NHEDGES);
    }

    // 4) per-row top-32 mask, in place
    topk_mask_kernel<<<NNODES, 256>>>(out, NNODES);
}

// round 6
// speedup vs baseline: 1.0228x; 1.0228x over previous
#include <cuda_runtime.h>
#include <math.h>

// ---------------------------------------------------------------------------
// Problem constants
// ---------------------------------------------------------------------------
#define NNODES  10000
#define NHEDGES 512
#define EDIM    128
#define TOPK    32
#define ALPHA   3.0f

// ---------------------------------------------------------------------------
// Scratch (device globals -- no runtime allocation allowed)
// ---------------------------------------------------------------------------
__device__ float g_nv1[NNODES * EDIM];
__device__ float g_nv2[NHEDGES * EDIM];
__device__ float g_H[NNODES * NHEDGES];

// ---------------------------------------------------------------------------
// Kernel 1: nodevec = tanh(ALPHA*(emb[row]@W + b)), 8 rows per block,
// W cached in SMEM (one load per block instead of per row).
// Bit path per output: ascending-k single-accumulator fmaf (unchanged).
// ---------------------------------------------------------------------------
#define NV_ROWS 8
#define NV_SMEM ((EDIM * EDIM + NV_ROWS * EDIM) * 4)   // 69632 B

__global__ void __launch_bounds__(EDIM) nodevec_kernel(
    const float* __restrict__ emb,
    const int*   __restrict__ idx,
    const float* __restrict__ W,
    const float* __restrict__ b,
    float*       __restrict__ out,
    int nrows)
{
    extern __shared__ __align__(16) float nv_smem[];
    float* sW   = nv_smem;                 // [128][128]
    float* s_in = nv_smem + EDIM * EDIM;   // [8][128]

    const int tid = threadIdx.x;
    const int r0  = blockIdx.x * NV_ROWS;

    // cooperative W load (float4)
    const float4* Wv = reinterpret_cast<const float4*>(W);
    float4*       sWv = reinterpret_cast<float4*>(sW);
#pragma unroll
    for (int i = 0; i < (EDIM * EDIM / 4) / EDIM; i++)
        sWv[i * EDIM + tid] = Wv[i * EDIM + tid];

    // gather 8 input rows
#pragma unroll
    for (int q = 0; q < NV_ROWS; q++) {
        const int r  = r0 + q;
        const int sr = (r < nrows) ? (idx ? idx[r] : r) : 0;
        s_in[q * EDIM + tid] = emb[(size_t)sr * EDIM + tid];
    }
    __syncthreads();

    float acc[NV_ROWS];
    const float bd = b[tid];
#pragma unroll
    for (int q = 0; q < NV_ROWS; q++) acc[q] = bd;

#pragma unroll 4
    for (int k = 0; k < EDIM; k++) {
        const float w = sW[k * EDIM + tid];
#pragma unroll
        for (int q = 0; q < NV_ROWS; q++)
            acc[q] = fmaf(s_in[q * EDIM + k], w, acc[q]);
    }

#pragma unroll
    for (int q = 0; q < NV_ROWS; q++) {
        const int r = r0 + q;
        if (r < nrows)
            out[(size_t)r * EDIM + tid] = tanhf(ALPHA * acc[q]);
    }
}

// ---------------------------------------------------------------------------
// Kernel 2: H = relu(tanh(3 * nv1 @ nv2^T))  -- unchanged (proven bit-path).
// ---------------------------------------------------------------------------
#define GT_TM 128
#define GT_BK 16

__global__ void __launch_bounds__(256, 2) h_gemm_kernel(
    const float* __restrict__ A,
    const float* __restrict__ B,
    float*       __restrict__ C,
    int M, int N, int Kd)
{
    __shared__ __align__(16) float As[2][GT_BK][GT_TM];
    __shared__ __align__(16) float Bs[2][GT_BK][GT_TM];

    const int tid = threadIdx.x;
    const int bm  = blockIdx.y * GT_TM;
    const int bn  = blockIdx.x * GT_TM;
    const int tx  = tid & 15;
    const int ty  = tid >> 4;

    float acc[8][8];
#pragma unroll
    for (int i = 0; i < 8; i++)
#pragma unroll
        for (int j = 0; j < 8; j++) acc[i][j] = 0.0f;

    auto stage = [&](int buf, int k0) {
#pragma unroll
        for (int s = 0; s < 2; s++) {
            const int f  = tid + s * 256;
            const int r  = f >> 2;
            const int kq = (f & 3) << 2;
            const int ga = bm + r;
            float4 va = make_float4(0.f, 0.f, 0.f, 0.f);
            if (ga < M)
                va = *reinterpret_cast<const float4*>(A + (size_t)ga * Kd + k0 + kq);
            As[buf][kq + 0][r] = va.x; As[buf][kq + 1][r] = va.y;
            As[buf][kq + 2][r] = va.z; As[buf][kq + 3][r] = va.w;

            const int gb = bn + r;
            float4 vb = make_float4(0.f, 0.f, 0.f, 0.f);
            if (gb < N)
                vb = *reinterpret_cast<const float4*>(B + (size_t)gb * Kd + k0 + kq);
            Bs[buf][kq + 0][r] = vb.x; Bs[buf][kq + 1][r] = vb.y;
            Bs[buf][kq + 2][r] = vb.z; Bs[buf][kq + 3][r] = vb.w;
        }
    };

    stage(0, 0);
    __syncthreads();

    const int nk = Kd / GT_BK;
    for (int kt = 0; kt < nk; kt++) {
        const int cur = kt & 1;
        if (kt + 1 < nk) stage(cur ^ 1, (kt + 1) * GT_BK);

#pragma unroll
        for (int kk = 0; kk < GT_BK; kk++) {
            float a[8], b[8];
#pragma unroll
            for (int i = 0; i < 8; i += 4)
                *reinterpret_cast<float4*>(&a[i]) =
                    *reinterpret_cast<const float4*>(&As[cur][kk][ty * 8 + i]);
#pragma unroll
            for (int j = 0; j < 8; j += 4)
                *reinterpret_cast<float4*>(&b[j]) =
                    *reinterpret_cast<const float4*>(&Bs[cur][kk][tx * 8 + j]);
#pragma unroll
            for (int i = 0; i < 8; i++)
#pragma unroll
                for (int j = 0; j < 8; j++)
                    acc[i][j] = fmaf(a[i], b[j], acc[i][j]);
        }
        __syncthreads();
    }

#pragma unroll
    for (int i = 0; i < 8; i++) {
        const int gr = bm + ty * 8 + i;
        if (gr >= M) continue;
        float* crow = C + (size_t)gr * N;
#pragma unroll
        for (int j = 0; j < 8; j += 4) {
            const int gc = bn + tx * 8 + j;
            float4 v;
            v.x = fmaxf(tanhf(ALPHA * acc[i][j + 0]), 0.0f);
            v.y = fmaxf(tanhf(ALPHA * acc[i][j + 1]), 0.0f);
            v.z = fmaxf(tanhf(ALPHA * acc[i][j + 2]), 0.0f);
            v.w = fmaxf(tanhf(ALPHA * acc[i][j + 3]), 0.0f);
            if (gc + 3 < N) {
                *reinterpret_cast<float4*>(crow + gc) = v;
            } else {
                const float vv[4] = {v.x, v.y, v.z, v.w};
                for (int q = 0; q < 4; q++)
                    if (gc + q < N) crow[gc + q] = vv[q];
            }
        }
    }
}

// ---------------------------------------------------------------------------
// Kernel 3: adj = H @ H^T, scalar fmaf (bit-identical sequential-k chain),
// BK=32 (half the barriers of R4, 2x scheduling window per region).
// Symmetric: bx >= by tiles only; mirror via padded SMEM transpose.
// SMEM union: mainloop As/Bs[2][32][128] = 64KB; epilogue Ct 128x133 = 68096B.
// ---------------------------------------------------------------------------
#define BK2 32
#define ADJ_SMEM_BYTES (128 * 133 * 4)   // 68096 >= 65536

__global__ void __launch_bounds__(256, 2) adj_sym_kernel(
    const float* __restrict__ A,
    float*       __restrict__ C,
    int M, int Kd)
{
    extern __shared__ __align__(16) float smem_pool[];

    const int by = blockIdx.y, bx = blockIdx.x;
    if (bx < by) return;

    float (*As)[BK2][GT_TM] = reinterpret_cast<float (*)[BK2][GT_TM]>(smem_pool);
    float (*Bs)[BK2][GT_TM] =
        reinterpret_cast<float (*)[BK2][GT_TM]>(smem_pool + 2 * BK2 * GT_TM);

    const int tid = threadIdx.x;
    const int bm  = by * GT_TM;
    const int bn  = bx * GT_TM;
    const int tx  = tid & 15;
    const int ty  = tid >> 4;

    float acc[8][8];
#pragma unroll
    for (int i = 0; i < 8; i++)
#pragma unroll
        for (int j = 0; j < 8; j++) acc[i][j] = 0.0f;

    auto stage = [&](int buf, int k0) {
#pragma unroll
        for (int s = 0; s < 4; s++) {
            const int f  = tid + s * 256;        // 0..1023
            const int r  = f >> 3;               // 0..127
            const int kq = (f & 7) << 2;         // 0,4,...,28
            const int ga = bm + r;
            float4 va = make_float4(0.f, 0.f, 0.f, 0.f);
            if (ga < M)
                va = *reinterpret_cast<const float4*>(A + (size_t)ga * Kd + k0 + kq);
            As[buf][kq + 0][r] = va.x; As[buf][kq + 1][r] = va.y;
            As[buf][kq + 2][r] = va.z; As[buf][kq + 3][r] = va.w;

            const int gb = bn + r;
            float4 vb = make_float4(0.f, 0.f, 0.f, 0.f);
            if (gb < M)
                vb = *reinterpret_cast<const float4*>(A + (size_t)gb * Kd + k0 + kq);
            Bs[buf][kq + 0][r] = vb.x; Bs[buf][kq + 1][r] = vb.y;
            Bs[buf][kq + 2][r] = vb.z; Bs[buf][kq + 3][r] = vb.w;
        }
    };

    stage(0, 0);
    __syncthreads();

    const int nk = Kd / BK2;   // 16
    for (int kt = 0; kt < nk; kt++) {
        const int cur = kt & 1;
        if (kt + 1 < nk) stage(cur ^ 1, (kt + 1) * BK2);

#pragma unroll
        for (int kk = 0; kk < BK2; kk++) {
            float a[8], b[8];
#pragma unroll
            for (int i = 0; i < 8; i += 4)
                *reinterpret_cast<float4*>(&a[i]) =
                    *reinterpret_cast<const float4*>(&As[cur][kk][ty * 8 + i]);
#pragma unroll
            for (int j = 0; j < 8; j += 4)
                *reinterpret_cast<float4*>(&b[j]) =
                    *reinterpret_cast<const float4*>(&Bs[cur][kk][tx * 8 + j]);
#pragma unroll
            for (int i = 0; i < 8; i++)
#pragma unroll
                for (int j = 0; j < 8; j++)
                    acc[i][j] = fmaf(a[i], b[j], acc[i][j]);
        }
        __syncthreads();
    }

    // ---- epilogue: direct tile (coalesced) + mirror via SMEM transpose ----
    float* Ct = smem_pool;                       // [128][133]
#define CT(r, c) Ct[(r) * 133 + (c)]

#pragma unroll
    for (int i = 0; i < 8; i++) {
        const int r0 = ty * 8 + i;
        const int gr = bm + r0;
#pragma unroll
        for (int j = 0; j < 8; j += 4) {
            const int c0 = tx * 8 + j;
            const float v0 = acc[i][j + 0], v1 = acc[i][j + 1];
            const float v2 = acc[i][j + 2], v3 = acc[i][j + 3];
            CT(r0, c0 + 0) = v0; CT(r0, c0 + 1) = v1;
            CT(r0, c0 + 2) = v2; CT(r0, c0 + 3) = v3;

            if (gr < M) {
                const int gc = bn + c0;
                if (gc + 3 < M) {
                    *reinterpret_cast<float4*>(C + (size_t)gr * M + gc) =
                        make_float4(v0, v1, v2, v3);
                } else {
                    const float vv[4] = {v0, v1, v2, v3};
                    for (int q = 0; q < 4; q++)
                        if (gc + q < M) C[(size_t)gr * M + gc + q] = vv[q];
                }
            }
        }
    }
    __syncthreads();

    for (int i = tid; i < 128 * 128; i += 256) {
        const int r2 = i >> 7;
        const int c2 = i & 127;
        const int gR = bn + r2, gC = bm + c2;
        if (gR < M && gC < M)
            C[(size_t)gR * M + gC] = CT(c2, r2);
    }
#undef CT
}

// ---------------------------------------------------------------------------
// Kernel 4: per-row top-K mask (warp-aggregated histogram + suffix scan).
// ---------------------------------------------------------------------------
__global__ void __launch_bounds__(256) topk_mask_kernel(float* __restrict__ adj, int N)
{
    __shared__ float    s_val[NNODES];
    __shared__ unsigned s_hist[256];
    __shared__ unsigned s_scan[256];
    __shared__ unsigned s_prefix;
    __shared__ int      s_rank, s_cnt;

    const int    tid  = threadIdx.x;
    const size_t base = (size_t)blockIdx.x * N;

    for (int j = tid; j < N; j += 256) s_val[j] = adj[base + j];
    __syncthreads();

    unsigned prefix = 0u;
    int      rank   = TOPK;
    int      cnt_eq = 0;

    for (int shift = 24; shift >= 0; shift -= 8) {
        s_hist[tid] = 0;
        __syncthreads();

        const unsigned hmask = (shift == 24) ? 0u : (0xFFFFFFFFu << (shift + 8));
        for (int j0 = 0; j0 < N; j0 += 256) {
            const int j = j0 + tid;
            bool pred = false;
            unsigned k = 0u, bin = 0u;
            if (j < N) {
                k    = __float_as_uint(s_val[j]);
                pred = ((k & hmask) == prefix);
                bin  = (k >> shift) & 0xFFu;
            }
            const unsigned ballot = __ballot_sync(0xFFFFFFFFu, pred);
            if (pred) {
                const unsigned peers = __match_any_sync(ballot, bin);
                if ((tid & 31) == (__ffs(peers) - 1))
                    atomicAdd(&s_hist[bin], __popc(peers));
            }
        }
        __syncthreads();

        const unsigned h = s_hist[tid];
        s_scan[tid] = h;
        __syncthreads();
#pragma unroll
        for (int off = 1; off < 256; off <<= 1) {
            const unsigned v   = s_scan[tid];
            const unsigned add = (tid + off < 256) ? s_scan[tid + off] : 0u;
            __syncthreads();
            s_scan[tid] = v + add;
            __syncthreads();
        }
        const unsigned Sb  = s_scan[tid];
        const unsigned Sb1 = (tid < 255) ? s_scan[tid + 1] : 0u;
        if ((int)Sb >= rank && (int)Sb1 < rank) {
            s_prefix = prefix | ((unsigned)tid << shift);
            s_rank   = rank - (int)Sb1;
            s_cnt    = (int)(Sb - Sb1);
        }
        __syncthreads();
        prefix = s_prefix;
        rank   = s_rank;
        cnt_eq = s_cnt;
        __syncthreads();
    }

    const float Tval = __uint_as_float(prefix);

    if (cnt_eq > rank) {
        if (tid == 0) {
            int kept = 0;
            for (int j = 0; j < N; j++) {
                if (__float_as_uint(s_val[j]) == prefix) {
                    kept++;
                    if (kept > rank) s_val[j] = -1.0f;
                }
            }
        }
        __syncthreads();
    }

    for (int j = tid; j < N; j += 256) {
        const float v = s_val[j];
        adj[base + j] = (v >= Tval) ? v : 0.0f;
    }
}

// ---------------------------------------------------------------------------
// kernel_launch
// ---------------------------------------------------------------------------
extern "C" void kernel_launch(void* const* d_in, const int* in_sizes, int n_in,
                              void* d_out, int out_size)
{
    (void)in_sizes; (void)n_in; (void)out_size;

    const int*   idx   = (const int*)  d_in[0];
    const float* embn  = (const float*)d_in[1];
    const float* embhe = (const float*)d_in[2];
    const float* W1    = (const float*)d_in[3];
    const float* b1    = (const float*)d_in[4];
    const float* W2    = (const float*)d_in[5];
    const float* b2    = (const float*)d_in[6];
    float*       out   = (float*)d_out;

    float *p_nv1 = nullptr, *p_nv2 = nullptr, *p_H = nullptr;
    cudaGetSymbolAddress((void**)&p_nv1, g_nv1);
    cudaGetSymbolAddress((void**)&p_nv2, g_nv2);
    cudaGetSymbolAddress((void**)&p_H,   g_H);

    cudaFuncSetAttribute(adj_sym_kernel,
                         cudaFuncAttributeMaxDynamicSharedMemorySize,
                         ADJ_SMEM_BYTES);
    cudaFuncSetAttribute(nodevec_kernel,
                         cudaFuncAttributeMaxDynamicSharedMemorySize,
                         NV_SMEM);

    // 1) nodevecs (8 rows per block, W in SMEM)
    nodevec_kernel<<<NNODES / NV_ROWS, EDIM, NV_SMEM>>>(embn, idx, W1, b1,
                                                        p_nv1, NNODES);
    nodevec_kernel<<<NHEDGES / NV_ROWS, EDIM, NV_SMEM>>>(embhe, nullptr, W2, b2,
                                                         p_nv2, NHEDGES);

    // 2) H = relu(tanh(3 * nv1 @ nv2^T))   [10000,512]
    {
        dim3 grid((NHEDGES + GT_TM - 1) / GT_TM, (NNODES + GT_TM - 1) / GT_TM);
        h_gemm_kernel<<<grid, 256>>>(p_nv1, p_nv2, p_H, NNODES, NHEDGES, EDIM);
    }

    // 3) adj = H @ H^T (scalar fmaf, BK=32, symmetric tiles)
    {
        const int nt = (NNODES + GT_TM - 1) / GT_TM;
        dim3 grid(nt, nt);
        adj_sym_kernel<<<grid, 256, ADJ_SMEM_BYTES>>>(p_H, out, NNODES, NHEDGES);
    }

    // 4) per-row top-32 mask, in place
    topk_mask_kernel<<<NNODES, 256>>>(out, NNODES);
}

// round 7
// speedup vs baseline: 1.0709x; 1.0470x over previous
#include <cuda_runtime.h>
#include <math.h>

// ---------------------------------------------------------------------------
// Problem constants
// ---------------------------------------------------------------------------
#define NNODES  10000
#define NHEDGES 512
#define EDIM    128
#define TOPK    32
#define ALPHA   3.0f

// ---------------------------------------------------------------------------
// Scratch (device globals -- no runtime allocation allowed)
// ---------------------------------------------------------------------------
__device__ float g_nv1[NNODES * EDIM];
__device__ float g_nv2[NHEDGES * EDIM];
__device__ float g_H[NNODES * NHEDGES];

// ---------------------------------------------------------------------------
// Kernel 1: nodevec = tanh(ALPHA*(emb[row]@W + b)), 8 rows per block,
// W cached in SMEM. Bit path per output: ascending-k single-accumulator fmaf.
// ---------------------------------------------------------------------------
#define NV_ROWS 8
#define NV_SMEM ((EDIM * EDIM + NV_ROWS * EDIM) * 4)

__global__ void __launch_bounds__(EDIM) nodevec_kernel(
    const float* __restrict__ emb,
    const int*   __restrict__ idx,
    const float* __restrict__ W,
    const float* __restrict__ b,
    float*       __restrict__ out,
    int nrows)
{
    extern __shared__ __align__(16) float nv_smem[];
    float* sW   = nv_smem;
    float* s_in = nv_smem + EDIM * EDIM;

    const int tid = threadIdx.x;
    const int r0  = blockIdx.x * NV_ROWS;

    const float4* Wv  = reinterpret_cast<const float4*>(W);
    float4*       sWv = reinterpret_cast<float4*>(sW);
#pragma unroll
    for (int i = 0; i < (EDIM * EDIM / 4) / EDIM; i++)
        sWv[i * EDIM + tid] = Wv[i * EDIM + tid];

#pragma unroll
    for (int q = 0; q < NV_ROWS; q++) {
        const int r  = r0 + q;
        const int sr = (r < nrows) ? (idx ? idx[r] : r) : 0;
        s_in[q * EDIM + tid] = emb[(size_t)sr * EDIM + tid];
    }
    __syncthreads();

    float acc[NV_ROWS];
    const float bd = b[tid];
#pragma unroll
    for (int q = 0; q < NV_ROWS; q++) acc[q] = bd;

#pragma unroll 4
    for (int k = 0; k < EDIM; k++) {
        const float w = sW[k * EDIM + tid];
#pragma unroll
        for (int q = 0; q < NV_ROWS; q++)
            acc[q] = fmaf(s_in[q * EDIM + k], w, acc[q]);
    }

#pragma unroll
    for (int q = 0; q < NV_ROWS; q++) {
        const int r = r0 + q;
        if (r < nrows)
            out[(size_t)r * EDIM + tid] = tanhf(ALPHA * acc[q]);
    }
}

// ---------------------------------------------------------------------------
// Kernel 2: H = relu(tanh(3 * nv1 @ nv2^T))  -- proven bit-path, unchanged.
// ---------------------------------------------------------------------------
#define GT_TM 128
#define GT_BK 16

__global__ void __launch_bounds__(256, 2) h_gemm_kernel(
    const float* __restrict__ A,
    const float* __restrict__ B,
    float*       __restrict__ C,
    int M, int N, int Kd)
{
    __shared__ __align__(16) float As[2][GT_BK][GT_TM];
    __shared__ __align__(16) float Bs[2][GT_BK][GT_TM];

    const int tid = threadIdx.x;
    const int bm  = blockIdx.y * GT_TM;
    const int bn  = blockIdx.x * GT_TM;
    const int tx  = tid & 15;
    const int ty  = tid >> 4;

    float acc[8][8];
#pragma unroll
    for (int i = 0; i < 8; i++)
#pragma unroll
        for (int j = 0; j < 8; j++) acc[i][j] = 0.0f;

    auto stage = [&](int buf, int k0) {
#pragma unroll
        for (int s = 0; s < 2; s++) {
            const int f  = tid + s * 256;
            const int r  = f >> 2;
            const int kq = (f & 3) << 2;
            const int ga = bm + r;
            float4 va = make_float4(0.f, 0.f, 0.f, 0.f);
            if (ga < M)
                va = *reinterpret_cast<const float4*>(A + (size_t)ga * Kd + k0 + kq);
            As[buf][kq + 0][r] = va.x; As[buf][kq + 1][r] = va.y;
            As[buf][kq + 2][r] = va.z; As[buf][kq + 3][r] = va.w;

            const int gb = bn + r;
            float4 vb = make_float4(0.f, 0.f, 0.f, 0.f);
            if (gb < N)
                vb = *reinterpret_cast<const float4*>(B + (size_t)gb * Kd + k0 + kq);
            Bs[buf][kq + 0][r] = vb.x; Bs[buf][kq + 1][r] = vb.y;
            Bs[buf][kq + 2][r] = vb.z; Bs[buf][kq + 3][r] = vb.w;
        }
    };

    stage(0, 0);
    __syncthreads();

    const int nk = Kd / GT_BK;
    for (int kt = 0; kt < nk; kt++) {
        const int cur = kt & 1;
        if (kt + 1 < nk) stage(cur ^ 1, (kt + 1) * GT_BK);

#pragma unroll
        for (int kk = 0; kk < GT_BK; kk++) {
            float a[8], b[8];
#pragma unroll
            for (int i = 0; i < 8; i += 4)
                *reinterpret_cast<float4*>(&a[i]) =
                    *reinterpret_cast<const float4*>(&As[cur][kk][ty * 8 + i]);
#pragma unroll
            for (int j = 0; j < 8; j += 4)
                *reinterpret_cast<float4*>(&b[j]) =
                    *reinterpret_cast<const float4*>(&Bs[cur][kk][tx * 8 + j]);
#pragma unroll
            for (int i = 0; i < 8; i++)
#pragma unroll
                for (int j = 0; j < 8; j++)
                    acc[i][j] = fmaf(a[i], b[j], acc[i][j]);
        }
        __syncthreads();
    }

#pragma unroll
    for (int i = 0; i < 8; i++) {
        const int gr = bm + ty * 8 + i;
        if (gr >= M) continue;
        float* crow = C + (size_t)gr * N;
#pragma unroll
        for (int j = 0; j < 8; j += 4) {
            const int gc = bn + tx * 8 + j;
            float4 v;
            v.x = fmaxf(tanhf(ALPHA * acc[i][j + 0]), 0.0f);
            v.y = fmaxf(tanhf(ALPHA * acc[i][j + 1]), 0.0f);
            v.z = fmaxf(tanhf(ALPHA * acc[i][j + 2]), 0.0f);
            v.w = fmaxf(tanhf(ALPHA * acc[i][j + 3]), 0.0f);
            if (gc + 3 < N) {
                *reinterpret_cast<float4*>(crow + gc) = v;
            } else {
                const float vv[4] = {v.x, v.y, v.z, v.w};
                for (int q = 0; q < 4; q++)
                    if (gc + q < N) crow[gc + q] = vv[q];
            }
        }
    }
}

// ---------------------------------------------------------------------------
// Kernel 3: adj = H @ H^T -- R4's exact kernel (best measured, bit-identical
// ascending-k fmaf chain; at the FFMA structural ceiling). FROZEN.
// ---------------------------------------------------------------------------
#define ADJ_SMEM_BYTES (128 * 133 * 4)

__global__ void __launch_bounds__(256, 2) adj_sym_kernel(
    const float* __restrict__ A,
    float*       __restrict__ C,
    int M, int Kd)
{
    extern __shared__ __align__(16) float smem_pool[];

    const int by = blockIdx.y, bx = blockIdx.x;
    if (bx < by) return;

    float (*As)[GT_BK][GT_TM] = reinterpret_cast<float (*)[GT_BK][GT_TM]>(smem_pool);
    float (*Bs)[GT_BK][GT_TM] =
        reinterpret_cast<float (*)[GT_BK][GT_TM]>(smem_pool + 2 * GT_BK * GT_TM);

    const int tid = threadIdx.x;
    const int bm  = by * GT_TM;
    const int bn  = bx * GT_TM;
    const int tx  = tid & 15;
    const int ty  = tid >> 4;

    float acc[8][8];
#pragma unroll
    for (int i = 0; i < 8; i++)
#pragma unroll
        for (int j = 0; j < 8; j++) acc[i][j] = 0.0f;

    auto stage = [&](int buf, int k0) {
#pragma unroll
        for (int s = 0; s < 2; s++) {
            const int f  = tid + s * 256;
            const int r  = f >> 2;
            const int kq = (f & 3) << 2;
            const int ga = bm + r;
            float4 va = make_float4(0.f, 0.f, 0.f, 0.f);
            if (ga < M)
                va = *reinterpret_cast<const float4*>(A + (size_t)ga * Kd + k0 + kq);
            As[buf][kq + 0][r] = va.x; As[buf][kq + 1][r] = va.y;
            As[buf][kq + 2][r] = va.z; As[buf][kq + 3][r] = va.w;

            const int gb = bn + r;
            float4 vb = make_float4(0.f, 0.f, 0.f, 0.f);
            if (gb < M)
                vb = *reinterpret_cast<const float4*>(A + (size_t)gb * Kd + k0 + kq);
            Bs[buf][kq + 0][r] = vb.x; Bs[buf][kq + 1][r] = vb.y;
            Bs[buf][kq + 2][r] = vb.z; Bs[buf][kq + 3][r] = vb.w;
        }
    };

    stage(0, 0);
    __syncthreads();

    const int nk = Kd / GT_BK;
    for (int kt = 0; kt < nk; kt++) {
        const int cur = kt & 1;
        if (kt + 1 < nk) stage(cur ^ 1, (kt + 1) * GT_BK);

#pragma unroll
        for (int kk = 0; kk < GT_BK; kk++) {
            float a[8], b[8];
#pragma unroll
            for (int i = 0; i < 8; i += 4)
                *reinterpret_cast<float4*>(&a[i]) =
                    *reinterpret_cast<const float4*>(&As[cur][kk][ty * 8 + i]);
#pragma unroll
            for (int j = 0; j < 8; j += 4)
                *reinterpret_cast<float4*>(&b[j]) =
                    *reinterpret_cast<const float4*>(&Bs[cur][kk][tx * 8 + j]);
#pragma unroll
            for (int i = 0; i < 8; i++)
#pragma unroll
                for (int j = 0; j < 8; j++)
                    acc[i][j] = fmaf(a[i], b[j], acc[i][j]);
        }
        __syncthreads();
    }

    float* Ct = smem_pool;
#define CT(r, c) Ct[(r) * 133 + (c)]

#pragma unroll
    for (int i = 0; i < 8; i++) {
        const int r0 = ty * 8 + i;
        const int gr = bm + r0;
#pragma unroll
        for (int j = 0; j < 8; j += 4) {
            const int c0 = tx * 8 + j;
            const float v0 = acc[i][j + 0], v1 = acc[i][j + 1];
            const float v2 = acc[i][j + 2], v3 = acc[i][j + 3];
            CT(r0, c0 + 0) = v0; CT(r0, c0 + 1) = v1;
            CT(r0, c0 + 2) = v2; CT(r0, c0 + 3) = v3;

            if (gr < M) {
                const int gc = bn + c0;
                if (gc + 3 < M) {
                    *reinterpret_cast<float4*>(C + (size_t)gr * M + gc) =
                        make_float4(v0, v1, v2, v3);
                } else {
                    const float vv[4] = {v0, v1, v2, v3};
                    for (int q = 0; q < 4; q++)
                        if (gc + q < M) C[(size_t)gr * M + gc + q] = vv[q];
                }
            }
        }
    }
    __syncthreads();

    for (int i = tid; i < 128 * 128; i += 256) {
        const int r2 = i >> 7;
        const int c2 = i & 127;
        const int gR = bn + r2, gC = bm + c2;
        if (gR < M && gC < M)
            C[(size_t)gR * M + gC] = CT(c2, r2);
    }
#undef CT
}

// ---------------------------------------------------------------------------
// Kernel 4: per-row top-K mask. Candidate-compacted radix select:
//   pass 1: 256-bin histogram over top byte of the full row
//   compact indices of the selected bucket into a u16 list
//   passes 2-4: radix on the candidate list only (typically tiny)
// Decision semantics identical to the proven full-scan radix (same bin/rank/
// cnt recurrence, same lowest-index tie-break). adj >= 0 -> uint-monotone.
// ---------------------------------------------------------------------------
#define TPK_THREADS 512
#define TPK_SMEM (NNODES * 4 + NNODES * 2 + 256 * 4 + 256 * 4 + 64)

__global__ void __launch_bounds__(TPK_THREADS) topk_mask_kernel(
    float* __restrict__ adj, int N)
{
    extern __shared__ __align__(16) unsigned char tpk_smem[];
    unsigned*       s_key  = reinterpret_cast<unsigned*>(tpk_smem);          // [N]
    unsigned short* s_cand = reinterpret_cast<unsigned short*>(s_key + NNODES); // [N]
    unsigned*       s_hist = reinterpret_cast<unsigned*>(s_cand + NNODES);   // [256]
    unsigned*       s_scan = s_hist + 256;                                   // [256]
    __shared__ int  s_b, s_rank, s_cnt, s_ccnt;

    const int    tid  = threadIdx.x;
    const size_t base = (size_t)blockIdx.x * N;
    const unsigned lane_lt = (1u << (tid & 31)) - 1u;

    // ---- load row (uint4 vectorized; N % 4 == 0) ----
    {
        const uint4* g4 = reinterpret_cast<const uint4*>(adj + base);
        uint4*       s4 = reinterpret_cast<uint4*>(s_key);
        for (int j = tid; j < N / 4; j += TPK_THREADS) s4[j] = g4[j];
    }
    __syncthreads();

    unsigned prefix = 0u;
    int rank = TOPK, cnt = 0;

    // ---- pass 1: full-row histogram on byte 3 ----
    if (tid < 256) s_hist[tid] = 0u;
    __syncthreads();
    for (int j0 = 0; j0 < N; j0 += TPK_THREADS) {
        const int j = j0 + tid;
        const bool pred = (j < N);
        const unsigned bin = pred ? (s_key[j] >> 24) : 0u;
        const unsigned act = __ballot_sync(0xFFFFFFFFu, pred);
        if (pred) {
            const unsigned peers = __match_any_sync(act, bin);
            if ((tid & 31) == (__ffs(peers) - 1))
                atomicAdd(&s_hist[bin], __popc(peers));
        }
    }
    __syncthreads();

    // suffix scan + select (shared helper pattern, inlined per pass)
    {
        if (tid < 256) s_scan[tid] = s_hist[tid];
        __syncthreads();
#pragma unroll
        for (int off = 1; off < 256; off <<= 1) {
            unsigned v = 0u, a = 0u;
            if (tid < 256) { v = s_scan[tid]; a = (tid + off < 256) ? s_scan[tid + off] : 0u; }
            __syncthreads();
            if (tid < 256) s_scan[tid] = v + a;
            __syncthreads();
        }
        if (tid < 256) {
            const unsigned Sb  = s_scan[tid];
            const unsigned Sb1 = (tid < 255) ? s_scan[tid + 1] : 0u;
            if ((int)Sb >= rank && (int)Sb1 < rank) {
                s_b = tid; s_rank = rank - (int)Sb1; s_cnt = (int)(Sb - Sb1);
            }
        }
        __syncthreads();
        prefix |= ((unsigned)s_b << 24);
        rank = s_rank; cnt = s_cnt;
        __syncthreads();
    }

    // ---- compact candidates: indices with top byte == selected bin ----
    const unsigned b1 = prefix >> 24;
    if (tid == 0) s_ccnt = 0;
    __syncthreads();
    for (int j0 = 0; j0 < N; j0 += TPK_THREADS) {
        const int j = j0 + tid;
        const bool pred = (j < N) && ((s_key[j] >> 24) == b1);
        const unsigned m = __ballot_sync(0xFFFFFFFFu, pred);
        int cb = 0;
        if ((tid & 31) == 0 && m) cb = atomicAdd(&s_ccnt, __popc(m));
        cb = __shfl_sync(0xFFFFFFFFu, cb, 0);
        if (pred) s_cand[cb + __popc(m & lane_lt)] = (unsigned short)j;
    }
    __syncthreads();

    // ---- passes 2..4 over the candidate list ----
    for (int shift = 16; shift >= 0; shift -= 8) {
        if (tid < 256) s_hist[tid] = 0u;
        __syncthreads();
        for (int i0 = 0; i0 < cnt; i0 += TPK_THREADS) {
            const int i = i0 + tid;
            const bool pred = (i < cnt);
            const unsigned bin = pred ? ((s_key[s_cand[i]] >> shift) & 0xFFu) : 0u;
            const unsigned act = __ballot_sync(0xFFFFFFFFu, pred);
            if (pred) {
                const unsigned peers = __match_any_sync(act, bin);
                if ((tid & 31) == (__ffs(peers) - 1))
                    atomicAdd(&s_hist[bin], __popc(peers));
            }
        }
        __syncthreads();

        if (tid < 256) s_scan[tid] = s_hist[tid];
        __syncthreads();
#pragma unroll
        for (int off = 1; off < 256; off <<= 1) {
            unsigned v = 0u, a = 0u;
            if (tid < 256) { v = s_scan[tid]; a = (tid + off < 256) ? s_scan[tid + off] : 0u; }
            __syncthreads();
            if (tid < 256) s_scan[tid] = v + a;
            __syncthreads();
        }
        if (tid < 256) {
            const unsigned Sb  = s_scan[tid];
            const unsigned Sb1 = (tid < 255) ? s_scan[tid + 1] : 0u;
            if ((int)Sb >= rank && (int)Sb1 < rank) {
                s_b = tid; s_rank = rank - (int)Sb1; s_cnt = (int)(Sb - Sb1);
            }
        }
        __syncthreads();
        const unsigned b2 = (unsigned)s_b;
        const int new_rank = s_rank, new_cnt = s_cnt;
        __syncthreads();
        prefix |= (b2 << shift);

        if (shift > 0) {
            // in-place chunked compaction: keep cands whose byte == b2.
            // Writes never pass the next chunk's read frontier (pushed <= read).
            if (tid == 0) s_ccnt = 0;
            __syncthreads();
            for (int i0 = 0; i0 < cnt; i0 += TPK_THREADS) {
                const int i = i0 + tid;
                bool pred = false;
                unsigned short cv = 0;
                if (i < cnt) {
                    cv = s_cand[i];
                    pred = (((s_key[cv] >> shift) & 0xFFu) == b2);
                }
                __syncthreads();   // all reads of this chunk complete
                const unsigned m = __ballot_sync(0xFFFFFFFFu, pred);
                int cb = 0;
                if ((tid & 31) == 0 && m) cb = atomicAdd(&s_ccnt, __popc(m));
                cb = __shfl_sync(0xFFFFFFFFu, cb, 0);
                if (pred) s_cand[cb + __popc(m & lane_lt)] = cv;
                __syncthreads();   // writes land before next chunk reads
            }
        }
        rank = new_rank; cnt = new_cnt;
    }

    const float Tval = __uint_as_float(prefix);

    if (cnt > rank) {
        // ties at threshold: keep first `rank` by index (rare; serial).
        if (tid == 0) {
            int kept = 0;
            for (int j = 0; j < N; j++) {
                if (s_key[j] == prefix) {
                    kept++;
                    if (kept > rank) s_key[j] = 0xBF800000u;  // -1.0f
                }
            }
        }
        __syncthreads();
    }

    // ---- write output (float4 vectorized) ----
    {
        float4* g4 = reinterpret_cast<float4*>(adj + base);
        const uint4* s4 = reinterpret_cast<const uint4*>(s_key);
        for (int j = tid; j < N / 4; j += TPK_THREADS) {
            const uint4 k = s4[j];
            float4 v;
            const float f0 = __uint_as_float(k.x), f1 = __uint_as_float(k.y);
            const float f2 = __uint_as_float(k.z), f3 = __uint_as_float(k.w);
            v.x = (f0 >= Tval) ? f0 : 0.0f;
            v.y = (f1 >= Tval) ? f1 : 0.0f;
            v.z = (f2 >= Tval) ? f2 : 0.0f;
            v.w = (f3 >= Tval) ? f3 : 0.0f;
            g4[j] = v;
        }
    }
}

// ---------------------------------------------------------------------------
// kernel_launch
// ---------------------------------------------------------------------------
extern "C" void kernel_launch(void* const* d_in, const int* in_sizes, int n_in,
                              void* d_out, int out_size)
{
    (void)in_sizes; (void)n_in; (void)out_size;

    const int*   idx   = (const int*)  d_in[0];
    const float* embn  = (const float*)d_in[1];
    const float* embhe = (const float*)d_in[2];
    const float* W1    = (const float*)d_in[3];
    const float* b1    = (const float*)d_in[4];
    const float* W2    = (const float*)d_in[5];
    const float* b2    = (const float*)d_in[6];
    float*       out   = (float*)d_out;

    float *p_nv1 = nullptr, *p_nv2 = nullptr, *p_H = nullptr;
    cudaGetSymbolAddress((void**)&p_nv1, g_nv1);
    cudaGetSymbolAddress((void**)&p_nv2, g_nv2);
    cudaGetSymbolAddress((void**)&p_H,   g_H);

    cudaFuncSetAttribute(adj_sym_kernel,
                         cudaFuncAttributeMaxDynamicSharedMemorySize,
                         ADJ_SMEM_BYTES);
    cudaFuncSetAttribute(nodevec_kernel,
                         cudaFuncAttributeMaxDynamicSharedMemorySize,
                         NV_SMEM);
    cudaFuncSetAttribute(topk_mask_kernel,
                         cudaFuncAttributeMaxDynamicSharedMemorySize,
                         TPK_SMEM);

    // 1) nodevecs
    nodevec_kernel<<<NNODES / NV_ROWS, EDIM, NV_SMEM>>>(embn, idx, W1, b1,
                                                        p_nv1, NNODES);
    nodevec_kernel<<<NHEDGES / NV_ROWS, EDIM, NV_SMEM>>>(embhe, nullptr, W2, b2,
                                                         p_nv2, NHEDGES);

    // 2) H = relu(tanh(3 * nv1 @ nv2^T))   [10000,512]
    {
        dim3 grid((NHEDGES + GT_TM - 1) / GT_TM, (NNODES + GT_TM - 1) / GT_TM);
        h_gemm_kernel<<<grid, 256>>>(p_nv1, p_nv2, p_H, NNODES, NHEDGES, EDIM);
    }

    // 3) adj = H @ H^T (frozen R4 bit pattern; symmetric tiles)
    {
        const int nt = (NNODES + GT_TM - 1) / GT_TM;
        dim3 grid(nt, nt);
        adj_sym_kernel<<<grid, 256, ADJ_SMEM_BYTES>>>(p_H, out, NNODES, NHEDGES);
    }

    // 4) per-row top-32 mask (candidate-compacted radix select)
    topk_mask_kernel<<<NNODES, TPK_THREADS, TPK_SMEM>>>(out, NNODES);
}

// round 8
// speedup vs baseline: 1.2169x; 1.1364x over previous
#include <cuda_runtime.h>
#include <math.h>

// ---------------------------------------------------------------------------
// Problem constants
// ---------------------------------------------------------------------------
#define NNODES  10000
#define NHEDGES 512
#define EDIM    128
#define TOPK    32
#define ALPHA   3.0f

// ---------------------------------------------------------------------------
// Scratch (device globals -- no runtime allocation allowed)
// ---------------------------------------------------------------------------
__device__ float g_nv1[NNODES * EDIM];
__device__ float g_nv2[NHEDGES * EDIM];
__device__ float g_H[NNODES * NHEDGES];

// ---------------------------------------------------------------------------
// Kernel 1: nodevec = tanh(ALPHA*(emb[row]@W + b)), 8 rows per block,
// W cached in SMEM. Bit path per output: ascending-k single-accumulator fmaf.
// ---------------------------------------------------------------------------
#define NV_ROWS 8
#define NV_SMEM ((EDIM * EDIM + NV_ROWS * EDIM) * 4)

__global__ void __launch_bounds__(EDIM) nodevec_kernel(
    const float* __restrict__ emb,
    const int*   __restrict__ idx,
    const float* __restrict__ W,
    const float* __restrict__ b,
    float*       __restrict__ out,
    int nrows)
{
    extern __shared__ __align__(16) float nv_smem[];
    float* sW   = nv_smem;
    float* s_in = nv_smem + EDIM * EDIM;

    const int tid = threadIdx.x;
    const int r0  = blockIdx.x * NV_ROWS;

    const float4* Wv  = reinterpret_cast<const float4*>(W);
    float4*       sWv = reinterpret_cast<float4*>(sW);
#pragma unroll
    for (int i = 0; i < (EDIM * EDIM / 4) / EDIM; i++)
        sWv[i * EDIM + tid] = Wv[i * EDIM + tid];

#pragma unroll
    for (int q = 0; q < NV_ROWS; q++) {
        const int r  = r0 + q;
        const int sr = (r < nrows) ? (idx ? idx[r] : r) : 0;
        s_in[q * EDIM + tid] = emb[(size_t)sr * EDIM + tid];
    }
    __syncthreads();

    float acc[NV_ROWS];
    const float bd = b[tid];
#pragma unroll
    for (int q = 0; q < NV_ROWS; q++) acc[q] = bd;

#pragma unroll 4
    for (int k = 0; k < EDIM; k++) {
        const float w = sW[k * EDIM + tid];
#pragma unroll
        for (int q = 0; q < NV_ROWS; q++)
            acc[q] = fmaf(s_in[q * EDIM + k], w, acc[q]);
    }

#pragma unroll
    for (int q = 0; q < NV_ROWS; q++) {
        const int r = r0 + q;
        if (r < nrows)
            out[(size_t)r * EDIM + tid] = tanhf(ALPHA * acc[q]);
    }
}

// ---------------------------------------------------------------------------
// Kernel 2: H = relu(tanh(3 * nv1 @ nv2^T))  -- proven bit-path, unchanged.
// ---------------------------------------------------------------------------
#define GT_TM 128
#define GT_BK 16

__global__ void __launch_bounds__(256, 2) h_gemm_kernel(
    const float* __restrict__ A,
    const float* __restrict__ B,
    float*       __restrict__ C,
    int M, int N, int Kd)
{
    __shared__ __align__(16) float As[2][GT_BK][GT_TM];
    __shared__ __align__(16) float Bs[2][GT_BK][GT_TM];

    const int tid = threadIdx.x;
    const int bm  = blockIdx.y * GT_TM;
    const int bn  = blockIdx.x * GT_TM;
    const int tx  = tid & 15;
    const int ty  = tid >> 4;

    float acc[8][8];
#pragma unroll
    for (int i = 0; i < 8; i++)
#pragma unroll
        for (int j = 0; j < 8; j++) acc[i][j] = 0.0f;

    auto stage = [&](int buf, int k0) {
#pragma unroll
        for (int s = 0; s < 2; s++) {
            const int f  = tid + s * 256;
            const int r  = f >> 2;
            const int kq = (f & 3) << 2;
            const int ga = bm + r;
            float4 va = make_float4(0.f, 0.f, 0.f, 0.f);
            if (ga < M)
                va = *reinterpret_cast<const float4*>(A + (size_t)ga * Kd + k0 + kq);
            As[buf][kq + 0][r] = va.x; As[buf][kq + 1][r] = va.y;
            As[buf][kq + 2][r] = va.z; As[buf][kq + 3][r] = va.w;

            const int gb = bn + r;
            float4 vb = make_float4(0.f, 0.f, 0.f, 0.f);
            if (gb < N)
                vb = *reinterpret_cast<const float4*>(B + (size_t)gb * Kd + k0 + kq);
            Bs[buf][kq + 0][r] = vb.x; Bs[buf][kq + 1][r] = vb.y;
            Bs[buf][kq + 2][r] = vb.z; Bs[buf][kq + 3][r] = vb.w;
        }
    };

    stage(0, 0);
    __syncthreads();

    const int nk = Kd / GT_BK;
    for (int kt = 0; kt < nk; kt++) {
        const int cur = kt & 1;
        if (kt + 1 < nk) stage(cur ^ 1, (kt + 1) * GT_BK);

#pragma unroll
        for (int kk = 0; kk < GT_BK; kk++) {
            float a[8], b[8];
#pragma unroll
            for (int i = 0; i < 8; i += 4)
                *reinterpret_cast<float4*>(&a[i]) =
                    *reinterpret_cast<const float4*>(&As[cur][kk][ty * 8 + i]);
#pragma unroll
            for (int j = 0; j < 8; j += 4)
                *reinterpret_cast<float4*>(&b[j]) =
                    *reinterpret_cast<const float4*>(&Bs[cur][kk][tx * 8 + j]);
#pragma unroll
            for (int i = 0; i < 8; i++)
#pragma unroll
                for (int j = 0; j < 8; j++)
                    acc[i][j] = fmaf(a[i], b[j], acc[i][j]);
        }
        __syncthreads();
    }

#pragma unroll
    for (int i = 0; i < 8; i++) {
        const int gr = bm + ty * 8 + i;
        if (gr >= M) continue;
        float* crow = C + (size_t)gr * N;
#pragma unroll
        for (int j = 0; j < 8; j += 4) {
            const int gc = bn + tx * 8 + j;
            float4 v;
            v.x = fmaxf(tanhf(ALPHA * acc[i][j + 0]), 0.0f);
            v.y = fmaxf(tanhf(ALPHA * acc[i][j + 1]), 0.0f);
            v.z = fmaxf(tanhf(ALPHA * acc[i][j + 2]), 0.0f);
            v.w = fmaxf(tanhf(ALPHA * acc[i][j + 3]), 0.0f);
            if (gc + 3 < N) {
                *reinterpret_cast<float4*>(crow + gc) = v;
            } else {
                const float vv[4] = {v.x, v.y, v.z, v.w};
                for (int q = 0; q < 4; q++)
                    if (gc + q < N) crow[gc + q] = vv[q];
            }
        }
    }
}

// ---------------------------------------------------------------------------
// Kernel 3: adj = H @ H^T -- FROZEN (R4 bit pattern; FFMA structural floor).
// ---------------------------------------------------------------------------
#define ADJ_SMEM_BYTES (128 * 133 * 4)

__global__ void __launch_bounds__(256, 2) adj_sym_kernel(
    const float* __restrict__ A,
    float*       __restrict__ C,
    int M, int Kd)
{
    extern __shared__ __align__(16) float smem_pool[];

    const int by = blockIdx.y, bx = blockIdx.x;
    if (bx < by) return;

    float (*As)[GT_BK][GT_TM] = reinterpret_cast<float (*)[GT_BK][GT_TM]>(smem_pool);
    float (*Bs)[GT_BK][GT_TM] =
        reinterpret_cast<float (*)[GT_BK][GT_TM]>(smem_pool + 2 * GT_BK * GT_TM);

    const int tid = threadIdx.x;
    const int bm  = by * GT_TM;
    const int bn  = bx * GT_TM;
    const int tx  = tid & 15;
    const int ty  = tid >> 4;

    float acc[8][8];
#pragma unroll
    for (int i = 0; i < 8; i++)
#pragma unroll
        for (int j = 0; j < 8; j++) acc[i][j] = 0.0f;

    auto stage = [&](int buf, int k0) {
#pragma unroll
        for (int s = 0; s < 2; s++) {
            const int f  = tid + s * 256;
            const int r  = f >> 2;
            const int kq = (f & 3) << 2;
            const int ga = bm + r;
            float4 va = make_float4(0.f, 0.f, 0.f, 0.f);
            if (ga < M)
                va = *reinterpret_cast<const float4*>(A + (size_t)ga * Kd + k0 + kq);
            As[buf][kq + 0][r] = va.x; As[buf][kq + 1][r] = va.y;
            As[buf][kq + 2][r] = va.z; As[buf][kq + 3][r] = va.w;

            const int gb = bn + r;
            float4 vb = make_float4(0.f, 0.f, 0.f, 0.f);
            if (gb < M)
                vb = *reinterpret_cast<const float4*>(A + (size_t)gb * Kd + k0 + kq);
            Bs[buf][kq + 0][r] = vb.x; Bs[buf][kq + 1][r] = vb.y;
            Bs[buf][kq + 2][r] = vb.z; Bs[buf][kq + 3][r] = vb.w;
        }
    };

    stage(0, 0);
    __syncthreads();

    const int nk = Kd / GT_BK;
    for (int kt = 0; kt < nk; kt++) {
        const int cur = kt & 1;
        if (kt + 1 < nk) stage(cur ^ 1, (kt + 1) * GT_BK);

#pragma unroll
        for (int kk = 0; kk < GT_BK; kk++) {
            float a[8], b[8];
#pragma unroll
            for (int i = 0; i < 8; i += 4)
                *reinterpret_cast<float4*>(&a[i]) =
                    *reinterpret_cast<const float4*>(&As[cur][kk][ty * 8 + i]);
#pragma unroll
            for (int j = 0; j < 8; j += 4)
                *reinterpret_cast<float4*>(&b[j]) =
                    *reinterpret_cast<const float4*>(&Bs[cur][kk][tx * 8 + j]);
#pragma unroll
            for (int i = 0; i < 8; i++)
#pragma unroll
                for (int j = 0; j < 8; j++)
                    acc[i][j] = fmaf(a[i], b[j], acc[i][j]);
        }
        __syncthreads();
    }

    float* Ct = smem_pool;
#define CT(r, c) Ct[(r) * 133 + (c)]

#pragma unroll
    for (int i = 0; i < 8; i++) {
        const int r0 = ty * 8 + i;
        const int gr = bm + r0;
#pragma unroll
        for (int j = 0; j < 8; j += 4) {
            const int c0 = tx * 8 + j;
            const float v0 = acc[i][j + 0], v1 = acc[i][j + 1];
            const float v2 = acc[i][j + 2], v3 = acc[i][j + 3];
            CT(r0, c0 + 0) = v0; CT(r0, c0 + 1) = v1;
            CT(r0, c0 + 2) = v2; CT(r0, c0 + 3) = v3;

            if (gr < M) {
                const int gc = bn + c0;
                if (gc + 3 < M) {
                    *reinterpret_cast<float4*>(C + (size_t)gr * M + gc) =
                        make_float4(v0, v1, v2, v3);
                } else {
                    const float vv[4] = {v0, v1, v2, v3};
                    for (int q = 0; q < 4; q++)
                        if (gc + q < M) C[(size_t)gr * M + gc + q] = vv[q];
                }
            }
        }
    }
    __syncthreads();

    for (int i = tid; i < 128 * 128; i += 256) {
        const int r2 = i >> 7;
        const int c2 = i & 127;
        const int gR = bn + r2, gC = bm + c2;
        if (gR < M && gC < M)
            C[(size_t)gR * M + gC] = CT(c2, r2);
    }
#undef CT
}

// ---------------------------------------------------------------------------
// Kernel 4: per-row top-K mask. 2048-bin radix select on bits 31..21 (digit
// includes 3 mantissa bits -> concentrated values spread across bins), fused
// with the row load. Candidates (<=4096) gathered once; passes 2/3 re-filter
// the same list (bits 20..10, 9..0). Hierarchical suffix-scan (shfl + 16 warp
// totals): ~3 barriers/pass. Exact: same Kth-select recurrence, same
// lowest-index tie path. adj >= 0 -> uint keys order-preserving.
// ---------------------------------------------------------------------------
#define TPK_THREADS 512
#define TPK_NWARP   (TPK_THREADS / 32)
#define TPK_BINS    2048
#define CAND_MAX    4096
#define TPK_SMEM    (NNODES * 4 + CAND_MAX * 2 + TPK_BINS * 4 + 256)

__global__ void __launch_bounds__(TPK_THREADS) topk_mask_kernel(
    float* __restrict__ adj, int N)
{
    extern __shared__ __align__(16) unsigned char tpk_smem[];
    unsigned*       s_key  = reinterpret_cast<unsigned*>(tpk_smem);              // [N]
    unsigned short* s_cand = reinterpret_cast<unsigned short*>(s_key + NNODES);  // [CAND_MAX]
    unsigned*       s_hist = reinterpret_cast<unsigned*>(s_cand + CAND_MAX);     // [2048]
    unsigned*       s_wsum = s_hist + TPK_BINS;                                  // [16]
    unsigned*       s_wexc = s_wsum + TPK_NWARP;                                 // [16]
    __shared__ int  s_b, s_rank, s_cnt, s_ccnt;

    const int tid  = threadIdx.x;
    const int lane = tid & 31;
    const int warp = tid >> 5;
    const size_t base = (size_t)blockIdx.x * N;
    const unsigned lane_lt = (1u << lane) - 1u;

    // ---- zero hist ----
#pragma unroll
    for (int i = 0; i < TPK_BINS / TPK_THREADS; i++)
        s_hist[i * TPK_THREADS + tid] = 0u;
    __syncthreads();

    // ---- load row + fused pass-1 histogram (bins = key >> 21) ----
    {
        const uint4* g4 = reinterpret_cast<const uint4*>(adj + base);
        uint4*       s4 = reinterpret_cast<uint4*>(s_key);
        const int n4 = N / 4;   // N % 4 == 0
        for (int j0 = 0; j0 < n4; j0 += TPK_THREADS) {
            const int j = j0 + tid;
            const bool pred = (j < n4);
            uint4 k = make_uint4(0u, 0u, 0u, 0u);
            if (pred) { k = g4[j]; s4[j] = k; }
            const unsigned act = __ballot_sync(0xFFFFFFFFu, pred);
            unsigned e[4] = {k.x >> 21, k.y >> 21, k.z >> 21, k.w >> 21};
#pragma unroll
            for (int q = 0; q < 4; q++) {
                if (pred) {
                    const unsigned peers = __match_any_sync(act, e[q]);
                    if (lane == (__ffs(peers) - 1))
                        atomicAdd(&s_hist[e[q]], __popc(peers));
                }
            }
        }
    }
    __syncthreads();

    // ===== generic: hierarchical suffix-scan over s_hist + Kth-bin select ====
    // each thread owns 4 bins [4t .. 4t+3]
    auto select_bin = [&](int rank) {
        unsigned h[4], sfx[4];
#pragma unroll
        for (int q = 0; q < 4; q++) h[q] = s_hist[tid * 4 + q];
        sfx[3] = h[3];
        sfx[2] = h[2] + sfx[3];
        sfx[1] = h[1] + sfx[2];
        sfx[0] = h[0] + sfx[1];
        const unsigned tot = sfx[0];

        unsigned v = tot;   // within-warp inclusive suffix over thread totals
#pragma unroll
        for (int off = 1; off < 32; off <<= 1) {
            const unsigned u = __shfl_down_sync(0xFFFFFFFFu, v, off);
            if (lane + off < 32) v += u;
        }
        if (lane == 0) s_wsum[warp] = v;    // warp total
        __syncthreads();
        if (warp == 0) {
            unsigned wv = (lane < TPK_NWARP) ? s_wsum[lane] : 0u;
#pragma unroll
            for (int off = 1; off < TPK_NWARP; off <<= 1) {
                const unsigned u = __shfl_down_sync(0xFFFFFFFFu, wv, off);
                if (lane + off < 32) wv += u;
            }
            if (lane < TPK_NWARP) s_wexc[lane] = wv - s_wsum[lane];
        }
        __syncthreads();
        // excl suffix over threads with index > tid
        const unsigned excl = s_wexc[warp] + (v - tot);
#pragma unroll
        for (int q = 0; q < 4; q++) {
            const unsigned Sb = sfx[q] + excl;
            if ((int)Sb >= rank && (int)(Sb - h[q]) < rank) {
                s_b    = tid * 4 + q;
                s_rank = rank - (int)(Sb - h[q]);
                s_cnt  = (int)h[q];
            }
        }
        __syncthreads();
    };

    // ---- pass 1 select ----
    select_bin(TOPK);
    const unsigned b1 = (unsigned)s_b;     // 11-bit digit
    int rank = s_rank;
    int cnt  = s_cnt;
    __syncthreads();

    // ---- gather candidates (key >> 21 == b1) into u16 list ----
    const bool use_cand = (cnt <= CAND_MAX);
    if (use_cand) {
        if (tid == 0) s_ccnt = 0;
        __syncthreads();
        for (int j0 = 0; j0 < N; j0 += TPK_THREADS) {
            const int j = j0 + tid;
            const bool pred = (j < N) && ((s_key[j] >> 21) == b1);
            const unsigned m = __ballot_sync(0xFFFFFFFFu, pred);
            int cb = 0;
            if (lane == 0 && m) cb = atomicAdd(&s_ccnt, __popc(m));
            cb = __shfl_sync(0xFFFFFFFFu, cb, 0);
            if (pred) s_cand[cb + __popc(m & lane_lt)] = (unsigned short)j;
        }
    }
    __syncthreads();

    // ---- pass 2: bins = bits 20..10, among keys with prefix b1 ----
    {
#pragma unroll
        for (int i = 0; i < TPK_BINS / TPK_THREADS; i++)
            s_hist[i * TPK_THREADS + tid] = 0u;
        __syncthreads();
        if (use_cand) {
            for (int i = tid; i < cnt; i += TPK_THREADS) {
                const unsigned k = s_key[s_cand[i]];
                atomicAdd(&s_hist[(k >> 10) & 0x7FFu], 1u);
            }
        } else {
            for (int j = tid; j < N; j += TPK_THREADS) {
                const unsigned k = s_key[j];
                if ((k >> 21) == b1)
                    atomicAdd(&s_hist[(k >> 10) & 0x7FFu], 1u);
            }
        }
        __syncthreads();
        select_bin(rank);
    }
    const unsigned pref21 = (b1 << 11) | (unsigned)s_b;   // bits 31..10
    rank = s_rank;
    cnt  = s_cnt;
    __syncthreads();

    // ---- pass 3: bins = bits 9..0, among keys with prefix pref21 ----
    {
#pragma unroll
        for (int i = 0; i < TPK_BINS / TPK_THREADS; i++)
            s_hist[i * TPK_THREADS + tid] = 0u;
        __syncthreads();
        if (use_cand) {
            const int cc = s_ccnt;
            for (int i = tid; i < cc; i += TPK_THREADS) {
                const unsigned k = s_key[s_cand[i]];
                if ((k >> 10) == pref21)
                    atomicAdd(&s_hist[k & 0x3FFu], 1u);
            }
        } else {
            for (int j = tid; j < N; j += TPK_THREADS) {
                const unsigned k = s_key[j];
                if ((k >> 10) == pref21)
                    atomicAdd(&s_hist[k & 0x3FFu], 1u);
            }
        }
        __syncthreads();
        select_bin(rank);
    }
    const unsigned prefix = (pref21 << 10) | (unsigned)s_b;  // full key
    rank = s_rank;
    cnt  = s_cnt;
    __syncthreads();

    const float Tval = __uint_as_float(prefix);

    if (cnt > rank) {
        // ties at threshold: keep first `rank` by index (rare; serial).
        if (tid == 0) {
            int kept = 0;
            for (int j = 0; j < N; j++) {
                if (s_key[j] == prefix) {
                    kept++;
                    if (kept > rank) s_key[j] = 0xBF800000u;  // -1.0f
                }
            }
        }
        __syncthreads();
    }

    // ---- write masked row ----
    {
        float4* g4 = reinterpret_cast<float4*>(adj + base);
        const uint4* s4 = reinterpret_cast<const uint4*>(s_key);
        for (int j = tid; j < N / 4; j += TPK_THREADS) {
            const uint4 k = s4[j];
            float4 v;
            const float f0 = __uint_as_float(k.x), f1 = __uint_as_float(k.y);
            const float f2 = __uint_as_float(k.z), f3 = __uint_as_float(k.w);
            v.x = (f0 >= Tval) ? f0 : 0.0f;
            v.y = (f1 >= Tval) ? f1 : 0.0f;
            v.z = (f2 >= Tval) ? f2 : 0.0f;
            v.w = (f3 >= Tval) ? f3 : 0.0f;
            g4[j] = v;
        }
    }
}

// ---------------------------------------------------------------------------
// kernel_launch
// ---------------------------------------------------------------------------
extern "C" void kernel_launch(void* const* d_in, const int* in_sizes, int n_in,
                              void* d_out, int out_size)
{
    (void)in_sizes; (void)n_in; (void)out_size;

    const int*   idx   = (const int*)  d_in[0];
    const float* embn  = (const float*)d_in[1];
    const float* embhe = (const float*)d_in[2];
    const float* W1    = (const float*)d_in[3];
    const float* b1    = (const float*)d_in[4];
    const float* W2    = (const float*)d_in[5];
    const float* b2    = (const float*)d_in[6];
    float*       out   = (float*)d_out;

    float *p_nv1 = nullptr, *p_nv2 = nullptr, *p_H = nullptr;
    cudaGetSymbolAddress((void**)&p_nv1, g_nv1);
    cudaGetSymbolAddress((void**)&p_nv2, g_nv2);
    cudaGetSymbolAddress((void**)&p_H,   g_H);

    cudaFuncSetAttribute(adj_sym_kernel,
                         cudaFuncAttributeMaxDynamicSharedMemorySize,
                         ADJ_SMEM_BYTES);
    cudaFuncSetAttribute(nodevec_kernel,
                         cudaFuncAttributeMaxDynamicSharedMemorySize,
                         NV_SMEM);
    cudaFuncSetAttribute(topk_mask_kernel,
                         cudaFuncAttributeMaxDynamicSharedMemorySize,
                         TPK_SMEM);

    // 1) nodevecs
    nodevec_kernel<<<NNODES / NV_ROWS, EDIM, NV_SMEM>>>(embn, idx, W1, b1,
                                                        p_nv1, NNODES);
    nodevec_kernel<<<NHEDGES / NV_ROWS, EDIM, NV_SMEM>>>(embhe, nullptr, W2, b2,
                                                         p_nv2, NHEDGES);

    // 2) H = relu(tanh(3 * nv1 @ nv2^T))   [10000,512]
    {
        dim3 grid((NHEDGES + GT_TM - 1) / GT_TM, (NNODES + GT_TM - 1) / GT_TM);
        h_gemm_kernel<<<grid, 256>>>(p_nv1, p_nv2, p_H, NNODES, NHEDGES, EDIM);
    }

    // 3) adj = H @ H^T (frozen R4 bit pattern; symmetric tiles)
    {
        const int nt = (NNODES + GT_TM - 1) / GT_TM;
        dim3 grid(nt, nt);
        adj_sym_kernel<<<grid, 256, ADJ_SMEM_BYTES>>>(p_H, out, NNODES, NHEDGES);
    }

    // 4) per-row top-32 mask (2048-bin radix select, fused hist + candidates)
    topk_mask_kernel<<<NNODES, TPK_THREADS, TPK_SMEM>>>(out, NNODES);
}

// round 9
// speedup vs baseline: 1.3006x; 1.0688x over previous
#include <cuda_runtime.h>
#include <cuda_bf16.h>
#include <math.h>

// ---------------------------------------------------------------------------
// Problem constants
// ---------------------------------------------------------------------------
#define NNODES  10000
#define NHEDGES 512
#define EDIM    128
#define TOPK    32
#define ALPHA   3.0f

// ---------------------------------------------------------------------------
// Scratch (device globals -- no runtime allocation allowed)
// ---------------------------------------------------------------------------
__device__ float          g_nv1[NNODES * EDIM];
__device__ float          g_nv2[NHEDGES * EDIM];
__device__ float          g_H  [NNODES * NHEDGES];          // exact H (fp32)
__device__ __nv_bfloat16  g_Hbf[NNODES * NHEDGES];          // bf16(H)
__device__ __nv_bfloat16  g_Abf[(size_t)NNODES * NNODES];   // approx adj (bf16)

// ---------------------------------------------------------------------------
// Kernel 1: nodevec = tanh(ALPHA*(emb[row]@W + b)), 8 rows/block, W in SMEM.
// ---------------------------------------------------------------------------
#define NV_ROWS 8
#define NV_SMEM ((EDIM * EDIM + NV_ROWS * EDIM) * 4)

__global__ void __launch_bounds__(EDIM) nodevec_kernel(
    const float* __restrict__ emb,
    const int*   __restrict__ idx,
    const float* __restrict__ W,
    const float* __restrict__ b,
    float*       __restrict__ out,
    int nrows)
{
    extern __shared__ __align__(16) float nv_smem[];
    float* sW   = nv_smem;
    float* s_in = nv_smem + EDIM * EDIM;

    const int tid = threadIdx.x;
    const int r0  = blockIdx.x * NV_ROWS;

    const float4* Wv  = reinterpret_cast<const float4*>(W);
    float4*       sWv = reinterpret_cast<float4*>(sW);
#pragma unroll
    for (int i = 0; i < (EDIM * EDIM / 4) / EDIM; i++)
        sWv[i * EDIM + tid] = Wv[i * EDIM + tid];

#pragma unroll
    for (int q = 0; q < NV_ROWS; q++) {
        const int r  = r0 + q;
        const int sr = (r < nrows) ? (idx ? idx[r] : r) : 0;
        s_in[q * EDIM + tid] = emb[(size_t)sr * EDIM + tid];
    }
    __syncthreads();

    float acc[NV_ROWS];
    const float bd = b[tid];
#pragma unroll
    for (int q = 0; q < NV_ROWS; q++) acc[q] = bd;

#pragma unroll 4
    for (int k = 0; k < EDIM; k++) {
        const float w = sW[k * EDIM + tid];
#pragma unroll
        for (int q = 0; q < NV_ROWS; q++)
            acc[q] = fmaf(s_in[q * EDIM + k], w, acc[q]);
    }

#pragma unroll
    for (int q = 0; q < NV_ROWS; q++) {
        const int r = r0 + q;
        if (r < nrows)
            out[(size_t)r * EDIM + tid] = tanhf(ALPHA * acc[q]);
    }
}

// ---------------------------------------------------------------------------
// Kernel 2: H = relu(tanh(3 * nv1 @ nv2^T))  (proven bit-path) + bf16 copy.
// ---------------------------------------------------------------------------
#define GT_TM 128
#define GT_BK 16

__global__ void __launch_bounds__(256, 2) h_gemm_kernel(
    const float* __restrict__ A,
    const float* __restrict__ B,
    float*         __restrict__ C,
    __nv_bfloat16* __restrict__ Cbf,
    int M, int N, int Kd)
{
    __shared__ __align__(16) float As[2][GT_BK][GT_TM];
    __shared__ __align__(16) float Bs[2][GT_BK][GT_TM];

    const int tid = threadIdx.x;
    const int bm  = blockIdx.y * GT_TM;
    const int bn  = blockIdx.x * GT_TM;
    const int tx  = tid & 15;
    const int ty  = tid >> 4;

    float acc[8][8];
#pragma unroll
    for (int i = 0; i < 8; i++)
#pragma unroll
        for (int j = 0; j < 8; j++) acc[i][j] = 0.0f;

    auto stage = [&](int buf, int k0) {
#pragma unroll
        for (int s = 0; s < 2; s++) {
            const int f  = tid + s * 256;
            const int r  = f >> 2;
            const int kq = (f & 3) << 2;
            const int ga = bm + r;
            float4 va = make_float4(0.f, 0.f, 0.f, 0.f);
            if (ga < M)
                va = *reinterpret_cast<const float4*>(A + (size_t)ga * Kd + k0 + kq);
            As[buf][kq + 0][r] = va.x; As[buf][kq + 1][r] = va.y;
            As[buf][kq + 2][r] = va.z; As[buf][kq + 3][r] = va.w;

            const int gb = bn + r;
            float4 vb = make_float4(0.f, 0.f, 0.f, 0.f);
            if (gb < N)
                vb = *reinterpret_cast<const float4*>(B + (size_t)gb * Kd + k0 + kq);
            Bs[buf][kq + 0][r] = vb.x; Bs[buf][kq + 1][r] = vb.y;
            Bs[buf][kq + 2][r] = vb.z; Bs[buf][kq + 3][r] = vb.w;
        }
    };

    stage(0, 0);
    __syncthreads();

    const int nk = Kd / GT_BK;
    for (int kt = 0; kt < nk; kt++) {
        const int cur = kt & 1;
        if (kt + 1 < nk) stage(cur ^ 1, (kt + 1) * GT_BK);

#pragma unroll
        for (int kk = 0; kk < GT_BK; kk++) {
            float a[8], b[8];
#pragma unroll
            for (int i = 0; i < 8; i += 4)
                *reinterpret_cast<float4*>(&a[i]) =
                    *reinterpret_cast<const float4*>(&As[cur][kk][ty * 8 + i]);
#pragma unroll
            for (int j = 0; j < 8; j += 4)
                *reinterpret_cast<float4*>(&b[j]) =
                    *reinterpret_cast<const float4*>(&Bs[cur][kk][tx * 8 + j]);
#pragma unroll
            for (int i = 0; i < 8; i++)
#pragma unroll
                for (int j = 0; j < 8; j++)
                    acc[i][j] = fmaf(a[i], b[j], acc[i][j]);
        }
        __syncthreads();
    }

#pragma unroll
    for (int i = 0; i < 8; i++) {
        const int gr = bm + ty * 8 + i;
        if (gr >= M) continue;
        float*         crow = C   + (size_t)gr * N;
        __nv_bfloat16* brow = Cbf + (size_t)gr * N;
#pragma unroll
        for (int j = 0; j < 8; j += 4) {
            const int gc = bn + tx * 8 + j;
            float4 v;
            v.x = fmaxf(tanhf(ALPHA * acc[i][j + 0]), 0.0f);
            v.y = fmaxf(tanhf(ALPHA * acc[i][j + 1]), 0.0f);
            v.z = fmaxf(tanhf(ALPHA * acc[i][j + 2]), 0.0f);
            v.w = fmaxf(tanhf(ALPHA * acc[i][j + 3]), 0.0f);
            if (gc + 3 < N) {
                *reinterpret_cast<float4*>(crow + gc) = v;
                brow[gc + 0] = __float2bfloat16(v.x);
                brow[gc + 1] = __float2bfloat16(v.y);
                brow[gc + 2] = __float2bfloat16(v.z);
                brow[gc + 3] = __float2bfloat16(v.w);
            } else {
                const float vv[4] = {v.x, v.y, v.z, v.w};
                for (int q = 0; q < 4; q++)
                    if (gc + q < N) {
                        crow[gc + q] = vv[q];
                        brow[gc + q] = __float2bfloat16(vv[q]);
                    }
            }
        }
    }
}

// ---------------------------------------------------------------------------
// Kernel 3: approx adj = bf16( Hbf @ Hbf^T ), bf16 MMA + fp32 accum.
// All terms nonneg -> rigorous bound |v - A| <= ~0.6% * A  (beta = 2^-6 used).
// ---------------------------------------------------------------------------
#define ABKC  32
#define APADK 40
#define AARR  (128 * APADK)
#define ABUF  (2 * AARR)
#define ASMEM (128 * 133 * 4)     // 68096 >= mainloop 40960

#define LDSM_X4(r, addr) \
    asm volatile("ldmatrix.sync.aligned.m8n8.x4.shared.b16 {%0,%1,%2,%3}, [%4];" \
        : "=r"((r)[0]), "=r"((r)[1]), "=r"((r)[2]), "=r"((r)[3]) : "r"(addr))
#define LDSM_X2(r, addr) \
    asm volatile("ldmatrix.sync.aligned.m8n8.x2.shared.b16 {%0,%1}, [%2];" \
        : "=r"((r)[0]), "=r"((r)[1]) : "r"(addr))
#define MMA_BF16(d, a, b) \
    asm volatile("mma.sync.aligned.m16n8k16.row.col.f32.bf16.bf16.f32 " \
        "{%0,%1,%2,%3},{%4,%5,%6,%7},{%8,%9},{%0,%1,%2,%3};" \
        : "+f"((d)[0]), "+f"((d)[1]), "+f"((d)[2]), "+f"((d)[3]) \
        : "r"((a)[0]), "r"((a)[1]), "r"((a)[2]), "r"((a)[3]), "r"((b)[0]), "r"((b)[1]))

__global__ void __launch_bounds__(256, 1) approx_mma_kernel(
    const __nv_bfloat16* __restrict__ Hbf,
    __nv_bfloat16* __restrict__ C,
    int M, int Kd)
{
    extern __shared__ __align__(16) unsigned char dynsmem[];
    __nv_bfloat16* s = reinterpret_cast<__nv_bfloat16*>(dynsmem);

    const int by = blockIdx.y, bx = blockIdx.x;
    if (bx < by) return;
    const int bm  = by * GT_TM, bn = bx * GT_TM;
    const int tid = threadIdx.x;
    const int lane = tid & 31, warp = tid >> 5;
    const int wm = warp >> 2;
    const int wn = warp & 3;

    const unsigned sbase = (unsigned)__cvta_generic_to_shared(s);

    auto stage = [&](int buf, int k0) {
#pragma unroll
        for (int a = 0; a < 2; a++) {
            const int rowbase = (a == 0) ? bm : bn;
#pragma unroll
            for (int sIt = 0; sIt < 2; sIt++) {
                const int idx  = tid + sIt * 256;
                const int row  = idx >> 2;
                const int unit = idx & 3;
                const int grow = rowbase + row;
                const int cpsz = (grow < M) ? 16 : 0;
                const void* src = Hbf + (size_t)(grow < M ? grow : 0) * Kd
                                      + k0 + unit * 8;
                const unsigned dst = sbase +
                    (unsigned)((buf * ABUF + a * AARR + row * APADK + unit * 8) * 2);
                asm volatile("cp.async.cg.shared.global [%0], [%1], 16, %2;\n"
                             :: "r"(dst), "l"(src), "r"(cpsz));
            }
        }
        asm volatile("cp.async.commit_group;\n" ::: "memory");
    };

    float acc[4][4][4];
#pragma unroll
    for (int i = 0; i < 4; i++)
#pragma unroll
        for (int j = 0; j < 4; j++)
#pragma unroll
            for (int q = 0; q < 4; q++) acc[i][j][q] = 0.0f;

    const int nk = Kd / ABKC;
    stage(0, 0);

    for (int kt = 0; kt < nk; kt++) {
        const int cur = kt & 1;
        if (kt + 1 < nk) {
            stage(cur ^ 1, (kt + 1) * ABKC);
            asm volatile("cp.async.wait_group 1;\n" ::: "memory");
        } else {
            asm volatile("cp.async.wait_group 0;\n" ::: "memory");
        }
        __syncthreads();

        const unsigned bA = sbase + (unsigned)((cur * ABUF + 0 * AARR) * 2);
        const unsigned bB = sbase + (unsigned)((cur * ABUF + 1 * AARR) * 2);

#pragma unroll
        for (int kk = 0; kk < 2; kk++) {
            unsigned ra[4][4], rb[4][2];
            const int arow = wm * 64 + (lane & 15);
            const int acol = kk * 16 + (lane >> 4) * 8;
#pragma unroll
            for (int mf = 0; mf < 4; mf++)
                LDSM_X4(ra[mf], bA + (unsigned)(((arow + mf * 16) * APADK + acol) * 2));
            const int brow = wn * 32 + (lane & 7);
            const int bcol = kk * 16 + ((lane >> 3) & 1) * 8;
#pragma unroll
            for (int nf = 0; nf < 4; nf++)
                LDSM_X2(rb[nf], bB + (unsigned)(((brow + nf * 8) * APADK + bcol) * 2));
#pragma unroll
            for (int mf = 0; mf < 4; mf++)
#pragma unroll
                for (int nf = 0; nf < 4; nf++)
                    MMA_BF16(acc[mf][nf], ra[mf], rb[nf]);
        }
        __syncthreads();
    }

    float* Ct = reinterpret_cast<float*>(dynsmem);
#define CT(r, c) Ct[(r) * 133 + (c)]

#pragma unroll
    for (int mf = 0; mf < 4; mf++) {
#pragma unroll
        for (int nf = 0; nf < 4; nf++) {
            const int r0 = wm * 64 + mf * 16 + (lane >> 2);
            const int c0 = wn * 32 + nf * 8 + (lane & 3) * 2;
            const __nv_bfloat16 b0 = __float2bfloat16(acc[mf][nf][0]);
            const __nv_bfloat16 b1 = __float2bfloat16(acc[mf][nf][1]);
            const __nv_bfloat16 b2 = __float2bfloat16(acc[mf][nf][2]);
            const __nv_bfloat16 b3 = __float2bfloat16(acc[mf][nf][3]);
            CT(r0, c0)     = __bfloat162float(b0);
            CT(r0, c0 + 1) = __bfloat162float(b1);
            CT(r0 + 8, c0)     = __bfloat162float(b2);
            CT(r0 + 8, c0 + 1) = __bfloat162float(b3);

            const int gc = bn + c0;               // even; M even -> gc+1 < M
            const int gr0 = bm + r0, gr1 = bm + r0 + 8;
            if (gr0 < M && gc < M) {
                __nv_bfloat162 p; p.x = b0; p.y = b1;
                *reinterpret_cast<__nv_bfloat162*>(C + (size_t)gr0 * M + gc) = p;
            }
            if (gr1 < M && gc < M) {
                __nv_bfloat162 p; p.x = b2; p.y = b3;
                *reinterpret_cast<__nv_bfloat162*>(C + (size_t)gr1 * M + gc) = p;
            }
        }
    }
    __syncthreads();

    for (int i = tid; i < 128 * 128; i += 256) {
        const int r2 = i >> 7;
        const int c2 = i & 127;
        const int gR = bn + r2, gC = bm + c2;
        if (gR < M && gC < M)
            C[(size_t)gR * M + gC] = __float2bfloat16(CT(c2, r2));
    }
#undef CT
}

// ---------------------------------------------------------------------------
// Kernel 4: per-row certified top-K (see header comment in theory above).
// ---------------------------------------------------------------------------
#define RK_THREADS 512
#define RK_SMEM (NNODES*2 + NNODES*2 + NNODES*4 + NHEDGES*4 + 256*4 + 128)

__global__ void __launch_bounds__(RK_THREADS) rowselect_kernel(
    const __nv_bfloat16* __restrict__ Abf,
    const float*         __restrict__ H,
    float*               __restrict__ out,
    int N, int Kd)
{
    extern __shared__ __align__(16) unsigned char sm[];
    unsigned short* s_apx  = reinterpret_cast<unsigned short*>(sm);
    unsigned short* s_cand = s_apx + NNODES;
    float*          s_val  = reinterpret_cast<float*>(s_cand + NNODES);
    float*          s_hrow = s_val + NNODES;
    unsigned*       s_hist = reinterpret_cast<unsigned*>(s_hrow + NHEDGES);
    unsigned*       s_wsum = s_hist + 256;
    unsigned*       s_wexc = s_wsum + 8;
    __shared__ int s_b, s_rank, s_cnt, s_ccnt;

    const int tid  = threadIdx.x;
    const int lane = tid & 31;
    const int warp = tid >> 5;
    const int row  = blockIdx.x;
    const size_t abase = (size_t)row * N;
    const unsigned lane_lt = (1u << lane) - 1u;

    if (tid < 256) s_hist[tid] = 0u;
    __syncthreads();

    // load approx row + fused high-byte histogram; load exact H row i
    {
        const uint4* g4 = reinterpret_cast<const uint4*>(Abf + abase);
        uint4*       s4 = reinterpret_cast<uint4*>(s_apx);
        const int n8 = N / 8;
        for (int j0 = 0; j0 < n8; j0 += RK_THREADS) {
            const int j = j0 + tid;
            const bool pred = (j < n8);
            uint4 k = make_uint4(0u, 0u, 0u, 0u);
            if (pred) { k = g4[j]; s4[j] = k; }
            const unsigned act = __ballot_sync(0xFFFFFFFFu, pred);
            if (pred) {
                const unsigned w[4] = {k.x, k.y, k.z, k.w};
#pragma unroll
                for (int q = 0; q < 4; q++) {
                    const unsigned blo = (w[q] >> 8) & 0xFFu;
                    const unsigned bhi = (w[q] >> 24);
                    unsigned peers = __match_any_sync(act, blo);
                    if (lane == (int)(__ffs(peers) - 1))
                        atomicAdd(&s_hist[blo], __popc(peers));
                    peers = __match_any_sync(act, bhi);
                    if (lane == (int)(__ffs(peers) - 1))
                        atomicAdd(&s_hist[bhi], __popc(peers));
                }
            }
        }
        const float4* h4 = reinterpret_cast<const float4*>(H + (size_t)row * Kd);
        if (tid < Kd / 4)
            reinterpret_cast<float4*>(s_hrow)[tid] = h4[tid];
    }
    __syncthreads();

    auto select256 = [&](int rank_in) {
        const unsigned h = (tid < 256) ? s_hist[tid] : 0u;
        unsigned v = h;
#pragma unroll
        for (int off = 1; off < 32; off <<= 1) {
            const unsigned u = __shfl_down_sync(0xFFFFFFFFu, v, off);
            if (lane + off < 32) v += u;
        }
        if (tid < 256 && lane == 0) s_wsum[warp] = v;
        __syncthreads();
        if (warp == 0) {
            unsigned wv = (lane < 8) ? s_wsum[lane] : 0u;
#pragma unroll
            for (int off = 1; off < 8; off <<= 1) {
                const unsigned u = __shfl_down_sync(0xFFFFFFFFu, wv, off);
                if (lane + off < 32) wv += u;
            }
            if (lane < 8) s_wexc[lane] = wv - s_wsum[lane];
        }
        __syncthreads();
        if (tid < 256) {
            const unsigned Sb = s_wexc[warp] + v;
            if ((int)Sb >= rank_in && (int)(Sb - h) < rank_in) {
                s_b = tid; s_rank = rank_in - (int)(Sb - h); s_cnt = (int)h;
            }
        }
        __syncthreads();
    };

    // a32 pass 1 (high byte)
    select256(TOPK);
    const unsigned b1 = (unsigned)s_b;
    const int rank1 = s_rank;
    __syncthreads();

    // a32 pass 2 (low byte among high == b1)
    if (tid < 256) s_hist[tid] = 0u;
    __syncthreads();
    for (int j0 = 0; j0 < N; j0 += RK_THREADS) {
        const int j = j0 + tid;
        bool pred = false; unsigned k = 0u;
        if (j < N) { k = s_apx[j]; pred = ((k >> 8) == b1); }
        const unsigned act = __ballot_sync(0xFFFFFFFFu, pred);
        if (pred) {
            const unsigned bin = k & 0xFFu;
            const unsigned peers = __match_any_sync(act, bin);
            if (lane == (int)(__ffs(peers) - 1))
                atomicAdd(&s_hist[bin], __popc(peers));
        }
    }
    __syncthreads();
    select256(rank1);
    const unsigned a32key = (b1 << 8) | (unsigned)s_b;
    __syncthreads();

    // gather candidates
    const bool zerocase = (a32key == 0u);
    const float cutf = zerocase ? 0.0f
        : (__uint_as_float(a32key << 16) * 0.9692f);
    if (tid == 0) s_ccnt = 0;
    __syncthreads();
    for (int j0 = 0; j0 < N; j0 += RK_THREADS) {
        const int j = j0 + tid;
        bool pred = false;
        if (j < N) {
            const unsigned k = s_apx[j];
            pred = zerocase ? (k != 0u)
                            : (__uint_as_float(k << 16) >= cutf);
        }
        const unsigned m = __ballot_sync(0xFFFFFFFFu, pred);
        int cb = 0;
        if (lane == 0 && m) cb = atomicAdd(&s_ccnt, __popc(m));
        cb = __shfl_sync(0xFFFFFFFFu, cb, 0);
        if (pred) s_cand[cb + __popc(m & lane_lt)] = (unsigned short)j;
    }
    __syncthreads();
    const int cnt = s_ccnt;

    // exact dots for candidates (ascending-k fmaf; frozen-kernel bit chain)
    for (int c = tid; c < cnt; c += RK_THREADS) {
        const int j = s_cand[c];
        const float4* b4 = reinterpret_cast<const float4*>(H + (size_t)j * Kd);
        float acc = 0.0f;
#pragma unroll 4
        for (int k4 = 0; k4 < NHEDGES / 4; k4++) {
            const float4 bv = __ldg(&b4[k4]);
            const float4 av = *reinterpret_cast<const float4*>(&s_hrow[k4 * 4]);
            acc = fmaf(av.x, bv.x, acc);
            acc = fmaf(av.y, bv.y, acc);
            acc = fmaf(av.z, bv.z, acc);
            acc = fmaf(av.w, bv.w, acc);
        }
        s_val[c] = acc;
    }
    __syncthreads();

    // exact threshold T among candidates (== 32nd overall) + jax tie rule
    float Tval = 0.0f;
    if (!zerocase) {
        unsigned prefix = 0u;
        int rank = TOPK, cntEq = 0;
        for (int shift = 24; shift >= 0; shift -= 8) {
            if (tid < 256) s_hist[tid] = 0u;
            __syncthreads();
            const unsigned hm = (shift == 24) ? 0u : (0xFFFFFFFFu << (shift + 8));
            for (int c = tid; c < cnt; c += RK_THREADS) {
                const unsigned k = __float_as_uint(s_val[c]);
                if ((k & hm) == prefix)
                    atomicAdd(&s_hist[(k >> shift) & 0xFFu], 1u);
            }
            __syncthreads();
            select256(rank);
            prefix |= ((unsigned)s_b << shift);
            rank  = s_rank;
            cntEq = s_cnt;
            __syncthreads();
        }
        Tval = __uint_as_float(prefix);

        if (cntEq > rank) {
            if (tid == 0) {
                for (int c = 0; c < cnt; c++) s_apx[c] = 0;
                for (int it = 0; it < rank; it++) {
                    int bestc = -1, bestj = 0x7FFFFFFF;
                    for (int c = 0; c < cnt; c++)
                        if (!s_apx[c] && __float_as_uint(s_val[c]) == prefix
                            && (int)s_cand[c] < bestj) {
                            bestj = s_cand[c]; bestc = c;
                        }
                    s_apx[bestc] = 1;
                }
                for (int c = 0; c < cnt; c++)
                    if (!s_apx[c] && __float_as_uint(s_val[c]) == prefix)
                        s_val[c] = -1.0f;
            }
            __syncthreads();
        }
    }

    // write output row: zeros + kept exact values
    {
        float4* o4 = reinterpret_cast<float4*>(out + abase);
        const float4 z = make_float4(0.f, 0.f, 0.f, 0.f);
        for (int j = tid; j < N / 4; j += RK_THREADS) o4[j] = z;
        __syncthreads();
        for (int c = tid; c < cnt; c += RK_THREADS) {
            const float v = s_val[c];
            const bool keep = zerocase ? (v > 0.0f) : (v >= Tval);
            if (keep) out[abase + s_cand[c]] = v;
        }
    }
}

// ---------------------------------------------------------------------------
// kernel_launch
// ---------------------------------------------------------------------------
extern "C" void kernel_launch(void* const* d_in, const int* in_sizes, int n_in,
                              void* d_out, int out_size)
{
    (void)in_sizes; (void)n_in; (void)out_size;

    const int*   idx   = (const int*)  d_in[0];
    const float* embn  = (const float*)d_in[1];
    const float* embhe = (const float*)d_in[2];
    const float* W1    = (const float*)d_in[3];
    const float* b1    = (const float*)d_in[4];
    const float* W2    = (const float*)d_in[5];
    const float* b2    = (const float*)d_in[6];
    float*       out   = (float*)d_out;

    float *p_nv1 = nullptr, *p_nv2 = nullptr, *p_H = nullptr;
    __nv_bfloat16 *p_Hbf = nullptr, *p_Abf = nullptr;
    cudaGetSymbolAddress((void**)&p_nv1, g_nv1);
    cudaGetSymbolAddress((void**)&p_nv2, g_nv2);
    cudaGetSymbolAddress((void**)&p_H,   g_H);
    cudaGetSymbolAddress((void**)&p_Hbf, g_Hbf);
    cudaGetSymbolAddress((void**)&p_Abf, g_Abf);

    cudaFuncSetAttribute(nodevec_kernel,
                         cudaFuncAttributeMaxDynamicSharedMemorySize, NV_SMEM);
    cudaFuncSetAttribute(approx_mma_kernel,
                         cudaFuncAttributeMaxDynamicSharedMemorySize, ASMEM);
    cudaFuncSetAttribute(rowselect_kernel,
                         cudaFuncAttributeMaxDynamicSharedMemorySize, RK_SMEM);

    // 1) nodevecs
    nodevec_kernel<<<NNODES / NV_ROWS, EDIM, NV_SMEM>>>(embn, idx, W1, b1,
                                                        p_nv1, NNODES);
    nodevec_kernel<<<NHEDGES / NV_ROWS, EDIM, NV_SMEM>>>(embhe, nullptr, W2, b2,
                                                         p_nv2, NHEDGES);

    // 2) H (fp32, frozen bit-path) + bf16 copy
    {
        dim3 grid((NHEDGES + GT_TM - 1) / GT_TM, (NNODES + GT_TM - 1) / GT_TM);
        h_gemm_kernel<<<grid, 256>>>(p_nv1, p_nv2, p_H, p_Hbf,
                                     NNODES, NHEDGES, EDIM);
    }

    // 3) approx adj = bf16(Hbf @ Hbf^T), tensor cores, symmetric tiles
    {
        const int nt = (NNODES + GT_TM - 1) / GT_TM;
        dim3 grid(nt, nt);
        approx_mma_kernel<<<grid, 256, ASMEM>>>(p_Hbf, p_Abf, NNODES, NHEDGES);
    }

    // 4) per-row certified top-32: exact dots for candidates only
    rowselect_kernel<<<NNODES, RK_THREADS, RK_SMEM>>>(p_Abf, p_H, out,
                                                      NNODES, NHEDGES);
}

// round 10
// speedup vs baseline: 1.9370x; 1.4893x over previous
#include <cuda_runtime.h>
#include <cuda_bf16.h>
#include <math.h>

// ---------------------------------------------------------------------------
// Problem constants
// ---------------------------------------------------------------------------
#define NNODES  10000
#define NHEDGES 512
#define EDIM    128
#define TOPK    32
#define ALPHA   3.0f

// ---------------------------------------------------------------------------
// Scratch (device globals -- no runtime allocation allowed)
// ---------------------------------------------------------------------------
__device__ float          g_nv1[NNODES * EDIM];
__device__ float          g_nv2[NHEDGES * EDIM];
__device__ float          g_H  [NNODES * NHEDGES];          // exact H (fp32)
__device__ __nv_bfloat16  g_Hbf[NNODES * NHEDGES];          // bf16(H)
__device__ __nv_bfloat16  g_Abf[(size_t)NNODES * NNODES];   // approx adj (bf16)

// ---------------------------------------------------------------------------
// Kernel 1: nodevec = tanh(ALPHA*(emb[row]@W + b)), 8 rows/block, W in SMEM.
// ---------------------------------------------------------------------------
#define NV_ROWS 8
#define NV_SMEM ((EDIM * EDIM + NV_ROWS * EDIM) * 4)

__global__ void __launch_bounds__(EDIM) nodevec_kernel(
    const float* __restrict__ emb,
    const int*   __restrict__ idx,
    const float* __restrict__ W,
    const float* __restrict__ b,
    float*       __restrict__ out,
    int nrows)
{
    extern __shared__ __align__(16) float nv_smem[];
    float* sW   = nv_smem;
    float* s_in = nv_smem + EDIM * EDIM;

    const int tid = threadIdx.x;
    const int r0  = blockIdx.x * NV_ROWS;

    const float4* Wv  = reinterpret_cast<const float4*>(W);
    float4*       sWv = reinterpret_cast<float4*>(sW);
#pragma unroll
    for (int i = 0; i < (EDIM * EDIM / 4) / EDIM; i++)
        sWv[i * EDIM + tid] = Wv[i * EDIM + tid];

#pragma unroll
    for (int q = 0; q < NV_ROWS; q++) {
        const int r  = r0 + q;
        const int sr = (r < nrows) ? (idx ? idx[r] : r) : 0;
        s_in[q * EDIM + tid] = emb[(size_t)sr * EDIM + tid];
    }
    __syncthreads();

    float acc[NV_ROWS];
    const float bd = b[tid];
#pragma unroll
    for (int q = 0; q < NV_ROWS; q++) acc[q] = bd;

#pragma unroll 4
    for (int k = 0; k < EDIM; k++) {
        const float w = sW[k * EDIM + tid];
#pragma unroll
        for (int q = 0; q < NV_ROWS; q++)
            acc[q] = fmaf(s_in[q * EDIM + k], w, acc[q]);
    }

#pragma unroll
    for (int q = 0; q < NV_ROWS; q++) {
        const int r = r0 + q;
        if (r < nrows)
            out[(size_t)r * EDIM + tid] = tanhf(ALPHA * acc[q]);
    }
}

// ---------------------------------------------------------------------------
// Kernel 2: H = relu(tanh(3 * nv1 @ nv2^T))  (proven bit-path) + bf16 copy.
// ---------------------------------------------------------------------------
#define GT_TM 128
#define GT_BK 16

__global__ void __launch_bounds__(256, 2) h_gemm_kernel(
    const float* __restrict__ A,
    const float* __restrict__ B,
    float*         __restrict__ C,
    __nv_bfloat16* __restrict__ Cbf,
    int M, int N, int Kd)
{
    __shared__ __align__(16) float As[2][GT_BK][GT_TM];
    __shared__ __align__(16) float Bs[2][GT_BK][GT_TM];

    const int tid = threadIdx.x;
    const int bm  = blockIdx.y * GT_TM;
    const int bn  = blockIdx.x * GT_TM;
    const int tx  = tid & 15;
    const int ty  = tid >> 4;

    float acc[8][8];
#pragma unroll
    for (int i = 0; i < 8; i++)
#pragma unroll
        for (int j = 0; j < 8; j++) acc[i][j] = 0.0f;

    auto stage = [&](int buf, int k0) {
#pragma unroll
        for (int s = 0; s < 2; s++) {
            const int f  = tid + s * 256;
            const int r  = f >> 2;
            const int kq = (f & 3) << 2;
            const int ga = bm + r;
            float4 va = make_float4(0.f, 0.f, 0.f, 0.f);
            if (ga < M)
                va = *reinterpret_cast<const float4*>(A + (size_t)ga * Kd + k0 + kq);
            As[buf][kq + 0][r] = va.x; As[buf][kq + 1][r] = va.y;
            As[buf][kq + 2][r] = va.z; As[buf][kq + 3][r] = va.w;

            const int gb = bn + r;
            float4 vb = make_float4(0.f, 0.f, 0.f, 0.f);
            if (gb < N)
                vb = *reinterpret_cast<const float4*>(B + (size_t)gb * Kd + k0 + kq);
            Bs[buf][kq + 0][r] = vb.x; Bs[buf][kq + 1][r] = vb.y;
            Bs[buf][kq + 2][r] = vb.z; Bs[buf][kq + 3][r] = vb.w;
        }
    };

    stage(0, 0);
    __syncthreads();

    const int nk = Kd / GT_BK;
    for (int kt = 0; kt < nk; kt++) {
        const int cur = kt & 1;
        if (kt + 1 < nk) stage(cur ^ 1, (kt + 1) * GT_BK);

#pragma unroll
        for (int kk = 0; kk < GT_BK; kk++) {
            float a[8], b[8];
#pragma unroll
            for (int i = 0; i < 8; i += 4)
                *reinterpret_cast<float4*>(&a[i]) =
                    *reinterpret_cast<const float4*>(&As[cur][kk][ty * 8 + i]);
#pragma unroll
            for (int j = 0; j < 8; j += 4)
                *reinterpret_cast<float4*>(&b[j]) =
                    *reinterpret_cast<const float4*>(&Bs[cur][kk][tx * 8 + j]);
#pragma unroll
            for (int i = 0; i < 8; i++)
#pragma unroll
                for (int j = 0; j < 8; j++)
                    acc[i][j] = fmaf(a[i], b[j], acc[i][j]);
        }
        __syncthreads();
    }

#pragma unroll
    for (int i = 0; i < 8; i++) {
        const int gr = bm + ty * 8 + i;
        if (gr >= M) continue;
        float*         crow = C   + (size_t)gr * N;
        __nv_bfloat16* brow = Cbf + (size_t)gr * N;
#pragma unroll
        for (int j = 0; j < 8; j += 4) {
            const int gc = bn + tx * 8 + j;
            float4 v;
            v.x = fmaxf(tanhf(ALPHA * acc[i][j + 0]), 0.0f);
            v.y = fmaxf(tanhf(ALPHA * acc[i][j + 1]), 0.0f);
            v.z = fmaxf(tanhf(ALPHA * acc[i][j + 2]), 0.0f);
            v.w = fmaxf(tanhf(ALPHA * acc[i][j + 3]), 0.0f);
            if (gc + 3 < N) {
                *reinterpret_cast<float4*>(crow + gc) = v;
                brow[gc + 0] = __float2bfloat16(v.x);
                brow[gc + 1] = __float2bfloat16(v.y);
                brow[gc + 2] = __float2bfloat16(v.z);
                brow[gc + 3] = __float2bfloat16(v.w);
            } else {
                const float vv[4] = {v.x, v.y, v.z, v.w};
                for (int q = 0; q < 4; q++)
                    if (gc + q < N) {
                        crow[gc + q] = vv[q];
                        brow[gc + q] = __float2bfloat16(vv[q]);
                    }
            }
        }
    }
}

// ---------------------------------------------------------------------------
// Kernel 3: approx adj = bf16( Hbf @ Hbf^T ), bf16 MMA + fp32 accum.
// launch_bounds (256,2): 2 CTAs/SM to hide barrier + ldmatrix latency.
// ---------------------------------------------------------------------------
#define ABKC  32
#define APADK 40
#define AARR  (128 * APADK)
#define ABUF  (2 * AARR)
#define ASMEM (128 * 133 * 4)     // 68096 >= mainloop 40960; 2 CTAs fit in 228KB

#define LDSM_X4(r, addr) \
    asm volatile("ldmatrix.sync.aligned.m8n8.x4.shared.b16 {%0,%1,%2,%3}, [%4];" \
        : "=r"((r)[0]), "=r"((r)[1]), "=r"((r)[2]), "=r"((r)[3]) : "r"(addr))
#define LDSM_X2(r, addr) \
    asm volatile("ldmatrix.sync.aligned.m8n8.x2.shared.b16 {%0,%1}, [%2];" \
        : "=r"((r)[0]), "=r"((r)[1]) : "r"(addr))
#define MMA_BF16(d, a, b) \
    asm volatile("mma.sync.aligned.m16n8k16.row.col.f32.bf16.bf16.f32 " \
        "{%0,%1,%2,%3},{%4,%5,%6,%7},{%8,%9},{%0,%1,%2,%3};" \
        : "+f"((d)[0]), "+f"((d)[1]), "+f"((d)[2]), "+f"((d)[3]) \
        : "r"((a)[0]), "r"((a)[1]), "r"((a)[2]), "r"((a)[3]), "r"((b)[0]), "r"((b)[1]))

__global__ void __launch_bounds__(256, 2) approx_mma_kernel(
    const __nv_bfloat16* __restrict__ Hbf,
    __nv_bfloat16* __restrict__ C,
    int M, int Kd)
{
    extern __shared__ __align__(16) unsigned char dynsmem[];
    __nv_bfloat16* s = reinterpret_cast<__nv_bfloat16*>(dynsmem);

    const int by = blockIdx.y, bx = blockIdx.x;
    if (bx < by) return;
    const int bm  = by * GT_TM, bn = bx * GT_TM;
    const int tid = threadIdx.x;
    const int lane = tid & 31, warp = tid >> 5;
    const int wm = warp >> 2;
    const int wn = warp & 3;

    const unsigned sbase = (unsigned)__cvta_generic_to_shared(s);

    auto stage = [&](int buf, int k0) {
#pragma unroll
        for (int a = 0; a < 2; a++) {
            const int rowbase = (a == 0) ? bm : bn;
#pragma unroll
            for (int sIt = 0; sIt < 2; sIt++) {
                const int idx  = tid + sIt * 256;
                const int row  = idx >> 2;
                const int unit = idx & 3;
                const int grow = rowbase + row;
                const int cpsz = (grow < M) ? 16 : 0;
                const void* src = Hbf + (size_t)(grow < M ? grow : 0) * Kd
                                      + k0 + unit * 8;
                const unsigned dst = sbase +
                    (unsigned)((buf * ABUF + a * AARR + row * APADK + unit * 8) * 2);
                asm volatile("cp.async.cg.shared.global [%0], [%1], 16, %2;\n"
                             :: "r"(dst), "l"(src), "r"(cpsz));
            }
        }
        asm volatile("cp.async.commit_group;\n" ::: "memory");
    };

    float acc[4][4][4];
#pragma unroll
    for (int i = 0; i < 4; i++)
#pragma unroll
        for (int j = 0; j < 4; j++)
#pragma unroll
            for (int q = 0; q < 4; q++) acc[i][j][q] = 0.0f;

    const int nk = Kd / ABKC;
    stage(0, 0);

    for (int kt = 0; kt < nk; kt++) {
        const int cur = kt & 1;
        if (kt + 1 < nk) {
            stage(cur ^ 1, (kt + 1) * ABKC);
            asm volatile("cp.async.wait_group 1;\n" ::: "memory");
        } else {
            asm volatile("cp.async.wait_group 0;\n" ::: "memory");
        }
        __syncthreads();

        const unsigned bA = sbase + (unsigned)((cur * ABUF + 0 * AARR) * 2);
        const unsigned bB = sbase + (unsigned)((cur * ABUF + 1 * AARR) * 2);

#pragma unroll
        for (int kk = 0; kk < 2; kk++) {
            unsigned ra[4][4], rb[4][2];
            const int arow = wm * 64 + (lane & 15);
            const int acol = kk * 16 + (lane >> 4) * 8;
#pragma unroll
            for (int mf = 0; mf < 4; mf++)
                LDSM_X4(ra[mf], bA + (unsigned)(((arow + mf * 16) * APADK + acol) * 2));
            const int brow = wn * 32 + (lane & 7);
            const int bcol = kk * 16 + ((lane >> 3) & 1) * 8;
#pragma unroll
            for (int nf = 0; nf < 4; nf++)
                LDSM_X2(rb[nf], bB + (unsigned)(((brow + nf * 8) * APADK + bcol) * 2));
#pragma unroll
            for (int mf = 0; mf < 4; mf++)
#pragma unroll
                for (int nf = 0; nf < 4; nf++)
                    MMA_BF16(acc[mf][nf], ra[mf], rb[nf]);
        }
        __syncthreads();
    }

    float* Ct = reinterpret_cast<float*>(dynsmem);
#define CT(r, c) Ct[(r) * 133 + (c)]

#pragma unroll
    for (int mf = 0; mf < 4; mf++) {
#pragma unroll
        for (int nf = 0; nf < 4; nf++) {
            const int r0 = wm * 64 + mf * 16 + (lane >> 2);
            const int c0 = wn * 32 + nf * 8 + (lane & 3) * 2;
            const __nv_bfloat16 b0 = __float2bfloat16(acc[mf][nf][0]);
            const __nv_bfloat16 b1 = __float2bfloat16(acc[mf][nf][1]);
            const __nv_bfloat16 b2 = __float2bfloat16(acc[mf][nf][2]);
            const __nv_bfloat16 b3 = __float2bfloat16(acc[mf][nf][3]);
            CT(r0, c0)     = __bfloat162float(b0);
            CT(r0, c0 + 1) = __bfloat162float(b1);
            CT(r0 + 8, c0)     = __bfloat162float(b2);
            CT(r0 + 8, c0 + 1) = __bfloat162float(b3);

            const int gc = bn + c0;               // even; M even -> gc+1 < M
            const int gr0 = bm + r0, gr1 = bm + r0 + 8;
            if (gr0 < M && gc < M) {
                __nv_bfloat162 p; p.x = b0; p.y = b1;
                *reinterpret_cast<__nv_bfloat162*>(C + (size_t)gr0 * M + gc) = p;
            }
            if (gr1 < M && gc < M) {
                __nv_bfloat162 p; p.x = b2; p.y = b3;
                *reinterpret_cast<__nv_bfloat162*>(C + (size_t)gr1 * M + gc) = p;
            }
        }
    }
    __syncthreads();

    for (int i = tid; i < 128 * 128; i += 256) {
        const int r2 = i >> 7;
        const int c2 = i & 127;
        const int gR = bn + r2, gC = bm + c2;
        if (gR < M && gC < M)
            C[(size_t)gR * M + gC] = __float2bfloat16(CT(c2, r2));
    }
#undef CT
}

// ---------------------------------------------------------------------------
// Kernel 4: per-row certified top-K, ladder version.
//   - fused load + max-reduce (no atomics)
//   - 256-bucket LINEAR histogram over [f*max, max], f in {0.9, 0.6, 0}:
//     only tail elements touch atomics, spread across buckets.
//   - bucket lower-edge = certified LOWER bound of a32  ->  cut = lb*0.9692
//   - candidates -> exact ascending-k fmaf dots (frozen bit chain)
//   - exact 8-bit radix among candidates, jax tie rule, scatter write
//   - full-exact fallback (dense dots + proven radix) for degenerate rows.
// ---------------------------------------------------------------------------
#define RK_THREADS 256
#define RK_CMAX    2048
// smem: s_row f32[10000] (union: s_apx u16[10000] in first half) | s_val
//       f32[2048] | s_cand u16[2048] | s_hrow f32[512] | hist u32[256] | wsum/wexc
#define RK_OFF_VAL  40000
#define RK_OFF_CAND 48192
#define RK_OFF_HROW 52288
#define RK_OFF_HIST 54336
#define RK_OFF_WS   55360
#define RK_SMEM     55552

__global__ void __launch_bounds__(RK_THREADS, 4) rowselect_kernel(
    const __nv_bfloat16* __restrict__ Abf,
    const float*         __restrict__ H,
    float*               __restrict__ out,
    int N, int Kd)
{
    extern __shared__ __align__(16) unsigned char sm[];
    float*          s_row  = reinterpret_cast<float*>(sm);                 // [N] (fallback)
    unsigned short* s_apx  = reinterpret_cast<unsigned short*>(sm);        // [N] (normal)
    float*          s_val  = reinterpret_cast<float*>(sm + RK_OFF_VAL);    // [CMAX]
    unsigned short* s_cand = reinterpret_cast<unsigned short*>(sm + RK_OFF_CAND);
    float*          s_hrow = reinterpret_cast<float*>(sm + RK_OFF_HROW);   // [512]
    unsigned*       s_hist = reinterpret_cast<unsigned*>(sm + RK_OFF_HIST);// [256]
    unsigned*       s_wsum = reinterpret_cast<unsigned*>(sm + RK_OFF_WS);  // [8]
    unsigned*       s_wexc = s_wsum + 8;                                   // [8]
    __shared__ int   s_b, s_rank, s_cnt, s_ccnt;
    __shared__ float sh_fmax;

    const int tid  = threadIdx.x;
    const int lane = tid & 31;
    const int warp = tid >> 5;
    const int row  = blockIdx.x;
    const size_t abase = (size_t)row * N;
    const unsigned lane_lt = (1u << lane) - 1u;

    // ---- load approx row + fused max reduce; load exact H row ----
    unsigned um = 0u;
    {
        const uint4* g4 = reinterpret_cast<const uint4*>(Abf + abase);
        uint4*       s4 = reinterpret_cast<uint4*>(s_apx);
        const int n8 = N / 8;
        for (int j = tid; j < n8; j += RK_THREADS) {
            const uint4 k = g4[j];
            s4[j] = k;
            unsigned w;
            w = k.x; um = max(um, w & 0xFFFFu); um = max(um, w >> 16);
            w = k.y; um = max(um, w & 0xFFFFu); um = max(um, w >> 16);
            w = k.z; um = max(um, w & 0xFFFFu); um = max(um, w >> 16);
            w = k.w; um = max(um, w & 0xFFFFu); um = max(um, w >> 16);
        }
        const float4* h4 = reinterpret_cast<const float4*>(H + (size_t)row * Kd);
        if (tid < Kd / 4)
            reinterpret_cast<float4*>(s_hrow)[tid] = h4[tid];
    }
#pragma unroll
    for (int off = 16; off > 0; off >>= 1)
        um = max(um, __shfl_xor_sync(0xFFFFFFFFu, um, off));
    if (lane == 0) s_wsum[warp] = um;
    __syncthreads();
    if (tid == 0) {
        unsigned m = 0u;
        for (int i = 0; i < RK_THREADS / 32; i++) m = max(m, s_wsum[i]);
        sh_fmax = __uint_as_float(m << 16);
    }
    __syncthreads();
    const float vmax = sh_fmax;

    // all-zero approx row => exact row identically 0 => output zeros
    if (vmax <= 0.0f) {
        float4* o4 = reinterpret_cast<float4*>(out + abase);
        const float4 z = make_float4(0.f, 0.f, 0.f, 0.f);
        for (int j = tid; j < N / 4; j += RK_THREADS) o4[j] = z;
        return;
    }

    // ---- 256-bin Kth select helper (suffix over bin index) ----
    auto select256 = [&](int rank_in) {
        const unsigned h = s_hist[tid];
        unsigned v = h;
#pragma unroll
        for (int off = 1; off < 32; off <<= 1) {
            const unsigned u = __shfl_down_sync(0xFFFFFFFFu, v, off);
            if (lane + off < 32) v += u;
        }
        if (lane == 0) s_wsum[warp] = v;
        __syncthreads();
        if (warp == 0) {
            unsigned wv = (lane < 8) ? s_wsum[lane] : 0u;
#pragma unroll
            for (int off = 1; off < 8; off <<= 1) {
                const unsigned u = __shfl_down_sync(0xFFFFFFFFu, wv, off);
                if (lane + off < 32) wv += u;
            }
            if (lane < 8) s_wexc[lane] = wv - s_wsum[lane];
        }
        __syncthreads();
        {
            const unsigned Sb = s_wexc[warp] + v;   // count of bins >= tid
            if ((int)Sb >= rank_in && (int)(Sb - h) < rank_in) {
                s_b = tid; s_rank = rank_in - (int)(Sb - h); s_cnt = (int)h;
            }
        }
        __syncthreads();
    };

    // ---- ladder: find certified lower bound of a32 ----
    bool fallback = false;
    float cutLB = -1.0f;
    {
        const float fr[3] = {0.90f, 0.60f, 0.0f};
        for (int at = 0; at < 3; at++) {
            const float lo  = fr[at] * vmax;
            const float rng = vmax - lo;
            const float inv = 256.0f / rng;
            const float w   = rng * (1.0f / 256.0f);
            s_hist[tid] = 0u;
            if (tid == 0) s_b = -1;
            __syncthreads();
            for (int j = tid; j < N; j += RK_THREADS) {
                const float v = __uint_as_float((unsigned)s_apx[j] << 16);
                if (v >= lo) {
                    int b = (int)((vmax - v) * inv);
                    b = 255 - min(b, 255);            // high value -> high bin
                    atomicAdd(&s_hist[b], 1u);
                }
            }
            __syncthreads();
            select256(TOPK);
            const int found = s_b;
            __syncthreads();
            if (found >= 0) {
                const int u = 255 - found;
                cutLB = vmax - (float)(u + 2) * w;    // 1 bucket fp safety
                break;
            }
        }
        if (cutLB <= 0.0f) fallback = true;
    }

    int cnt = 0;
    if (!fallback) {
        // ---- gather candidates: A >= cutLB * (1-b)/(1+b) ----
        const float cut = cutLB * 0.9692f;
        if (tid == 0) s_ccnt = 0;
        __syncthreads();
        for (int j0 = 0; j0 < N; j0 += RK_THREADS) {
            const int j = j0 + tid;
            bool pred = false;
            if (j < N)
                pred = (__uint_as_float((unsigned)s_apx[j] << 16) >= cut);
            const unsigned m = __ballot_sync(0xFFFFFFFFu, pred);
            int cb = 0;
            if (lane == 0 && m) cb = atomicAdd(&s_ccnt, __popc(m));
            cb = __shfl_sync(0xFFFFFFFFu, cb, 0);
            if (pred) {
                const int pos = cb + __popc(m & lane_lt);
                if (pos < RK_CMAX) s_cand[pos] = (unsigned short)j;
            }
        }
        __syncthreads();
        cnt = s_ccnt;
        if (cnt > RK_CMAX) fallback = true;
    }

    if (!fallback) {
        // ---- exact dots (ascending-k fmaf: frozen-kernel bit chain) ----
        for (int c = tid; c < cnt; c += RK_THREADS) {
            const int j = s_cand[c];
            const float4* b4 = reinterpret_cast<const float4*>(H + (size_t)j * Kd);
            float acc = 0.0f;
#pragma unroll 4
            for (int k4 = 0; k4 < NHEDGES / 4; k4++) {
                const float4 bv = __ldg(&b4[k4]);
                const float4 av = *reinterpret_cast<const float4*>(&s_hrow[k4 * 4]);
                acc = fmaf(av.x, bv.x, acc);
                acc = fmaf(av.y, bv.y, acc);
                acc = fmaf(av.z, bv.z, acc);
                acc = fmaf(av.w, bv.w, acc);
            }
            s_val[c] = acc;
        }
        __syncthreads();

        // ---- exact threshold (4x8-bit radix among candidates) + jax ties --
        unsigned prefix = 0u;
        int rank = TOPK, cntEq = 0;
        for (int shift = 24; shift >= 0; shift -= 8) {
            s_hist[tid] = 0u;
            __syncthreads();
            const unsigned hm = (shift == 24) ? 0u : (0xFFFFFFFFu << (shift + 8));
            for (int c = tid; c < cnt; c += RK_THREADS) {
                const unsigned k = __float_as_uint(s_val[c]);
                if ((k & hm) == prefix)
                    atomicAdd(&s_hist[(k >> shift) & 0xFFu], 1u);
            }
            __syncthreads();
            select256(rank);
            prefix |= ((unsigned)s_b << shift);
            rank  = s_rank;
            cntEq = s_cnt;
            __syncthreads();
        }
        const float Tval = __uint_as_float(prefix);

        if (cntEq > rank) {
            if (tid == 0) {
                for (int c = 0; c < cnt; c++) s_apx[c] = 0;   // reuse as flags
                for (int it = 0; it < rank; it++) {
                    int bestc = -1, bestj = 0x7FFFFFFF;
                    for (int c = 0; c < cnt; c++)
                        if (!s_apx[c] && __float_as_uint(s_val[c]) == prefix
                            && (int)s_cand[c] < bestj) {
                            bestj = s_cand[c]; bestc = c;
                        }
                    s_apx[bestc] = 1;
                }
                for (int c = 0; c < cnt; c++)
                    if (!s_apx[c] && __float_as_uint(s_val[c]) == prefix)
                        s_val[c] = -1.0f;
            }
            __syncthreads();
        }

        // ---- zero + scatter exact kept values ----
        float4* o4 = reinterpret_cast<float4*>(out + abase);
        const float4 z = make_float4(0.f, 0.f, 0.f, 0.f);
        for (int j = tid; j < N / 4; j += RK_THREADS) o4[j] = z;
        __syncthreads();
        for (int c = tid; c < cnt; c += RK_THREADS) {
            const float v = s_val[c];
            if (v >= Tval) out[abase + s_cand[c]] = v;
        }
        return;
    }

    // ================= full-exact fallback (degenerate rows) ================
    __syncthreads();
    for (int j = tid; j < N; j += RK_THREADS) {
        const float4* b4 = reinterpret_cast<const float4*>(H + (size_t)j * Kd);
        float acc = 0.0f;
#pragma unroll 4
        for (int k4 = 0; k4 < NHEDGES / 4; k4++) {
            const float4 bv = __ldg(&b4[k4]);
            const float4 av = *reinterpret_cast<const float4*>(&s_hrow[k4 * 4]);
            acc = fmaf(av.x, bv.x, acc);
            acc = fmaf(av.y, bv.y, acc);
            acc = fmaf(av.z, bv.z, acc);
            acc = fmaf(av.w, bv.w, acc);
        }
        s_row[j] = acc;
    }
    __syncthreads();

    unsigned prefix = 0u;
    int rank = TOPK, cntEq = 0;
    for (int shift = 24; shift >= 0; shift -= 8) {
        s_hist[tid] = 0u;
        __syncthreads();
        const unsigned hm = (shift == 24) ? 0u : (0xFFFFFFFFu << (shift + 8));
        for (int j = tid; j < N; j += RK_THREADS) {
            const unsigned k = __float_as_uint(s_row[j]);
            if ((k & hm) == prefix)
                atomicAdd(&s_hist[(k >> shift) & 0xFFu], 1u);
        }
        __syncthreads();
        select256(rank);
        prefix |= ((unsigned)s_b << shift);
        rank  = s_rank;
        cntEq = s_cnt;
        __syncthreads();
    }
    const float Tval = __uint_as_float(prefix);

    if (cntEq > rank) {
        if (tid == 0) {
            int kept = 0;
            for (int j = 0; j < N; j++) {
                if (__float_as_uint(s_row[j]) == prefix) {
                    kept++;
                    if (kept > rank) s_row[j] = -1.0f;
                }
            }
        }
        __syncthreads();
    }

    for (int j = tid; j < N; j += RK_THREADS) {
        const float v = s_row[j];
        out[abase + j] = (v >= Tval) ? v : 0.0f;
    }
}

// ---------------------------------------------------------------------------
// kernel_launch
// ---------------------------------------------------------------------------
extern "C" void kernel_launch(void* const* d_in, const int* in_sizes, int n_in,
                              void* d_out, int out_size)
{
    (void)in_sizes; (void)n_in; (void)out_size;

    const int*   idx   = (const int*)  d_in[0];
    const float* embn  = (const float*)d_in[1];
    const float* embhe = (const float*)d_in[2];
    const float* W1    = (const float*)d_in[3];
    const float* b1    = (const float*)d_in[4];
    const float* W2    = (const float*)d_in[5];
    const float* b2    = (const float*)d_in[6];
    float*       out   = (float*)d_out;

    float *p_nv1 = nullptr, *p_nv2 = nullptr, *p_H = nullptr;
    __nv_bfloat16 *p_Hbf = nullptr, *p_Abf = nullptr;
    cudaGetSymbolAddress((void**)&p_nv1, g_nv1);
    cudaGetSymbolAddress((void**)&p_nv2, g_nv2);
    cudaGetSymbolAddress((void**)&p_H,   g_H);
    cudaGetSymbolAddress((void**)&p_Hbf, g_Hbf);
    cudaGetSymbolAddress((void**)&p_Abf, g_Abf);

    cudaFuncSetAttribute(nodevec_kernel,
                         cudaFuncAttributeMaxDynamicSharedMemorySize, NV_SMEM);
    cudaFuncSetAttribute(approx_mma_kernel,
                         cudaFuncAttributeMaxDynamicSharedMemorySize, ASMEM);
    cudaFuncSetAttribute(rowselect_kernel,
                         cudaFuncAttributeMaxDynamicSharedMemorySize, RK_SMEM);

    // 1) nodevecs
    nodevec_kernel<<<NNODES / NV_ROWS, EDIM, NV_SMEM>>>(embn, idx, W1, b1,
                                                        p_nv1, NNODES);
    nodevec_kernel<<<NHEDGES / NV_ROWS, EDIM, NV_SMEM>>>(embhe, nullptr, W2, b2,
                                                         p_nv2, NHEDGES);

    // 2) H (fp32, frozen bit-path) + bf16 copy
    {
        dim3 grid((NHEDGES + GT_TM - 1) / GT_TM, (NNODES + GT_TM - 1) / GT_TM);
        h_gemm_kernel<<<grid, 256>>>(p_nv1, p_nv2, p_H, p_Hbf,
                                     NNODES, NHEDGES, EDIM);
    }

    // 3) approx adj = bf16(Hbf @ Hbf^T), tensor cores, symmetric tiles
    {
        const int nt = (NNODES + GT_TM - 1) / GT_TM;
        dim3 grid(nt, nt);
        approx_mma_kernel<<<grid, 256, ASMEM>>>(p_Hbf, p_Abf, NNODES, NHEDGES);
    }

    // 4) per-row certified top-32 (ladder + exact candidate dots)
    rowselect_kernel<<<NNODES, RK_THREADS, RK_SMEM>>>(p_Abf, p_H, out,
                                                      NNODES, NHEDGES);
}

// round 11
// speedup vs baseline: 2.3276x; 1.2017x over previous
#include <cuda_runtime.h>
#include <cuda_bf16.h>
#include <math.h>

// ---------------------------------------------------------------------------
// Problem constants
// ---------------------------------------------------------------------------
#define NNODES  10000
#define NHEDGES 512
#define EDIM    128
#define TOPK    32
#define ALPHA   3.0f
#define SENTINEL 0x7FFFFFFF

// ---------------------------------------------------------------------------
// Scratch (device globals -- no runtime allocation allowed)
// ---------------------------------------------------------------------------
#define SK_CMAX 6144
__device__ float          g_nv1[NNODES * EDIM];
__device__ float          g_nv2[NHEDGES * EDIM];
__device__ float          g_H  [NNODES * NHEDGES];          // exact H (fp32)
__device__ __nv_bfloat16  g_Hbf[NNODES * NHEDGES];          // bf16(H)
__device__ __nv_bfloat16  g_Abf[(size_t)NNODES * NNODES];   // approx adj (bf16)
__device__ unsigned short g_cand[(size_t)NNODES * SK_CMAX]; // per-row candidates
__device__ int            g_ccnt[NNODES];                   // per-row counts

// ---------------------------------------------------------------------------
// Kernel 1: nodevec (unchanged)
// ---------------------------------------------------------------------------
#define NV_ROWS 8
#define NV_SMEM ((EDIM * EDIM + NV_ROWS * EDIM) * 4)

__global__ void __launch_bounds__(EDIM) nodevec_kernel(
    const float* __restrict__ emb,
    const int*   __restrict__ idx,
    const float* __restrict__ W,
    const float* __restrict__ b,
    float*       __restrict__ out,
    int nrows)
{
    extern __shared__ __align__(16) float nv_smem[];
    float* sW   = nv_smem;
    float* s_in = nv_smem + EDIM * EDIM;

    const int tid = threadIdx.x;
    const int r0  = blockIdx.x * NV_ROWS;

    const float4* Wv  = reinterpret_cast<const float4*>(W);
    float4*       sWv = reinterpret_cast<float4*>(sW);
#pragma unroll
    for (int i = 0; i < (EDIM * EDIM / 4) / EDIM; i++)
        sWv[i * EDIM + tid] = Wv[i * EDIM + tid];

#pragma unroll
    for (int q = 0; q < NV_ROWS; q++) {
        const int r  = r0 + q;
        const int sr = (r < nrows) ? (idx ? idx[r] : r) : 0;
        s_in[q * EDIM + tid] = emb[(size_t)sr * EDIM + tid];
    }
    __syncthreads();

    float acc[NV_ROWS];
    const float bd = b[tid];
#pragma unroll
    for (int q = 0; q < NV_ROWS; q++) acc[q] = bd;

#pragma unroll 4
    for (int k = 0; k < EDIM; k++) {
        const float w = sW[k * EDIM + tid];
#pragma unroll
        for (int q = 0; q < NV_ROWS; q++)
            acc[q] = fmaf(s_in[q * EDIM + k], w, acc[q]);
    }

#pragma unroll
    for (int q = 0; q < NV_ROWS; q++) {
        const int r = r0 + q;
        if (r < nrows)
            out[(size_t)r * EDIM + tid] = tanhf(ALPHA * acc[q]);
    }
}

// ---------------------------------------------------------------------------
// Kernel 2: H (fp32, frozen bit-path) + bf16 copy (unchanged)
// ---------------------------------------------------------------------------
#define GT_TM 128
#define GT_BK 16

__global__ void __launch_bounds__(256, 2) h_gemm_kernel(
    const float* __restrict__ A,
    const float* __restrict__ B,
    float*         __restrict__ C,
    __nv_bfloat16* __restrict__ Cbf,
    int M, int N, int Kd)
{
    __shared__ __align__(16) float As[2][GT_BK][GT_TM];
    __shared__ __align__(16) float Bs[2][GT_BK][GT_TM];

    const int tid = threadIdx.x;
    const int bm  = blockIdx.y * GT_TM;
    const int bn  = blockIdx.x * GT_TM;
    const int tx  = tid & 15;
    const int ty  = tid >> 4;

    float acc[8][8];
#pragma unroll
    for (int i = 0; i < 8; i++)
#pragma unroll
        for (int j = 0; j < 8; j++) acc[i][j] = 0.0f;

    auto stage = [&](int buf, int k0) {
#pragma unroll
        for (int s = 0; s < 2; s++) {
            const int f  = tid + s * 256;
            const int r  = f >> 2;
            const int kq = (f & 3) << 2;
            const int ga = bm + r;
            float4 va = make_float4(0.f, 0.f, 0.f, 0.f);
            if (ga < M)
                va = *reinterpret_cast<const float4*>(A + (size_t)ga * Kd + k0 + kq);
            As[buf][kq + 0][r] = va.x; As[buf][kq + 1][r] = va.y;
            As[buf][kq + 2][r] = va.z; As[buf][kq + 3][r] = va.w;

            const int gb = bn + r;
            float4 vb = make_float4(0.f, 0.f, 0.f, 0.f);
            if (gb < N)
                vb = *reinterpret_cast<const float4*>(B + (size_t)gb * Kd + k0 + kq);
            Bs[buf][kq + 0][r] = vb.x; Bs[buf][kq + 1][r] = vb.y;
            Bs[buf][kq + 2][r] = vb.z; Bs[buf][kq + 3][r] = vb.w;
        }
    };

    stage(0, 0);
    __syncthreads();

    const int nk = Kd / GT_BK;
    for (int kt = 0; kt < nk; kt++) {
        const int cur = kt & 1;
        if (kt + 1 < nk) stage(cur ^ 1, (kt + 1) * GT_BK);

#pragma unroll
        for (int kk = 0; kk < GT_BK; kk++) {
            float a[8], b[8];
#pragma unroll
            for (int i = 0; i < 8; i += 4)
                *reinterpret_cast<float4*>(&a[i]) =
                    *reinterpret_cast<const float4*>(&As[cur][kk][ty * 8 + i]);
#pragma unroll
            for (int j = 0; j < 8; j += 4)
                *reinterpret_cast<float4*>(&b[j]) =
                    *reinterpret_cast<const float4*>(&Bs[cur][kk][tx * 8 + j]);
#pragma unroll
            for (int i = 0; i < 8; i++)
#pragma unroll
                for (int j = 0; j < 8; j++)
                    acc[i][j] = fmaf(a[i], b[j], acc[i][j]);
        }
        __syncthreads();
    }

#pragma unroll
    for (int i = 0; i < 8; i++) {
        const int gr = bm + ty * 8 + i;
        if (gr >= M) continue;
        float*         crow = C   + (size_t)gr * N;
        __nv_bfloat16* brow = Cbf + (size_t)gr * N;
#pragma unroll
        for (int j = 0; j < 8; j += 4) {
            const int gc = bn + tx * 8 + j;
            float4 v;
            v.x = fmaxf(tanhf(ALPHA * acc[i][j + 0]), 0.0f);
            v.y = fmaxf(tanhf(ALPHA * acc[i][j + 1]), 0.0f);
            v.z = fmaxf(tanhf(ALPHA * acc[i][j + 2]), 0.0f);
            v.w = fmaxf(tanhf(ALPHA * acc[i][j + 3]), 0.0f);
            if (gc + 3 < N) {
                *reinterpret_cast<float4*>(crow + gc) = v;
                brow[gc + 0] = __float2bfloat16(v.x);
                brow[gc + 1] = __float2bfloat16(v.y);
                brow[gc + 2] = __float2bfloat16(v.z);
                brow[gc + 3] = __float2bfloat16(v.w);
            } else {
                const float vv[4] = {v.x, v.y, v.z, v.w};
                for (int q = 0; q < 4; q++)
                    if (gc + q < N) {
                        crow[gc + q] = vv[q];
                        brow[gc + q] = __float2bfloat16(vv[q]);
                    }
            }
        }
    }
}

// ---------------------------------------------------------------------------
// Kernel 3: approx adj = bf16( Hbf @ Hbf^T )  (unchanged from R10)
// ---------------------------------------------------------------------------
#define ABKC  32
#define APADK 40
#define AARR  (128 * APADK)
#define ABUF  (2 * AARR)
#define ASMEM (128 * 133 * 4)

#define LDSM_X4(r, addr) \
    asm volatile("ldmatrix.sync.aligned.m8n8.x4.shared.b16 {%0,%1,%2,%3}, [%4];" \
        : "=r"((r)[0]), "=r"((r)[1]), "=r"((r)[2]), "=r"((r)[3]) : "r"(addr))
#define LDSM_X2(r, addr) \
    asm volatile("ldmatrix.sync.aligned.m8n8.x2.shared.b16 {%0,%1}, [%2];" \
        : "=r"((r)[0]), "=r"((r)[1]) : "r"(addr))
#define MMA_BF16(d, a, b) \
    asm volatile("mma.sync.aligned.m16n8k16.row.col.f32.bf16.bf16.f32 " \
        "{%0,%1,%2,%3},{%4,%5,%6,%7},{%8,%9},{%0,%1,%2,%3};" \
        : "+f"((d)[0]), "+f"((d)[1]), "+f"((d)[2]), "+f"((d)[3]) \
        : "r"((a)[0]), "r"((a)[1]), "r"((a)[2]), "r"((a)[3]), "r"((b)[0]), "r"((b)[1]))

__global__ void __launch_bounds__(256, 2) approx_mma_kernel(
    const __nv_bfloat16* __restrict__ Hbf,
    __nv_bfloat16* __restrict__ C,
    int M, int Kd)
{
    extern __shared__ __align__(16) unsigned char dynsmem[];
    __nv_bfloat16* s = reinterpret_cast<__nv_bfloat16*>(dynsmem);

    const int by = blockIdx.y, bx = blockIdx.x;
    if (bx < by) return;
    const int bm  = by * GT_TM, bn = bx * GT_TM;
    const int tid = threadIdx.x;
    const int lane = tid & 31, warp = tid >> 5;
    const int wm = warp >> 2;
    const int wn = warp & 3;

    const unsigned sbase = (unsigned)__cvta_generic_to_shared(s);

    auto stage = [&](int buf, int k0) {
#pragma unroll
        for (int a = 0; a < 2; a++) {
            const int rowbase = (a == 0) ? bm : bn;
#pragma unroll
            for (int sIt = 0; sIt < 2; sIt++) {
                const int idx  = tid + sIt * 256;
                const int row  = idx >> 2;
                const int unit = idx & 3;
                const int grow = rowbase + row;
                const int cpsz = (grow < M) ? 16 : 0;
                const void* src = Hbf + (size_t)(grow < M ? grow : 0) * Kd
                                      + k0 + unit * 8;
                const unsigned dst = sbase +
                    (unsigned)((buf * ABUF + a * AARR + row * APADK + unit * 8) * 2);
                asm volatile("cp.async.cg.shared.global [%0], [%1], 16, %2;\n"
                             :: "r"(dst), "l"(src), "r"(cpsz));
            }
        }
        asm volatile("cp.async.commit_group;\n" ::: "memory");
    };

    float acc[4][4][4];
#pragma unroll
    for (int i = 0; i < 4; i++)
#pragma unroll
        for (int j = 0; j < 4; j++)
#pragma unroll
            for (int q = 0; q < 4; q++) acc[i][j][q] = 0.0f;

    const int nk = Kd / ABKC;
    stage(0, 0);

    for (int kt = 0; kt < nk; kt++) {
        const int cur = kt & 1;
        if (kt + 1 < nk) {
            stage(cur ^ 1, (kt + 1) * ABKC);
            asm volatile("cp.async.wait_group 1;\n" ::: "memory");
        } else {
            asm volatile("cp.async.wait_group 0;\n" ::: "memory");
        }
        __syncthreads();

        const unsigned bA = sbase + (unsigned)((cur * ABUF + 0 * AARR) * 2);
        const unsigned bB = sbase + (unsigned)((cur * ABUF + 1 * AARR) * 2);

#pragma unroll
        for (int kk = 0; kk < 2; kk++) {
            unsigned ra[4][4], rb[4][2];
            const int arow = wm * 64 + (lane & 15);
            const int acol = kk * 16 + (lane >> 4) * 8;
#pragma unroll
            for (int mf = 0; mf < 4; mf++)
                LDSM_X4(ra[mf], bA + (unsigned)(((arow + mf * 16) * APADK + acol) * 2));
            const int brow = wn * 32 + (lane & 7);
            const int bcol = kk * 16 + ((lane >> 3) & 1) * 8;
#pragma unroll
            for (int nf = 0; nf < 4; nf++)
                LDSM_X2(rb[nf], bB + (unsigned)(((brow + nf * 8) * APADK + bcol) * 2));
#pragma unroll
            for (int mf = 0; mf < 4; mf++)
#pragma unroll
                for (int nf = 0; nf < 4; nf++)
                    MMA_BF16(acc[mf][nf], ra[mf], rb[nf]);
        }
        __syncthreads();
    }

    float* Ct = reinterpret_cast<float*>(dynsmem);
#define CT(r, c) Ct[(r) * 133 + (c)]

#pragma unroll
    for (int mf = 0; mf < 4; mf++) {
#pragma unroll
        for (int nf = 0; nf < 4; nf++) {
            const int r0 = wm * 64 + mf * 16 + (lane >> 2);
            const int c0 = wn * 32 + nf * 8 + (lane & 3) * 2;
            const __nv_bfloat16 b0 = __float2bfloat16(acc[mf][nf][0]);
            const __nv_bfloat16 b1 = __float2bfloat16(acc[mf][nf][1]);
            const __nv_bfloat16 b2 = __float2bfloat16(acc[mf][nf][2]);
            const __nv_bfloat16 b3 = __float2bfloat16(acc[mf][nf][3]);
            CT(r0, c0)     = __bfloat162float(b0);
            CT(r0, c0 + 1) = __bfloat162float(b1);
            CT(r0 + 8, c0)     = __bfloat162float(b2);
            CT(r0 + 8, c0 + 1) = __bfloat162float(b3);

            const int gc = bn + c0;
            const int gr0 = bm + r0, gr1 = bm + r0 + 8;
            if (gr0 < M && gc < M) {
                __nv_bfloat162 p; p.x = b0; p.y = b1;
                *reinterpret_cast<__nv_bfloat162*>(C + (size_t)gr0 * M + gc) = p;
            }
            if (gr1 < M && gc < M) {
                __nv_bfloat162 p; p.x = b2; p.y = b3;
                *reinterpret_cast<__nv_bfloat162*>(C + (size_t)gr1 * M + gc) = p;
            }
        }
    }
    __syncthreads();

    for (int i = tid; i < 128 * 128; i += 256) {
        const int r2 = i >> 7;
        const int c2 = i & 127;
        const int gR = bn + r2, gC = bm + c2;
        if (gR < M && gC < M)
            C[(size_t)gR * M + gC] = __float2bfloat16(CT(c2, r2));
    }
#undef CT
}

// ---------------------------------------------------------------------------
// Shared helper: 256-bin Kth select (suffix over bin index). 256 threads.
// ---------------------------------------------------------------------------
__device__ __forceinline__ void select256_fn(
    const unsigned* s_hist, unsigned* s_wsum, unsigned* s_wexc,
    int* s_b, int* s_rank, int* s_cnt, int rank_in, int tid)
{
    const int lane = tid & 31, warp = tid >> 5;
    const unsigned h = s_hist[tid];
    unsigned v = h;
#pragma unroll
    for (int off = 1; off < 32; off <<= 1) {
        const unsigned u = __shfl_down_sync(0xFFFFFFFFu, v, off);
        if (lane + off < 32) v += u;
    }
    if (lane == 0) s_wsum[warp] = v;
    __syncthreads();
    if (warp == 0) {
        unsigned wv = (lane < 8) ? s_wsum[lane] : 0u;
#pragma unroll
        for (int off = 1; off < 8; off <<= 1) {
            const unsigned u = __shfl_down_sync(0xFFFFFFFFu, wv, off);
            if (lane + off < 32) wv += u;
        }
        if (lane < 8) s_wexc[lane] = wv - s_wsum[lane];
    }
    __syncthreads();
    {
        const unsigned Sb = s_wexc[warp] + v;   // count of bins >= tid
        if ((int)Sb >= rank_in && (int)(Sb - h) < rank_in) {
            *s_b = tid; *s_rank = rank_in - (int)(Sb - h); *s_cnt = (int)h;
        }
    }
    __syncthreads();
}

// ---------------------------------------------------------------------------
// Kernel 4a: per-row candidate generation + output-row zeroing.
// ladder lower-bound of a32 -> certified cut = 0.988 * lb  (delta <= 0.59%,
// (1-d)/(1+d) = 0.98827 > 0.988).
// ---------------------------------------------------------------------------
#define CK_THREADS 256
#define CK_SMEM (NNODES * 2 + 256 * 4 + 64)

__global__ void __launch_bounds__(CK_THREADS, 4) cand_kernel(
    const __nv_bfloat16* __restrict__ Abf,
    float*          __restrict__ out,
    unsigned short* __restrict__ cand,
    int*            __restrict__ ccnt,
    int N)
{
    extern __shared__ __align__(16) unsigned char sm[];
    unsigned short* s_apx  = reinterpret_cast<unsigned short*>(sm);          // [N]
    unsigned*       s_hist = reinterpret_cast<unsigned*>(sm + NNODES * 2);   // [256]
    unsigned*       s_wsum = s_hist + 256;                                   // [8]
    unsigned*       s_wexc = s_wsum + 8;                                     // [8]
    __shared__ int   s_b, s_rank, s_cnt, s_ccnt;
    __shared__ float sh_fmax;

    const int tid  = threadIdx.x;
    const int lane = tid & 31;
    const int warp = tid >> 5;
    const int row  = blockIdx.x;
    const size_t abase = (size_t)row * N;
    const unsigned lane_lt = (1u << lane) - 1u;

    // zero the output row (fire-and-forget stores)
    {
        float4* o4 = reinterpret_cast<float4*>(out + abase);
        const float4 z = make_float4(0.f, 0.f, 0.f, 0.f);
        for (int j = tid; j < N / 4; j += CK_THREADS) o4[j] = z;
    }

    // load approx row + fused max reduce
    unsigned um = 0u;
    {
        const uint4* g4 = reinterpret_cast<const uint4*>(Abf + abase);
        uint4*       s4 = reinterpret_cast<uint4*>(s_apx);
        const int n8 = N / 8;
        for (int j = tid; j < n8; j += CK_THREADS) {
            const uint4 k = g4[j];
            s4[j] = k;
            unsigned w;
            w = k.x; um = max(um, w & 0xFFFFu); um = max(um, w >> 16);
            w = k.y; um = max(um, w & 0xFFFFu); um = max(um, w >> 16);
            w = k.z; um = max(um, w & 0xFFFFu); um = max(um, w >> 16);
            w = k.w; um = max(um, w & 0xFFFFu); um = max(um, w >> 16);
        }
    }
#pragma unroll
    for (int off = 16; off > 0; off >>= 1)
        um = max(um, __shfl_xor_sync(0xFFFFFFFFu, um, off));
    if (lane == 0) s_wsum[warp] = um;
    __syncthreads();
    if (tid == 0) {
        unsigned m = 0u;
        for (int i = 0; i < CK_THREADS / 32; i++) m = max(m, s_wsum[i]);
        sh_fmax = __uint_as_float(m << 16);
    }
    __syncthreads();
    const float vmax = sh_fmax;

    if (vmax <= 0.0f) {            // all-exact-zero row; zeros already written
        if (tid == 0) ccnt[row] = 0;
        return;
    }

    // ladder: certified lower bound of a32 (32nd-largest approx)
    float cutLB = -1.0f;
    {
        const float fr[4] = {0.96f, 0.85f, 0.5f, 0.0f};
        for (int at = 0; at < 4; at++) {
            const float lo  = fr[at] * vmax;
            const float rng = vmax - lo;
            const float inv = 256.0f / rng;
            const float w   = rng * (1.0f / 256.0f);
            s_hist[tid] = 0u;
            if (tid == 0) s_b = -1;
            __syncthreads();
            for (int j = tid; j < N; j += CK_THREADS) {
                const float v = __uint_as_float((unsigned)s_apx[j] << 16);
                if (v >= lo) {
                    int bq = (int)((vmax - v) * inv);
                    bq = 255 - min(bq, 255);
                    atomicAdd(&s_hist[bq], 1u);
                }
            }
            __syncthreads();
            select256_fn(s_hist, s_wsum, s_wexc, &s_b, &s_rank, &s_cnt, TOPK, tid);
            const int found = s_b;
            __syncthreads();
            if (found >= 0) {
                const int u = 255 - found;
                cutLB = vmax - (float)(u + 2) * w;   // one-bucket fp safety
                break;
            }
        }
    }
    if (cutLB <= 0.0f) {
        if (tid == 0) ccnt[row] = SENTINEL;          // fallback row
        return;
    }

    // gather candidates: A >= cutLB * 0.988 (certified superset of true top-K)
    const float cut = cutLB * 0.988f;
    if (tid == 0) s_ccnt = 0;
    __syncthreads();
    unsigned short* crow = cand + (size_t)row * SK_CMAX;
    for (int j0 = 0; j0 < N; j0 += CK_THREADS) {
        const int j = j0 + tid;
        bool pred = false;
        if (j < N)
            pred = (__uint_as_float((unsigned)s_apx[j] << 16) >= cut);
        const unsigned m = __ballot_sync(0xFFFFFFFFu, pred);
        int cb = 0;
        if (lane == 0 && m) cb = atomicAdd(&s_ccnt, __popc(m));
        cb = __shfl_sync(0xFFFFFFFFu, cb, 0);
        if (pred) {
            const int pos = cb + __popc(m & lane_lt);
            if (pos < SK_CMAX) crow[pos] = (unsigned short)j;
        }
    }
    __syncthreads();
    if (tid == 0)
        ccnt[row] = (s_ccnt <= SK_CMAX) ? s_ccnt : SENTINEL;
}

// ---------------------------------------------------------------------------
// Kernel 4b: per-row exact dots (frozen ascending-k fmaf bit chain) + exact
// radix select + jax tie rule + scatter writes. Small SMEM -> high occupancy.
// ---------------------------------------------------------------------------
#define SK_THREADS 256
#define SK_OFF_VAL  2048
#define SK_OFF_CAND 26624
#define SK_OFF_HIST 38912
#define SK_OFF_WS   39936
#define SK_SMEM     40000

__global__ void __launch_bounds__(SK_THREADS, 4) select_kernel(
    const unsigned short* __restrict__ cand,
    const int*            __restrict__ ccnt,
    const float*          __restrict__ H,
    float*                __restrict__ out,
    int N, int Kd)
{
    const int row = blockIdx.x;
    const int cnt = ccnt[row];
    if (cnt == 0 || cnt > SK_CMAX) return;      // zero row / fallback row

    extern __shared__ __align__(16) unsigned char sm[];
    float*          s_hrow = reinterpret_cast<float*>(sm);                   // [512]
    float*          s_val  = reinterpret_cast<float*>(sm + SK_OFF_VAL);      // [CMAX]
    unsigned short* s_cand = reinterpret_cast<unsigned short*>(sm + SK_OFF_CAND);
    unsigned*       s_hist = reinterpret_cast<unsigned*>(sm + SK_OFF_HIST);  // [256]
    unsigned*       s_wsum = reinterpret_cast<unsigned*>(sm + SK_OFF_WS);    // [8]
    unsigned*       s_wexc = s_wsum + 8;                                     // [8]
    __shared__ int s_b, s_rank, s_cnt;

    const int tid = threadIdx.x;
    const size_t abase = (size_t)row * N;

    if (tid < Kd / 4)
        reinterpret_cast<float4*>(s_hrow)[tid] =
            reinterpret_cast<const float4*>(H + (size_t)row * Kd)[tid];
    {
        const unsigned short* crow = cand + (size_t)row * SK_CMAX;
        for (int c = tid; c < cnt; c += SK_THREADS) s_cand[c] = crow[c];
    }
    __syncthreads();

    // exact dots (ascending-k single-accumulator fmaf == frozen bit chain)
    for (int c = tid; c < cnt; c += SK_THREADS) {
        const int j = s_cand[c];
        const float4* b4 = reinterpret_cast<const float4*>(H + (size_t)j * Kd);
        float acc = 0.0f;
#pragma unroll 8
        for (int k4 = 0; k4 < NHEDGES / 4; k4++) {
            const float4 bv = __ldg(&b4[k4]);
            const float4 av = *reinterpret_cast<const float4*>(&s_hrow[k4 * 4]);
            acc = fmaf(av.x, bv.x, acc);
            acc = fmaf(av.y, bv.y, acc);
            acc = fmaf(av.z, bv.z, acc);
            acc = fmaf(av.w, bv.w, acc);
        }
        s_val[c] = acc;
    }
    __syncthreads();

    // exact threshold: 4x8-bit radix among candidates (== 32nd overall)
    unsigned prefix = 0u;
    int rank = TOPK, cntEq = 0;
    for (int shift = 24; shift >= 0; shift -= 8) {
        s_hist[tid] = 0u;
        __syncthreads();
        const unsigned hm = (shift == 24) ? 0u : (0xFFFFFFFFu << (shift + 8));
        for (int c = tid; c < cnt; c += SK_THREADS) {
            const unsigned k = __float_as_uint(s_val[c]);
            if ((k & hm) == prefix)
                atomicAdd(&s_hist[(k >> shift) & 0xFFu], 1u);
        }
        __syncthreads();
        select256_fn(s_hist, s_wsum, s_wexc, &s_b, &s_rank, &s_cnt, rank, tid);
        prefix |= ((unsigned)s_b << shift);
        rank  = s_rank;
        cntEq = s_cnt;
        __syncthreads();
    }
    const float Tval = __uint_as_float(prefix);

    if (cntEq > rank) {
        // jax tie rule: keep `rank` tied entries with the smallest column j.
        // (candidate order is not j-sorted -> min-j search; rare + small.)
        if (tid == 0) {
            for (int c = 0; c < cnt; c++)
                if (__float_as_uint(s_val[c]) == prefix) s_val[c] = -2.0f;
            for (int it = 0; it < rank; it++) {
                int bestc = -1, bestj = 0x7FFFFFFF;
                for (int c = 0; c < cnt; c++)
                    if (s_val[c] == -2.0f && (int)s_cand[c] < bestj) {
                        bestj = s_cand[c]; bestc = c;
                    }
                s_val[bestc] = Tval;          // restore kept tied value
            }
            for (int c = 0; c < cnt; c++)
                if (s_val[c] == -2.0f) s_val[c] = -1.0f;
        }
        __syncthreads();
    }

    for (int c = tid; c < cnt; c += SK_THREADS) {
        const float v = s_val[c];
        if (v >= Tval) out[abase + s_cand[c]] = v;
    }
}

// ---------------------------------------------------------------------------
// Kernel 4c: full-exact fallback for sentinel rows (early-exit otherwise).
// ---------------------------------------------------------------------------
#define FB_SMEM (NNODES * 4 + NHEDGES * 4 + 256 * 4 + 64)

__global__ void __launch_bounds__(256, 2) fallback_kernel(
    const int*   __restrict__ ccnt,
    const float* __restrict__ H,
    float*       __restrict__ out,
    int N, int Kd)
{
    const int row = blockIdx.x;
    if (ccnt[row] != SENTINEL) return;

    extern __shared__ __align__(16) unsigned char sm[];
    float*    s_row  = reinterpret_cast<float*>(sm);                        // [N]
    float*    s_hrow = reinterpret_cast<float*>(sm + NNODES * 4);           // [512]
    unsigned* s_hist = reinterpret_cast<unsigned*>(sm + NNODES * 4 + NHEDGES * 4);
    unsigned* s_wsum = s_hist + 256;
    unsigned* s_wexc = s_wsum + 8;
    __shared__ int s_b, s_rank, s_cnt;

    const int tid = threadIdx.x;
    const size_t abase = (size_t)row * N;

    if (tid < Kd / 4)
        reinterpret_cast<float4*>(s_hrow)[tid] =
            reinterpret_cast<const float4*>(H + (size_t)row * Kd)[tid];
    __syncthreads();

    for (int j = tid; j < N; j += 256) {
        const float4* b4 = reinterpret_cast<const float4*>(H + (size_t)j * Kd);
        float acc = 0.0f;
#pragma unroll 4
        for (int k4 = 0; k4 < NHEDGES / 4; k4++) {
            const float4 bv = __ldg(&b4[k4]);
            const float4 av = *reinterpret_cast<const float4*>(&s_hrow[k4 * 4]);
            acc = fmaf(av.x, bv.x, acc);
            acc = fmaf(av.y, bv.y, acc);
            acc = fmaf(av.z, bv.z, acc);
            acc = fmaf(av.w, bv.w, acc);
        }
        s_row[j] = acc;
    }
    __syncthreads();

    unsigned prefix = 0u;
    int rank = TOPK, cntEq = 0;
    for (int shift = 24; shift >= 0; shift -= 8) {
        s_hist[tid] = 0u;
        __syncthreads();
        const unsigned hm = (shift == 24) ? 0u : (0xFFFFFFFFu << (shift + 8));
        for (int j = tid; j < N; j += 256) {
            const unsigned k = __float_as_uint(s_row[j]);
            if ((k & hm) == prefix)
                atomicAdd(&s_hist[(k >> shift) & 0xFFu], 1u);
        }
        __syncthreads();
        select256_fn(s_hist, s_wsum, s_wexc, &s_b, &s_rank, &s_cnt, rank, tid);
        prefix |= ((unsigned)s_b << shift);
        rank  = s_rank;
        cntEq = s_cnt;
        __syncthreads();
    }
    const float Tval = __uint_as_float(prefix);

    if (cntEq > rank) {
        if (tid == 0) {
            int kept = 0;
            for (int j = 0; j < N; j++) {
                if (__float_as_uint(s_row[j]) == prefix) {
                    kept++;
                    if (kept > rank) s_row[j] = -1.0f;
                }
            }
        }
        __syncthreads();
    }

    for (int j = tid; j < N; j += 256) {
        const float v = s_row[j];
        out[abase + j] = (v >= Tval) ? v : 0.0f;
    }
}

// ---------------------------------------------------------------------------
// kernel_launch
// ---------------------------------------------------------------------------
extern "C" void kernel_launch(void* const* d_in, const int* in_sizes, int n_in,
                              void* d_out, int out_size)
{
    (void)in_sizes; (void)n_in; (void)out_size;

    const int*   idx   = (const int*)  d_in[0];
    const float* embn  = (const float*)d_in[1];
    const float* embhe = (const float*)d_in[2];
    const float* W1    = (const float*)d_in[3];
    const float* b1    = (const float*)d_in[4];
    const float* W2    = (const float*)d_in[5];
    const float* b2    = (const float*)d_in[6];
    float*       out   = (float*)d_out;

    float *p_nv1 = nullptr, *p_nv2 = nullptr, *p_H = nullptr;
    __nv_bfloat16 *p_Hbf = nullptr, *p_Abf = nullptr;
    unsigned short *p_cand = nullptr;
    int *p_ccnt = nullptr;
    cudaGetSymbolAddress((void**)&p_nv1,  g_nv1);
    cudaGetSymbolAddress((void**)&p_nv2,  g_nv2);
    cudaGetSymbolAddress((void**)&p_H,    g_H);
    cudaGetSymbolAddress((void**)&p_Hbf,  g_Hbf);
    cudaGetSymbolAddress((void**)&p_Abf,  g_Abf);
    cudaGetSymbolAddress((void**)&p_cand, g_cand);
    cudaGetSymbolAddress((void**)&p_ccnt, g_ccnt);

    cudaFuncSetAttribute(nodevec_kernel,
                         cudaFuncAttributeMaxDynamicSharedMemorySize, NV_SMEM);
    cudaFuncSetAttribute(approx_mma_kernel,
                         cudaFuncAttributeMaxDynamicSharedMemorySize, ASMEM);
    cudaFuncSetAttribute(cand_kernel,
                         cudaFuncAttributeMaxDynamicSharedMemorySize, CK_SMEM);
    cudaFuncSetAttribute(select_kernel,
                         cudaFuncAttributeMaxDynamicSharedMemorySize, SK_SMEM);
    cudaFuncSetAttribute(fallback_kernel,
                         cudaFuncAttributeMaxDynamicSharedMemorySize, FB_SMEM);

    // 1) nodevecs
    nodevec_kernel<<<NNODES / NV_ROWS, EDIM, NV_SMEM>>>(embn, idx, W1, b1,
                                                        p_nv1, NNODES);
    nodevec_kernel<<<NHEDGES / NV_ROWS, EDIM, NV_SMEM>>>(embhe, nullptr, W2, b2,
                                                         p_nv2, NHEDGES);

    // 2) H (fp32, frozen bit-path) + bf16 copy
    {
        dim3 grid((NHEDGES + GT_TM - 1) / GT_TM, (NNODES + GT_TM - 1) / GT_TM);
        h_gemm_kernel<<<grid, 256>>>(p_nv1, p_nv2, p_H, p_Hbf,
                                     NNODES, NHEDGES, EDIM);
    }

    // 3) approx adj = bf16(Hbf @ Hbf^T)
    {
        const int nt = (NNODES + GT_TM - 1) / GT_TM;
        dim3 grid(nt, nt);
        approx_mma_kernel<<<grid, 256, ASMEM>>>(p_Hbf, p_Abf, NNODES, NHEDGES);
    }

    // 4) certified top-32 pipeline: candidates -> exact select -> fallback
    cand_kernel<<<NNODES, CK_THREADS, CK_SMEM>>>(p_Abf, out, p_cand, p_ccnt,
                                                 NNODES);
    select_kernel<<<NNODES, SK_THREADS, SK_SMEM>>>(p_cand, p_ccnt, p_H, out,
                                                   NNODES, NHEDGES);
    fallback_kernel<<<NNODES, 256, FB_SMEM>>>(p_ccnt, p_H, out,
                                              NNODES, NHEDGES);
}

// round 12
// speedup vs baseline: 2.4521x; 1.0535x over previous
#include <cuda_runtime.h>
#include <cuda_fp16.h>
#include <math.h>

// ---------------------------------------------------------------------------
// Problem constants
// ---------------------------------------------------------------------------
#define NNODES  10000
#define NHEDGES 512
#define EDIM    128
#define TOPK    32
#define ALPHA   3.0f
#define SENTINEL 0x7FFFFFFF

// ---------------------------------------------------------------------------
// Scratch (device globals -- no runtime allocation allowed)
// ---------------------------------------------------------------------------
#define SK_CMAX 4096
__device__ float          g_nv1[NNODES * EDIM];
__device__ float          g_nv2[NHEDGES * EDIM];
__device__ float          g_H  [NNODES * NHEDGES];          // exact H (fp32)
__device__ __half         g_Hhf[NNODES * NHEDGES];          // fp16(H)
__device__ __half         g_Ahf[(size_t)NNODES * NNODES];   // approx adj (fp16)
__device__ unsigned short g_cand[(size_t)NNODES * SK_CMAX]; // per-row candidates
__device__ int            g_ccnt[NNODES];                   // per-row counts

// ---------------------------------------------------------------------------
// Kernel 1: nodevec (unchanged)
// ---------------------------------------------------------------------------
#define NV_ROWS 8
#define NV_SMEM ((EDIM * EDIM + NV_ROWS * EDIM) * 4)

__global__ void __launch_bounds__(EDIM) nodevec_kernel(
    const float* __restrict__ emb,
    const int*   __restrict__ idx,
    const float* __restrict__ W,
    const float* __restrict__ b,
    float*       __restrict__ out,
    int nrows)
{
    extern __shared__ __align__(16) float nv_smem[];
    float* sW   = nv_smem;
    float* s_in = nv_smem + EDIM * EDIM;

    const int tid = threadIdx.x;
    const int r0  = blockIdx.x * NV_ROWS;

    const float4* Wv  = reinterpret_cast<const float4*>(W);
    float4*       sWv = reinterpret_cast<float4*>(sW);
#pragma unroll
    for (int i = 0; i < (EDIM * EDIM / 4) / EDIM; i++)
        sWv[i * EDIM + tid] = Wv[i * EDIM + tid];

#pragma unroll
    for (int q = 0; q < NV_ROWS; q++) {
        const int r  = r0 + q;
        const int sr = (r < nrows) ? (idx ? idx[r] : r) : 0;
        s_in[q * EDIM + tid] = emb[(size_t)sr * EDIM + tid];
    }
    __syncthreads();

    float acc[NV_ROWS];
    const float bd = b[tid];
#pragma unroll
    for (int q = 0; q < NV_ROWS; q++) acc[q] = bd;

#pragma unroll 4
    for (int k = 0; k < EDIM; k++) {
        const float w = sW[k * EDIM + tid];
#pragma unroll
        for (int q = 0; q < NV_ROWS; q++)
            acc[q] = fmaf(s_in[q * EDIM + k], w, acc[q]);
    }

#pragma unroll
    for (int q = 0; q < NV_ROWS; q++) {
        const int r = r0 + q;
        if (r < nrows)
            out[(size_t)r * EDIM + tid] = tanhf(ALPHA * acc[q]);
    }
}

// ---------------------------------------------------------------------------
// Kernel 2: H (fp32, frozen bit-path) + fp16 copy.
// ---------------------------------------------------------------------------
#define GT_TM 128
#define GT_BK 16

__global__ void __launch_bounds__(256, 2) h_gemm_kernel(
    const float* __restrict__ A,
    const float* __restrict__ B,
    float*  __restrict__ C,
    __half* __restrict__ Chf,
    int M, int N, int Kd)
{
    __shared__ __align__(16) float As[2][GT_BK][GT_TM];
    __shared__ __align__(16) float Bs[2][GT_BK][GT_TM];

    const int tid = threadIdx.x;
    const int bm  = blockIdx.y * GT_TM;
    const int bn  = blockIdx.x * GT_TM;
    const int tx  = tid & 15;
    const int ty  = tid >> 4;

    float acc[8][8];
#pragma unroll
    for (int i = 0; i < 8; i++)
#pragma unroll
        for (int j = 0; j < 8; j++) acc[i][j] = 0.0f;

    auto stage = [&](int buf, int k0) {
#pragma unroll
        for (int s = 0; s < 2; s++) {
            const int f  = tid + s * 256;
            const int r  = f >> 2;
            const int kq = (f & 3) << 2;
            const int ga = bm + r;
            float4 va = make_float4(0.f, 0.f, 0.f, 0.f);
            if (ga < M)
                va = *reinterpret_cast<const float4*>(A + (size_t)ga * Kd + k0 + kq);
            As[buf][kq + 0][r] = va.x; As[buf][kq + 1][r] = va.y;
            As[buf][kq + 2][r] = va.z; As[buf][kq + 3][r] = va.w;

            const int gb = bn + r;
            float4 vb = make_float4(0.f, 0.f, 0.f, 0.f);
            if (gb < N)
                vb = *reinterpret_cast<const float4*>(B + (size_t)gb * Kd + k0 + kq);
            Bs[buf][kq + 0][r] = vb.x; Bs[buf][kq + 1][r] = vb.y;
            Bs[buf][kq + 2][r] = vb.z; Bs[buf][kq + 3][r] = vb.w;
        }
    };

    stage(0, 0);
    __syncthreads();

    const int nk = Kd / GT_BK;
    for (int kt = 0; kt < nk; kt++) {
        const int cur = kt & 1;
        if (kt + 1 < nk) stage(cur ^ 1, (kt + 1) * GT_BK);

#pragma unroll
        for (int kk = 0; kk < GT_BK; kk++) {
            float a[8], b[8];
#pragma unroll
            for (int i = 0; i < 8; i += 4)
                *reinterpret_cast<float4*>(&a[i]) =
                    *reinterpret_cast<const float4*>(&As[cur][kk][ty * 8 + i]);
#pragma unroll
            for (int j = 0; j < 8; j += 4)
                *reinterpret_cast<float4*>(&b[j]) =
                    *reinterpret_cast<const float4*>(&Bs[cur][kk][tx * 8 + j]);
#pragma unroll
            for (int i = 0; i < 8; i++)
#pragma unroll
                for (int j = 0; j < 8; j++)
                    acc[i][j] = fmaf(a[i], b[j], acc[i][j]);
        }
        __syncthreads();
    }

#pragma unroll
    for (int i = 0; i < 8; i++) {
        const int gr = bm + ty * 8 + i;
        if (gr >= M) continue;
        float*  crow = C   + (size_t)gr * N;
        __half* hrow = Chf + (size_t)gr * N;
#pragma unroll
        for (int j = 0; j < 8; j += 4) {
            const int gc = bn + tx * 8 + j;
            float4 v;
            v.x = fmaxf(tanhf(ALPHA * acc[i][j + 0]), 0.0f);
            v.y = fmaxf(tanhf(ALPHA * acc[i][j + 1]), 0.0f);
            v.z = fmaxf(tanhf(ALPHA * acc[i][j + 2]), 0.0f);
            v.w = fmaxf(tanhf(ALPHA * acc[i][j + 3]), 0.0f);
            if (gc + 3 < N) {
                *reinterpret_cast<float4*>(crow + gc) = v;
                hrow[gc + 0] = __float2half(v.x);
                hrow[gc + 1] = __float2half(v.y);
                hrow[gc + 2] = __float2half(v.z);
                hrow[gc + 3] = __float2half(v.w);
            } else {
                const float vv[4] = {v.x, v.y, v.z, v.w};
                for (int q = 0; q < 4; q++)
                    if (gc + q < N) {
                        crow[gc + q] = vv[q];
                        hrow[gc + q] = __float2half(vv[q]);
                    }
            }
        }
    }
}

// ---------------------------------------------------------------------------
// Kernel 3: approx adj = fp16( Hhf @ Hhf^T ), fp16 MMA + fp32 accum.
// Nonneg terms -> rigorous |v - A| <= 0.152%*A + 3e-5 absolute.
// ---------------------------------------------------------------------------
#define ABKC  32
#define APADK 40
#define AARR  (128 * APADK)
#define ABUF  (2 * AARR)
#define ASMEM (128 * 133 * 4)

#define LDSM_X4(r, addr) \
    asm volatile("ldmatrix.sync.aligned.m8n8.x4.shared.b16 {%0,%1,%2,%3}, [%4];" \
        : "=r"((r)[0]), "=r"((r)[1]), "=r"((r)[2]), "=r"((r)[3]) : "r"(addr))
#define LDSM_X2(r, addr) \
    asm volatile("ldmatrix.sync.aligned.m8n8.x2.shared.b16 {%0,%1}, [%2];" \
        : "=r"((r)[0]), "=r"((r)[1]) : "r"(addr))
#define MMA_F16(d, a, b) \
    asm volatile("mma.sync.aligned.m16n8k16.row.col.f32.f16.f16.f32 " \
        "{%0,%1,%2,%3},{%4,%5,%6,%7},{%8,%9},{%0,%1,%2,%3};" \
        : "+f"((d)[0]), "+f"((d)[1]), "+f"((d)[2]), "+f"((d)[3]) \
        : "r"((a)[0]), "r"((a)[1]), "r"((a)[2]), "r"((a)[3]), "r"((b)[0]), "r"((b)[1]))

__global__ void __launch_bounds__(256, 2) approx_mma_kernel(
    const __half* __restrict__ Hhf,
    __half* __restrict__ C,
    int M, int Kd)
{
    extern __shared__ __align__(16) unsigned char dynsmem[];
    __half* s = reinterpret_cast<__half*>(dynsmem);

    const int by = blockIdx.y, bx = blockIdx.x;
    if (bx < by) return;
    const int bm  = by * GT_TM, bn = bx * GT_TM;
    const int tid = threadIdx.x;
    const int lane = tid & 31, warp = tid >> 5;
    const int wm = warp >> 2;
    const int wn = warp & 3;

    const unsigned sbase = (unsigned)__cvta_generic_to_shared(s);

    auto stage = [&](int buf, int k0) {
#pragma unroll
        for (int a = 0; a < 2; a++) {
            const int rowbase = (a == 0) ? bm : bn;
#pragma unroll
            for (int sIt = 0; sIt < 2; sIt++) {
                const int idx  = tid + sIt * 256;
                const int row  = idx >> 2;
                const int unit = idx & 3;
                const int grow = rowbase + row;
                const int cpsz = (grow < M) ? 16 : 0;
                const void* src = Hhf + (size_t)(grow < M ? grow : 0) * Kd
                                      + k0 + unit * 8;
                const unsigned dst = sbase +
                    (unsigned)((buf * ABUF + a * AARR + row * APADK + unit * 8) * 2);
                asm volatile("cp.async.cg.shared.global [%0], [%1], 16, %2;\n"
                             :: "r"(dst), "l"(src), "r"(cpsz));
            }
        }
        asm volatile("cp.async.commit_group;\n" ::: "memory");
    };

    float acc[4][4][4];
#pragma unroll
    for (int i = 0; i < 4; i++)
#pragma unroll
        for (int j = 0; j < 4; j++)
#pragma unroll
            for (int q = 0; q < 4; q++) acc[i][j][q] = 0.0f;

    const int nk = Kd / ABKC;
    stage(0, 0);

    for (int kt = 0; kt < nk; kt++) {
        const int cur = kt & 1;
        if (kt + 1 < nk) {
            stage(cur ^ 1, (kt + 1) * ABKC);
            asm volatile("cp.async.wait_group 1;\n" ::: "memory");
        } else {
            asm volatile("cp.async.wait_group 0;\n" ::: "memory");
        }
        __syncthreads();

        const unsigned bA = sbase + (unsigned)((cur * ABUF + 0 * AARR) * 2);
        const unsigned bB = sbase + (unsigned)((cur * ABUF + 1 * AARR) * 2);

#pragma unroll
        for (int kk = 0; kk < 2; kk++) {
            unsigned ra[4][4], rb[4][2];
            const int arow = wm * 64 + (lane & 15);
            const int acol = kk * 16 + (lane >> 4) * 8;
#pragma unroll
            for (int mf = 0; mf < 4; mf++)
                LDSM_X4(ra[mf], bA + (unsigned)(((arow + mf * 16) * APADK + acol) * 2));
            const int brow = wn * 32 + (lane & 7);
            const int bcol = kk * 16 + ((lane >> 3) & 1) * 8;
#pragma unroll
            for (int nf = 0; nf < 4; nf++)
                LDSM_X2(rb[nf], bB + (unsigned)(((brow + nf * 8) * APADK + bcol) * 2));
#pragma unroll
            for (int mf = 0; mf < 4; mf++)
#pragma unroll
                for (int nf = 0; nf < 4; nf++)
                    MMA_F16(acc[mf][nf], ra[mf], rb[nf]);
        }
        __syncthreads();
    }

    float* Ct = reinterpret_cast<float*>(dynsmem);
#define CT(r, c) Ct[(r) * 133 + (c)]

#pragma unroll
    for (int mf = 0; mf < 4; mf++) {
#pragma unroll
        for (int nf = 0; nf < 4; nf++) {
            const int r0 = wm * 64 + mf * 16 + (lane >> 2);
            const int c0 = wn * 32 + nf * 8 + (lane & 3) * 2;
            const __half h0 = __float2half(acc[mf][nf][0]);
            const __half h1 = __float2half(acc[mf][nf][1]);
            const __half h2 = __float2half(acc[mf][nf][2]);
            const __half h3 = __float2half(acc[mf][nf][3]);
            CT(r0, c0)     = __half2float(h0);
            CT(r0, c0 + 1) = __half2float(h1);
            CT(r0 + 8, c0)     = __half2float(h2);
            CT(r0 + 8, c0 + 1) = __half2float(h3);

            const int gc = bn + c0;               // even; M even -> gc+1 < M
            const int gr0 = bm + r0, gr1 = bm + r0 + 8;
            if (gr0 < M && gc < M) {
                __half2 p; p.x = h0; p.y = h1;
                *reinterpret_cast<__half2*>(C + (size_t)gr0 * M + gc) = p;
            }
            if (gr1 < M && gc < M) {
                __half2 p; p.x = h2; p.y = h3;
                *reinterpret_cast<__half2*>(C + (size_t)gr1 * M + gc) = p;
            }
        }
    }
    __syncthreads();

    for (int i = tid; i < 128 * 128; i += 256) {
        const int r2 = i >> 7;
        const int c2 = i & 127;
        const int gR = bn + r2, gC = bm + c2;
        if (gR < M && gC < M)
            C[(size_t)gR * M + gC] = __float2half(CT(c2, r2));
    }
#undef CT
}

// ---------------------------------------------------------------------------
// Shared helper: 256-bin Kth select (suffix over bin index). 256 threads.
// ---------------------------------------------------------------------------
__device__ __forceinline__ void select256_fn(
    const unsigned* s_hist, unsigned* s_wsum, unsigned* s_wexc,
    int* s_b, int* s_rank, int* s_cnt, int rank_in, int tid)
{
    const int lane = tid & 31, warp = tid >> 5;
    const unsigned h = s_hist[tid];
    unsigned v = h;
#pragma unroll
    for (int off = 1; off < 32; off <<= 1) {
        const unsigned u = __shfl_down_sync(0xFFFFFFFFu, v, off);
        if (lane + off < 32) v += u;
    }
    if (lane == 0) s_wsum[warp] = v;
    __syncthreads();
    if (warp == 0) {
        unsigned wv = (lane < 8) ? s_wsum[lane] : 0u;
#pragma unroll
        for (int off = 1; off < 8; off <<= 1) {
            const unsigned u = __shfl_down_sync(0xFFFFFFFFu, wv, off);
            if (lane + off < 32) wv += u;
        }
        if (lane < 8) s_wexc[lane] = wv - s_wsum[lane];
    }
    __syncthreads();
    {
        const unsigned Sb = s_wexc[warp] + v;
        if ((int)Sb >= rank_in && (int)(Sb - h) < rank_in) {
            *s_b = tid; *s_rank = rank_in - (int)(Sb - h); *s_cnt = (int)h;
        }
    }
    __syncthreads();
}

// fp16 u16 key -> float (nonneg fp16 bit pattern is order-preserving)
__device__ __forceinline__ float key2f(unsigned k) {
    return __half2float(__ushort_as_half((unsigned short)k));
}

// ---------------------------------------------------------------------------
// Kernel 4a: per-row candidate generation + output-row zeroing.
// cut = cutLB * 0.9965 - 2e-4 (certified superset; delta <= 0.152% + abs 3e-5)
// ---------------------------------------------------------------------------
#define CK_THREADS 256
#define CK_SMEM (NNODES * 2 + 256 * 4 + 64)

__global__ void __launch_bounds__(CK_THREADS, 4) cand_kernel(
    const __half*   __restrict__ Ahf,
    float*          __restrict__ out,
    unsigned short* __restrict__ cand,
    int*            __restrict__ ccnt,
    int N)
{
    extern __shared__ __align__(16) unsigned char sm[];
    unsigned short* s_apx  = reinterpret_cast<unsigned short*>(sm);          // [N]
    unsigned*       s_hist = reinterpret_cast<unsigned*>(sm + NNODES * 2);   // [256]
    unsigned*       s_wsum = s_hist + 256;                                   // [8]
    unsigned*       s_wexc = s_wsum + 8;                                     // [8]
    __shared__ int   s_b, s_rank, s_cnt, s_ccnt;
    __shared__ float sh_fmax;

    const int tid  = threadIdx.x;
    const int lane = tid & 31;
    const int warp = tid >> 5;
    const int row  = blockIdx.x;
    const size_t abase = (size_t)row * N;
    const unsigned lane_lt = (1u << lane) - 1u;

    // zero the output row
    {
        float4* o4 = reinterpret_cast<float4*>(out + abase);
        const float4 z = make_float4(0.f, 0.f, 0.f, 0.f);
        for (int j = tid; j < N / 4; j += CK_THREADS) o4[j] = z;
    }

    // load approx row + fused max reduce (u16 fp16 keys, order-preserving)
    unsigned um = 0u;
    {
        const uint4* g4 = reinterpret_cast<const uint4*>(Ahf + abase);
        uint4*       s4 = reinterpret_cast<uint4*>(s_apx);
        const int n8 = N / 8;
        for (int j = tid; j < n8; j += CK_THREADS) {
            const uint4 k = g4[j];
            s4[j] = k;
            unsigned w;
            w = k.x; um = max(um, w & 0xFFFFu); um = max(um, w >> 16);
            w = k.y; um = max(um, w & 0xFFFFu); um = max(um, w >> 16);
            w = k.z; um = max(um, w & 0xFFFFu); um = max(um, w >> 16);
            w = k.w; um = max(um, w & 0xFFFFu); um = max(um, w >> 16);
        }
    }
#pragma unroll
    for (int off = 16; off > 0; off >>= 1)
        um = max(um, __shfl_xor_sync(0xFFFFFFFFu, um, off));
    if (lane == 0) s_wsum[warp] = um;
    __syncthreads();
    if (tid == 0) {
        unsigned m = 0u;
        for (int i = 0; i < CK_THREADS / 32; i++) m = max(m, s_wsum[i]);
        sh_fmax = key2f(m);
    }
    __syncthreads();
    const float vmax = sh_fmax;

    if (vmax <= 0.0f) {
        if (tid == 0) ccnt[row] = 0;
        return;
    }

    // ladder: certified lower bound of a32 (32nd-largest approx)
    float cutLB = -1.0f;
    {
        const float fr[4] = {0.96f, 0.85f, 0.5f, 0.0f};
        for (int at = 0; at < 4; at++) {
            const float lo  = fr[at] * vmax;
            const float rng = vmax - lo;
            const float inv = 256.0f / rng;
            const float w   = rng * (1.0f / 256.0f);
            s_hist[tid] = 0u;
            if (tid == 0) s_b = -1;
            __syncthreads();
            for (int j = tid; j < N; j += CK_THREADS) {
                const float v = key2f(s_apx[j]);
                if (v >= lo) {
                    int bq = (int)((vmax - v) * inv);
                    bq = 255 - min(bq, 255);
                    atomicAdd(&s_hist[bq], 1u);
                }
            }
            __syncthreads();
            select256_fn(s_hist, s_wsum, s_wexc, &s_b, &s_rank, &s_cnt, TOPK, tid);
            const int found = s_b;
            __syncthreads();
            if (found >= 0) {
                const int u = 255 - found;
                cutLB = vmax - (float)(u + 2) * w;   // one-bucket fp safety
                break;
            }
        }
    }
    if (cutLB <= 0.0f) {
        if (tid == 0) ccnt[row] = SENTINEL;
        return;
    }

    // gather candidates: A >= cutLB*0.9965 - 2e-4 (certified superset)
    const float cut = cutLB * 0.9965f - 2e-4f;
    if (tid == 0) s_ccnt = 0;
    __syncthreads();
    unsigned short* crow = cand + (size_t)row * SK_CMAX;
    for (int j0 = 0; j0 < N; j0 += CK_THREADS) {
        const int j = j0 + tid;
        bool pred = false;
        if (j < N)
            pred = (key2f(s_apx[j]) >= cut);
        const unsigned m = __ballot_sync(0xFFFFFFFFu, pred);
        int cb = 0;
        if (lane == 0 && m) cb = atomicAdd(&s_ccnt, __popc(m));
        cb = __shfl_sync(0xFFFFFFFFu, cb, 0);
        if (pred) {
            const int pos = cb + __popc(m & lane_lt);
            if (pos < SK_CMAX) crow[pos] = (unsigned short)j;
        }
    }
    __syncthreads();
    if (tid == 0)
        ccnt[row] = (s_ccnt <= SK_CMAX) ? s_ccnt : SENTINEL;
}

// ---------------------------------------------------------------------------
// Kernel 4b: per-row exact dots (frozen ascending-k fmaf bit chain) + exact
// radix select + jax tie rule + scatter writes.
// ---------------------------------------------------------------------------
#define SK_THREADS 256
#define SK_OFF_VAL  2048
#define SK_OFF_CAND 18432
#define SK_OFF_HIST 26688
#define SK_OFF_WS   27712
#define SK_SMEM     27776

__global__ void __launch_bounds__(SK_THREADS, 4) select_kernel(
    const unsigned short* __restrict__ cand,
    const int*            __restrict__ ccnt,
    const float*          __restrict__ H,
    float*                __restrict__ out,
    int N, int Kd)
{
    const int row = blockIdx.x;
    const int cnt = ccnt[row];
    if (cnt == 0 || cnt > SK_CMAX) return;

    extern __shared__ __align__(16) unsigned char sm[];
    float*          s_hrow = reinterpret_cast<float*>(sm);                   // [512]
    float*          s_val  = reinterpret_cast<float*>(sm + SK_OFF_VAL);      // [CMAX]
    unsigned short* s_cand = reinterpret_cast<unsigned short*>(sm + SK_OFF_CAND);
    unsigned*       s_hist = reinterpret_cast<unsigned*>(sm + SK_OFF_HIST);  // [256]
    unsigned*       s_wsum = reinterpret_cast<unsigned*>(sm + SK_OFF_WS);    // [8]
    unsigned*       s_wexc = s_wsum + 8;                                     // [8]
    __shared__ int s_b, s_rank, s_cnt;

    const int tid = threadIdx.x;
    const size_t abase = (size_t)row * N;

    if (tid < Kd / 4)
        reinterpret_cast<float4*>(s_hrow)[tid] =
            reinterpret_cast<const float4*>(H + (size_t)row * Kd)[tid];
    {
        const unsigned short* crow = cand + (size_t)row * SK_CMAX;
        for (int c = tid; c < cnt; c += SK_THREADS) s_cand[c] = crow[c];
    }
    __syncthreads();

    // exact dots (ascending-k single-accumulator fmaf == frozen bit chain)
    for (int c = tid; c < cnt; c += SK_THREADS) {
        const int j = s_cand[c];
        const float4* b4 = reinterpret_cast<const float4*>(H + (size_t)j * Kd);
        float acc = 0.0f;
#pragma unroll 8
        for (int k4 = 0; k4 < NHEDGES / 4; k4++) {
            const float4 bv = __ldg(&b4[k4]);
            const float4 av = *reinterpret_cast<const float4*>(&s_hrow[k4 * 4]);
            acc = fmaf(av.x, bv.x, acc);
            acc = fmaf(av.y, bv.y, acc);
            acc = fmaf(av.z, bv.z, acc);
            acc = fmaf(av.w, bv.w, acc);
        }
        s_val[c] = acc;
    }
    __syncthreads();

    // exact threshold: 4x8-bit radix among candidates (== 32nd overall)
    unsigned prefix = 0u;
    int rank = TOPK, cntEq = 0;
    for (int shift = 24; shift >= 0; shift -= 8) {
        s_hist[tid] = 0u;
        __syncthreads();
        const unsigned hm = (shift == 24) ? 0u : (0xFFFFFFFFu << (shift + 8));
        for (int c = tid; c < cnt; c += SK_THREADS) {
            const unsigned k = __float_as_uint(s_val[c]);
            if ((k & hm) == prefix)
                atomicAdd(&s_hist[(k >> shift) & 0xFFu], 1u);
        }
        __syncthreads();
        select256_fn(s_hist, s_wsum, s_wexc, &s_b, &s_rank, &s_cnt, rank, tid);
        prefix |= ((unsigned)s_b << shift);
        rank  = s_rank;
        cntEq = s_cnt;
        __syncthreads();
    }
    const float Tval = __uint_as_float(prefix);

    if (cntEq > rank) {
        // jax tie rule: keep `rank` tied entries with smallest column j.
        if (tid == 0) {
            for (int c = 0; c < cnt; c++)
                if (__float_as_uint(s_val[c]) == prefix) s_val[c] = -2.0f;
            for (int it = 0; it < rank; it++) {
                int bestc = -1, bestj = 0x7FFFFFFF;
                for (int c = 0; c < cnt; c++)
                    if (s_val[c] == -2.0f && (int)s_cand[c] < bestj) {
                        bestj = s_cand[c]; bestc = c;
                    }
                s_val[bestc] = Tval;
            }
            for (int c = 0; c < cnt; c++)
                if (s_val[c] == -2.0f) s_val[c] = -1.0f;
        }
        __syncthreads();
    }

    for (int c = tid; c < cnt; c += SK_THREADS) {
        const float v = s_val[c];
        if (v >= Tval) out[abase + s_cand[c]] = v;
    }
}

// ---------------------------------------------------------------------------
// Kernel 4c: full-exact fallback for sentinel rows (early-exit otherwise).
// ---------------------------------------------------------------------------
#define FB_SMEM (NNODES * 4 + NHEDGES * 4 + 256 * 4 + 64)

__global__ void __launch_bounds__(256, 2) fallback_kernel(
    const int*   __restrict__ ccnt,
    const float* __restrict__ H,
    float*       __restrict__ out,
    int N, int Kd)
{
    const int row = blockIdx.x;
    if (ccnt[row] != SENTINEL) return;

    extern __shared__ __align__(16) unsigned char sm[];
    float*    s_row  = reinterpret_cast<float*>(sm);                        // [N]
    float*    s_hrow = reinterpret_cast<float*>(sm + NNODES * 4);           // [512]
    unsigned* s_hist = reinterpret_cast<unsigned*>(sm + NNODES * 4 + NHEDGES * 4);
    unsigned* s_wsum = s_hist + 256;
    unsigned* s_wexc = s_wsum + 8;
    __shared__ int s_b, s_rank, s_cnt;

    const int tid = threadIdx.x;
    const size_t abase = (size_t)row * N;

    if (tid < Kd / 4)
        reinterpret_cast<float4*>(s_hrow)[tid] =
            reinterpret_cast<const float4*>(H + (size_t)row * Kd)[tid];
    __syncthreads();

    for (int j = tid; j < N; j += 256) {
        const float4* b4 = reinterpret_cast<const float4*>(H + (size_t)j * Kd);
        float acc = 0.0f;
#pragma unroll 4
        for (int k4 = 0; k4 < NHEDGES / 4; k4++) {
            const float4 bv = __ldg(&b4[k4]);
            const float4 av = *reinterpret_cast<const float4*>(&s_hrow[k4 * 4]);
            acc = fmaf(av.x, bv.x, acc);
            acc = fmaf(av.y, bv.y, acc);
            acc = fmaf(av.z, bv.z, acc);
            acc = fmaf(av.w, bv.w, acc);
        }
        s_row[j] = acc;
    }
    __syncthreads();

    unsigned prefix = 0u;
    int rank = TOPK, cntEq = 0;
    for (int shift = 24; shift >= 0; shift -= 8) {
        s_hist[tid] = 0u;
        __syncthreads();
        const unsigned hm = (shift == 24) ? 0u : (0xFFFFFFFFu << (shift + 8));
        for (int j = tid; j < N; j += 256) {
            const unsigned k = __float_as_uint(s_row[j]);
            if ((k & hm) == prefix)
                atomicAdd(&s_hist[(k >> shift) & 0xFFu], 1u);
        }
        __syncthreads();
        select256_fn(s_hist, s_wsum, s_wexc, &s_b, &s_rank, &s_cnt, rank, tid);
        prefix |= ((unsigned)s_b << shift);
        rank  = s_rank;
        cntEq = s_cnt;
        __syncthreads();
    }
    const float Tval = __uint_as_float(prefix);

    if (cntEq > rank) {
        if (tid == 0) {
            int kept = 0;
            for (int j = 0; j < N; j++) {
                if (__float_as_uint(s_row[j]) == prefix) {
                    kept++;
                    if (kept > rank) s_row[j] = -1.0f;
                }
            }
        }
        __syncthreads();
    }

    for (int j = tid; j < N; j += 256) {
        const float v = s_row[j];
        out[abase + j] = (v >= Tval) ? v : 0.0f;
    }
}

// ---------------------------------------------------------------------------
// kernel_launch
// ---------------------------------------------------------------------------
extern "C" void kernel_launch(void* const* d_in, const int* in_sizes, int n_in,
                              void* d_out, int out_size)
{
    (void)in_sizes; (void)n_in; (void)out_size;

    const int*   idx   = (const int*)  d_in[0];
    const float* embn  = (const float*)d_in[1];
    const float* embhe = (const float*)d_in[2];
    const float* W1    = (const float*)d_in[3];
    const float* b1    = (const float*)d_in[4];
    const float* W2    = (const float*)d_in[5];
    const float* b2    = (const float*)d_in[6];
    float*       out   = (float*)d_out;

    float *p_nv1 = nullptr, *p_nv2 = nullptr, *p_H = nullptr;
    __half *p_Hhf = nullptr, *p_Ahf = nullptr;
    unsigned short *p_cand = nullptr;
    int *p_ccnt = nullptr;
    cudaGetSymbolAddress((void**)&p_nv1,  g_nv1);
    cudaGetSymbolAddress((void**)&p_nv2,  g_nv2);
    cudaGetSymbolAddress((void**)&p_H,    g_H);
    cudaGetSymbolAddress((void**)&p_Hhf,  g_Hhf);
    cudaGetSymbolAddress((void**)&p_Ahf,  g_Ahf);
    cudaGetSymbolAddress((void**)&p_cand, g_cand);
    cudaGetSymbolAddress((void**)&p_ccnt, g_ccnt);

    cudaFuncSetAttribute(nodevec_kernel,
                         cudaFuncAttributeMaxDynamicSharedMemorySize, NV_SMEM);
    cudaFuncSetAttribute(approx_mma_kernel,
                         cudaFuncAttributeMaxDynamicSharedMemorySize, ASMEM);
    cudaFuncSetAttribute(cand_kernel,
                         cudaFuncAttributeMaxDynamicSharedMemorySize, CK_SMEM);
    cudaFuncSetAttribute(select_kernel,
                         cudaFuncAttributeMaxDynamicSharedMemorySize, SK_SMEM);
    cudaFuncSetAttribute(fallback_kernel,
                         cudaFuncAttributeMaxDynamicSharedMemorySize, FB_SMEM);

    // 1) nodevecs
    nodevec_kernel<<<NNODES / NV_ROWS, EDIM, NV_SMEM>>>(embn, idx, W1, b1,
                                                        p_nv1, NNODES);
    nodevec_kernel<<<NHEDGES / NV_ROWS, EDIM, NV_SMEM>>>(embhe, nullptr, W2, b2,
                                                         p_nv2, NHEDGES);

    // 2) H (fp32, frozen bit-path) + fp16 copy
    {
        dim3 grid((NHEDGES + GT_TM - 1) / GT_TM, (NNODES + GT_TM - 1) / GT_TM);
        h_gemm_kernel<<<grid, 256>>>(p_nv1, p_nv2, p_H, p_Hhf,
                                     NNODES, NHEDGES, EDIM);
    }

    // 3) approx adj = fp16(Hhf @ Hhf^T)
    {
        const int nt = (NNODES + GT_TM - 1) / GT_TM;
        dim3 grid(nt, nt);
        approx_mma_kernel<<<grid, 256, ASMEM>>>(p_Hhf, p_Ahf, NNODES, NHEDGES);
    }

    // 4) certified top-32 pipeline: candidates -> exact select -> fallback
    cand_kernel<<<NNODES, CK_THREADS, CK_SMEM>>>(p_Ahf, out, p_cand, p_ccnt,
                                                 NNODES);
    select_kernel<<<NNODES, SK_THREADS, SK_SMEM>>>(p_cand, p_ccnt, p_H, out,
                                                   NNODES, NHEDGES);
    fallback_kernel<<<NNODES, 256, FB_SMEM>>>(p_ccnt, p_H, out,
                                              NNODES, NHEDGES);
}

// round 13
// speedup vs baseline: 2.5585x; 1.0434x over previous
#include <cuda_runtime.h>
#include <cuda_fp16.h>
#include <math.h>

// ---------------------------------------------------------------------------
// Problem constants
// ---------------------------------------------------------------------------
#define NNODES  10000
#define NHEDGES 512
#define EDIM    128
#define TOPK    32
#define ALPHA   3.0f
#define SENTINEL 0x7FFFFFFF

// ---------------------------------------------------------------------------
// Scratch (device globals -- no runtime allocation allowed)
// ---------------------------------------------------------------------------
#define SK_CMAX 4096
__device__ float          g_nv1[NNODES * EDIM];
__device__ float          g_nv2[NHEDGES * EDIM];
__device__ float          g_H  [NNODES * NHEDGES];          // exact H (fp32)
__device__ __half         g_Hhf[NNODES * NHEDGES];          // fp16(H)
__device__ __half         g_Ahf[(size_t)NNODES * NNODES];   // approx adj (fp16)
__device__ unsigned short g_cand[(size_t)NNODES * SK_CMAX]; // per-row candidates
__device__ int            g_ccnt[NNODES];                   // per-row counts

// ---------------------------------------------------------------------------
// Kernel 1: nodevec (unchanged)
// ---------------------------------------------------------------------------
#define NV_ROWS 8
#define NV_SMEM ((EDIM * EDIM + NV_ROWS * EDIM) * 4)

__global__ void __launch_bounds__(EDIM) nodevec_kernel(
    const float* __restrict__ emb,
    const int*   __restrict__ idx,
    const float* __restrict__ W,
    const float* __restrict__ b,
    float*       __restrict__ out,
    int nrows)
{
    extern __shared__ __align__(16) float nv_smem[];
    float* sW   = nv_smem;
    float* s_in = nv_smem + EDIM * EDIM;

    const int tid = threadIdx.x;
    const int r0  = blockIdx.x * NV_ROWS;

    const float4* Wv  = reinterpret_cast<const float4*>(W);
    float4*       sWv = reinterpret_cast<float4*>(sW);
#pragma unroll
    for (int i = 0; i < (EDIM * EDIM / 4) / EDIM; i++)
        sWv[i * EDIM + tid] = Wv[i * EDIM + tid];

#pragma unroll
    for (int q = 0; q < NV_ROWS; q++) {
        const int r  = r0 + q;
        const int sr = (r < nrows) ? (idx ? idx[r] : r) : 0;
        s_in[q * EDIM + tid] = emb[(size_t)sr * EDIM + tid];
    }
    __syncthreads();

    float acc[NV_ROWS];
    const float bd = b[tid];
#pragma unroll
    for (int q = 0; q < NV_ROWS; q++) acc[q] = bd;

#pragma unroll 4
    for (int k = 0; k < EDIM; k++) {
        const float w = sW[k * EDIM + tid];
#pragma unroll
        for (int q = 0; q < NV_ROWS; q++)
            acc[q] = fmaf(s_in[q * EDIM + k], w, acc[q]);
    }

#pragma unroll
    for (int q = 0; q < NV_ROWS; q++) {
        const int r = r0 + q;
        if (r < nrows)
            out[(size_t)r * EDIM + tid] = tanhf(ALPHA * acc[q]);
    }
}

// ---------------------------------------------------------------------------
// Kernel 2: H (fp32, frozen bit-path) + fp16 copy (unchanged)
// ---------------------------------------------------------------------------
#define GT_TM 128
#define GT_BK 16

__global__ void __launch_bounds__(256, 2) h_gemm_kernel(
    const float* __restrict__ A,
    const float* __restrict__ B,
    float*  __restrict__ C,
    __half* __restrict__ Chf,
    int M, int N, int Kd)
{
    __shared__ __align__(16) float As[2][GT_BK][GT_TM];
    __shared__ __align__(16) float Bs[2][GT_BK][GT_TM];

    const int tid = threadIdx.x;
    const int bm  = blockIdx.y * GT_TM;
    const int bn  = blockIdx.x * GT_TM;
    const int tx  = tid & 15;
    const int ty  = tid >> 4;

    float acc[8][8];
#pragma unroll
    for (int i = 0; i < 8; i++)
#pragma unroll
        for (int j = 0; j < 8; j++) acc[i][j] = 0.0f;

    auto stage = [&](int buf, int k0) {
#pragma unroll
        for (int s = 0; s < 2; s++) {
            const int f  = tid + s * 256;
            const int r  = f >> 2;
            const int kq = (f & 3) << 2;
            const int ga = bm + r;
            float4 va = make_float4(0.f, 0.f, 0.f, 0.f);
            if (ga < M)
                va = *reinterpret_cast<const float4*>(A + (size_t)ga * Kd + k0 + kq);
            As[buf][kq + 0][r] = va.x; As[buf][kq + 1][r] = va.y;
            As[buf][kq + 2][r] = va.z; As[buf][kq + 3][r] = va.w;

            const int gb = bn + r;
            float4 vb = make_float4(0.f, 0.f, 0.f, 0.f);
            if (gb < N)
                vb = *reinterpret_cast<const float4*>(B + (size_t)gb * Kd + k0 + kq);
            Bs[buf][kq + 0][r] = vb.x; Bs[buf][kq + 1][r] = vb.y;
            Bs[buf][kq + 2][r] = vb.z; Bs[buf][kq + 3][r] = vb.w;
        }
    };

    stage(0, 0);
    __syncthreads();

    const int nk = Kd / GT_BK;
    for (int kt = 0; kt < nk; kt++) {
        const int cur = kt & 1;
        if (kt + 1 < nk) stage(cur ^ 1, (kt + 1) * GT_BK);

#pragma unroll
        for (int kk = 0; kk < GT_BK; kk++) {
            float a[8], b[8];
#pragma unroll
            for (int i = 0; i < 8; i += 4)
                *reinterpret_cast<float4*>(&a[i]) =
                    *reinterpret_cast<const float4*>(&As[cur][kk][ty * 8 + i]);
#pragma unroll
            for (int j = 0; j < 8; j += 4)
                *reinterpret_cast<float4*>(&b[j]) =
                    *reinterpret_cast<const float4*>(&Bs[cur][kk][tx * 8 + j]);
#pragma unroll
            for (int i = 0; i < 8; i++)
#pragma unroll
                for (int j = 0; j < 8; j++)
                    acc[i][j] = fmaf(a[i], b[j], acc[i][j]);
        }
        __syncthreads();
    }

#pragma unroll
    for (int i = 0; i < 8; i++) {
        const int gr = bm + ty * 8 + i;
        if (gr >= M) continue;
        float*  crow = C   + (size_t)gr * N;
        __half* hrow = Chf + (size_t)gr * N;
#pragma unroll
        for (int j = 0; j < 8; j += 4) {
            const int gc = bn + tx * 8 + j;
            float4 v;
            v.x = fmaxf(tanhf(ALPHA * acc[i][j + 0]), 0.0f);
            v.y = fmaxf(tanhf(ALPHA * acc[i][j + 1]), 0.0f);
            v.z = fmaxf(tanhf(ALPHA * acc[i][j + 2]), 0.0f);
            v.w = fmaxf(tanhf(ALPHA * acc[i][j + 3]), 0.0f);
            if (gc + 3 < N) {
                *reinterpret_cast<float4*>(crow + gc) = v;
                hrow[gc + 0] = __float2half(v.x);
                hrow[gc + 1] = __float2half(v.y);
                hrow[gc + 2] = __float2half(v.z);
                hrow[gc + 3] = __float2half(v.w);
            } else {
                const float vv[4] = {v.x, v.y, v.z, v.w};
                for (int q = 0; q < 4; q++)
                    if (gc + q < N) {
                        crow[gc + q] = vv[q];
                        hrow[gc + q] = __float2half(vv[q]);
                    }
            }
        }
    }
}

// ---------------------------------------------------------------------------
// Kernel 3: approx adj = fp16( Hhf @ Hhf^T ), fp16 MMA + fp32 accum.
// K-chunk 64: 8 mainloop barriers (was 16); 72-padded rows (144B stride ->
// 8 ldmatrix rows span all 32 banks, conflict-free).
// ---------------------------------------------------------------------------
#define ABKC  64
#define APADK 72
#define AARR  (128 * APADK)        // 9216 halves per array
#define ABUF  (2 * AARR)           // A + B
#define ASMEM (2 * ABUF * 2)       // 73728 B >= epilogue CT 68096

#define LDSM_X4(r, addr) \
    asm volatile("ldmatrix.sync.aligned.m8n8.x4.shared.b16 {%0,%1,%2,%3}, [%4];" \
        : "=r"((r)[0]), "=r"((r)[1]), "=r"((r)[2]), "=r"((r)[3]) : "r"(addr))
#define LDSM_X2(r, addr) \
    asm volatile("ldmatrix.sync.aligned.m8n8.x2.shared.b16 {%0,%1}, [%2];" \
        : "=r"((r)[0]), "=r"((r)[1]) : "r"(addr))
#define MMA_F16(d, a, b) \
    asm volatile("mma.sync.aligned.m16n8k16.row.col.f32.f16.f16.f32 " \
        "{%0,%1,%2,%3},{%4,%5,%6,%7},{%8,%9},{%0,%1,%2,%3};" \
        : "+f"((d)[0]), "+f"((d)[1]), "+f"((d)[2]), "+f"((d)[3]) \
        : "r"((a)[0]), "r"((a)[1]), "r"((a)[2]), "r"((a)[3]), "r"((b)[0]), "r"((b)[1]))

__global__ void __launch_bounds__(256, 2) approx_mma_kernel(
    const __half* __restrict__ Hhf,
    __half* __restrict__ C,
    int M, int Kd)
{
    extern __shared__ __align__(16) unsigned char dynsmem[];
    __half* s = reinterpret_cast<__half*>(dynsmem);

    const int by = blockIdx.y, bx = blockIdx.x;
    if (bx < by) return;
    const int bm  = by * GT_TM, bn = bx * GT_TM;
    const int tid = threadIdx.x;
    const int lane = tid & 31, warp = tid >> 5;
    const int wm = warp >> 2;
    const int wn = warp & 3;

    const unsigned sbase = (unsigned)__cvta_generic_to_shared(s);

    auto stage = [&](int buf, int k0) {
#pragma unroll
        for (int a = 0; a < 2; a++) {
            const int rowbase = (a == 0) ? bm : bn;
#pragma unroll
            for (int sIt = 0; sIt < 4; sIt++) {
                const int idx  = tid + sIt * 256;      // 0..1023
                const int row  = idx >> 3;             // 0..127
                const int unit = idx & 7;              // 8 x 16B = 128B row
                const int grow = rowbase + row;
                const int cpsz = (grow < M) ? 16 : 0;
                const void* src = Hhf + (size_t)(grow < M ? grow : 0) * Kd
                                      + k0 + unit * 8;
                const unsigned dst = sbase +
                    (unsigned)((buf * ABUF + a * AARR + row * APADK + unit * 8) * 2);
                asm volatile("cp.async.cg.shared.global [%0], [%1], 16, %2;\n"
                             :: "r"(dst), "l"(src), "r"(cpsz));
            }
        }
        asm volatile("cp.async.commit_group;\n" ::: "memory");
    };

    float acc[4][4][4];
#pragma unroll
    for (int i = 0; i < 4; i++)
#pragma unroll
        for (int j = 0; j < 4; j++)
#pragma unroll
            for (int q = 0; q < 4; q++) acc[i][j][q] = 0.0f;

    const int nk = Kd / ABKC;   // 8
    stage(0, 0);

    for (int kt = 0; kt < nk; kt++) {
        const int cur = kt & 1;
        if (kt + 1 < nk) {
            stage(cur ^ 1, (kt + 1) * ABKC);
            asm volatile("cp.async.wait_group 1;\n" ::: "memory");
        } else {
            asm volatile("cp.async.wait_group 0;\n" ::: "memory");
        }
        __syncthreads();

        const unsigned bA = sbase + (unsigned)((cur * ABUF + 0 * AARR) * 2);
        const unsigned bB = sbase + (unsigned)((cur * ABUF + 1 * AARR) * 2);

#pragma unroll
        for (int kk = 0; kk < 4; kk++) {               // 4 x 16 = 64
            unsigned ra[4][4], rb[4][2];
            const int arow = wm * 64 + (lane & 15);
            const int acol = kk * 16 + (lane >> 4) * 8;
#pragma unroll
            for (int mf = 0; mf < 4; mf++)
                LDSM_X4(ra[mf], bA + (unsigned)(((arow + mf * 16) * APADK + acol) * 2));
            const int brow = wn * 32 + (lane & 7);
            const int bcol = kk * 16 + ((lane >> 3) & 1) * 8;
#pragma unroll
            for (int nf = 0; nf < 4; nf++)
                LDSM_X2(rb[nf], bB + (unsigned)(((brow + nf * 8) * APADK + bcol) * 2));
#pragma unroll
            for (int mf = 0; mf < 4; mf++)
#pragma unroll
                for (int nf = 0; nf < 4; nf++)
                    MMA_F16(acc[mf][nf], ra[mf], rb[nf]);
        }
        __syncthreads();
    }

    float* Ct = reinterpret_cast<float*>(dynsmem);
#define CT(r, c) Ct[(r) * 133 + (c)]

#pragma unroll
    for (int mf = 0; mf < 4; mf++) {
#pragma unroll
        for (int nf = 0; nf < 4; nf++) {
            const int r0 = wm * 64 + mf * 16 + (lane >> 2);
            const int c0 = wn * 32 + nf * 8 + (lane & 3) * 2;
            const __half h0 = __float2half(acc[mf][nf][0]);
            const __half h1 = __float2half(acc[mf][nf][1]);
            const __half h2 = __float2half(acc[mf][nf][2]);
            const __half h3 = __float2half(acc[mf][nf][3]);
            CT(r0, c0)     = __half2float(h0);
            CT(r0, c0 + 1) = __half2float(h1);
            CT(r0 + 8, c0)     = __half2float(h2);
            CT(r0 + 8, c0 + 1) = __half2float(h3);

            const int gc = bn + c0;               // even; M even -> gc+1 < M
            const int gr0 = bm + r0, gr1 = bm + r0 + 8;
            if (gr0 < M && gc < M) {
                __half2 p; p.x = h0; p.y = h1;
                *reinterpret_cast<__half2*>(C + (size_t)gr0 * M + gc) = p;
            }
            if (gr1 < M && gc < M) {
                __half2 p; p.x = h2; p.y = h3;
                *reinterpret_cast<__half2*>(C + (size_t)gr1 * M + gc) = p;
            }
        }
    }
    __syncthreads();

    for (int i = tid; i < 128 * 128; i += 256) {
        const int r2 = i >> 7;
        const int c2 = i & 127;
        const int gR = bn + r2, gC = bm + c2;
        if (gR < M && gC < M)
            C[(size_t)gR * M + gC] = __float2half(CT(c2, r2));
    }
#undef CT
}

// ---------------------------------------------------------------------------
// Shared helper: 256-bin Kth select (suffix over bin index). 256 threads.
// ---------------------------------------------------------------------------
__device__ __forceinline__ void select256_fn(
    const unsigned* s_hist, unsigned* s_wsum, unsigned* s_wexc,
    int* s_b, int* s_rank, int* s_cnt, int rank_in, int tid)
{
    const int lane = tid & 31, warp = tid >> 5;
    const unsigned h = s_hist[tid];
    unsigned v = h;
#pragma unroll
    for (int off = 1; off < 32; off <<= 1) {
        const unsigned u = __shfl_down_sync(0xFFFFFFFFu, v, off);
        if (lane + off < 32) v += u;
    }
    if (lane == 0) s_wsum[warp] = v;
    __syncthreads();
    if (warp == 0) {
        unsigned wv = (lane < 8) ? s_wsum[lane] : 0u;
#pragma unroll
        for (int off = 1; off < 8; off <<= 1) {
            const unsigned u = __shfl_down_sync(0xFFFFFFFFu, wv, off);
            if (lane + off < 32) wv += u;
        }
        if (lane < 8) s_wexc[lane] = wv - s_wsum[lane];
    }
    __syncthreads();
    {
        const unsigned Sb = s_wexc[warp] + v;
        if ((int)Sb >= rank_in && (int)(Sb - h) < rank_in) {
            *s_b = tid; *s_rank = rank_in - (int)(Sb - h); *s_cnt = (int)h;
        }
    }
    __syncthreads();
}

// fp16 u16 key -> float (nonneg fp16 bit pattern is order-preserving)
__device__ __forceinline__ float key2f(unsigned k) {
    return __half2float(__ushort_as_half((unsigned short)k));
}

// ---------------------------------------------------------------------------
// Kernel 4a: per-row candidate generation + output-row zeroing.
// cut = cutLB * 0.9965 - 2e-4 (certified superset; delta <= 0.152% + abs 3e-5)
// ---------------------------------------------------------------------------
#define CK_THREADS 256
#define CK_SMEM (NNODES * 2 + 256 * 4 + 64)

__global__ void __launch_bounds__(CK_THREADS, 6) cand_kernel(
    const __half*   __restrict__ Ahf,
    float*          __restrict__ out,
    unsigned short* __restrict__ cand,
    int*            __restrict__ ccnt,
    int N)
{
    extern __shared__ __align__(16) unsigned char sm[];
    unsigned short* s_apx  = reinterpret_cast<unsigned short*>(sm);          // [N]
    unsigned*       s_hist = reinterpret_cast<unsigned*>(sm + NNODES * 2);   // [256]
    unsigned*       s_wsum = s_hist + 256;                                   // [8]
    unsigned*       s_wexc = s_wsum + 8;                                     // [8]
    __shared__ int   s_b, s_rank, s_cnt, s_ccnt;
    __shared__ float sh_fmax;

    const int tid  = threadIdx.x;
    const int lane = tid & 31;
    const int warp = tid >> 5;
    const int row  = blockIdx.x;
    const size_t abase = (size_t)row * N;
    const unsigned lane_lt = (1u << lane) - 1u;

    // zero the output row
    {
        float4* o4 = reinterpret_cast<float4*>(out + abase);
        const float4 z = make_float4(0.f, 0.f, 0.f, 0.f);
        for (int j = tid; j < N / 4; j += CK_THREADS) o4[j] = z;
    }

    // load approx row + fused max reduce
    unsigned um = 0u;
    {
        const uint4* g4 = reinterpret_cast<const uint4*>(Ahf + abase);
        uint4*       s4 = reinterpret_cast<uint4*>(s_apx);
        const int n8 = N / 8;
        for (int j = tid; j < n8; j += CK_THREADS) {
            const uint4 k = g4[j];
            s4[j] = k;
            unsigned w;
            w = k.x; um = max(um, w & 0xFFFFu); um = max(um, w >> 16);
            w = k.y; um = max(um, w & 0xFFFFu); um = max(um, w >> 16);
            w = k.z; um = max(um, w & 0xFFFFu); um = max(um, w >> 16);
            w = k.w; um = max(um, w & 0xFFFFu); um = max(um, w >> 16);
        }
    }
#pragma unroll
    for (int off = 16; off > 0; off >>= 1)
        um = max(um, __shfl_xor_sync(0xFFFFFFFFu, um, off));
    if (lane == 0) s_wsum[warp] = um;
    __syncthreads();
    if (tid == 0) {
        unsigned m = 0u;
        for (int i = 0; i < CK_THREADS / 32; i++) m = max(m, s_wsum[i]);
        sh_fmax = key2f(m);
    }
    __syncthreads();
    const float vmax = sh_fmax;

    if (vmax <= 0.0f) {
        if (tid == 0) ccnt[row] = 0;
        return;
    }

    // ladder: certified lower bound of a32 (32nd-largest approx)
    float cutLB = -1.0f;
    {
        const float fr[4] = {0.96f, 0.85f, 0.5f, 0.0f};
        for (int at = 0; at < 4; at++) {
            const float lo  = fr[at] * vmax;
            const float rng = vmax - lo;
            const float inv = 256.0f / rng;
            const float w   = rng * (1.0f / 256.0f);
            s_hist[tid] = 0u;
            if (tid == 0) s_b = -1;
            __syncthreads();
            for (int j = tid; j < N; j += CK_THREADS) {
                const float v = key2f(s_apx[j]);
                if (v >= lo) {
                    int bq = (int)((vmax - v) * inv);
                    bq = 255 - min(bq, 255);
                    atomicAdd(&s_hist[bq], 1u);
                }
            }
            __syncthreads();
            select256_fn(s_hist, s_wsum, s_wexc, &s_b, &s_rank, &s_cnt, TOPK, tid);
            const int found = s_b;
            __syncthreads();
            if (found >= 0) {
                const int u = 255 - found;
                cutLB = vmax - (float)(u + 2) * w;   // one-bucket fp safety
                break;
            }
        }
    }
    if (cutLB <= 0.0f) {
        if (tid == 0) ccnt[row] = SENTINEL;
        return;
    }

    // gather candidates: A >= cutLB*0.9965 - 2e-4 (certified superset)
    const float cut = cutLB * 0.9965f - 2e-4f;
    if (tid == 0) s_ccnt = 0;
    __syncthreads();
    unsigned short* crow = cand + (size_t)row * SK_CMAX;
    for (int j0 = 0; j0 < N; j0 += CK_THREADS) {
        const int j = j0 + tid;
        bool pred = false;
        if (j < N)
            pred = (key2f(s_apx[j]) >= cut);
        const unsigned m = __ballot_sync(0xFFFFFFFFu, pred);
        int cb = 0;
        if (lane == 0 && m) cb = atomicAdd(&s_ccnt, __popc(m));
        cb = __shfl_sync(0xFFFFFFFFu, cb, 0);
        if (pred) {
            const int pos = cb + __popc(m & lane_lt);
            if (pos < SK_CMAX) crow[pos] = (unsigned short)j;
        }
    }
    __syncthreads();
    if (tid == 0)
        ccnt[row] = (s_ccnt <= SK_CMAX) ? s_ccnt : SENTINEL;
}

// ---------------------------------------------------------------------------
// Kernel 4b: per-row exact dots (frozen ascending-k fmaf bit chain) + exact
// radix select + jax tie rule + scatter writes.
// ---------------------------------------------------------------------------
#define SK_THREADS 256
#define SK_OFF_VAL  2048
#define SK_OFF_CAND 18432
#define SK_OFF_HIST 26688
#define SK_OFF_WS   27712
#define SK_SMEM     27776

__global__ void __launch_bounds__(SK_THREADS, 6) select_kernel(
    const unsigned short* __restrict__ cand,
    const int*            __restrict__ ccnt,
    const float*          __restrict__ H,
    float*                __restrict__ out,
    int N, int Kd)
{
    const int row = blockIdx.x;
    const int cnt = ccnt[row];
    if (cnt == 0 || cnt > SK_CMAX) return;

    extern __shared__ __align__(16) unsigned char sm[];
    float*          s_hrow = reinterpret_cast<float*>(sm);                   // [512]
    float*          s_val  = reinterpret_cast<float*>(sm + SK_OFF_VAL);      // [CMAX]
    unsigned short* s_cand = reinterpret_cast<unsigned short*>(sm + SK_OFF_CAND);
    unsigned*       s_hist = reinterpret_cast<unsigned*>(sm + SK_OFF_HIST);  // [256]
    unsigned*       s_wsum = reinterpret_cast<unsigned*>(sm + SK_OFF_WS);    // [8]
    unsigned*       s_wexc = s_wsum + 8;                                     // [8]
    __shared__ int s_b, s_rank, s_cnt;

    const int tid = threadIdx.x;
    const size_t abase = (size_t)row * N;

    if (tid < Kd / 4)
        reinterpret_cast<float4*>(s_hrow)[tid] =
            reinterpret_cast<const float4*>(H + (size_t)row * Kd)[tid];
    {
        const unsigned short* crow = cand + (size_t)row * SK_CMAX;
        for (int c = tid; c < cnt; c += SK_THREADS) s_cand[c] = crow[c];
    }
    __syncthreads();

    // exact dots (ascending-k single-accumulator fmaf == frozen bit chain)
    for (int c = tid; c < cnt; c += SK_THREADS) {
        const int j = s_cand[c];
        const float4* b4 = reinterpret_cast<const float4*>(H + (size_t)j * Kd);
        float acc = 0.0f;
#pragma unroll 4
        for (int k4 = 0; k4 < NHEDGES / 4; k4++) {
            const float4 bv = __ldg(&b4[k4]);
            const float4 av = *reinterpret_cast<const float4*>(&s_hrow[k4 * 4]);
            acc = fmaf(av.x, bv.x, acc);
            acc = fmaf(av.y, bv.y, acc);
            acc = fmaf(av.z, bv.z, acc);
            acc = fmaf(av.w, bv.w, acc);
        }
        s_val[c] = acc;
    }
    __syncthreads();

    // exact threshold: 4x8-bit radix among candidates (== 32nd overall)
    unsigned prefix = 0u;
    int rank = TOPK, cntEq = 0;
    for (int shift = 24; shift >= 0; shift -= 8) {
        s_hist[tid] = 0u;
        __syncthreads();
        const unsigned hm = (shift == 24) ? 0u : (0xFFFFFFFFu << (shift + 8));
        for (int c = tid; c < cnt; c += SK_THREADS) {
            const unsigned k = __float_as_uint(s_val[c]);
            if ((k & hm) == prefix)
                atomicAdd(&s_hist[(k >> shift) & 0xFFu], 1u);
        }
        __syncthreads();
        select256_fn(s_hist, s_wsum, s_wexc, &s_b, &s_rank, &s_cnt, rank, tid);
        prefix |= ((unsigned)s_b << shift);
        rank  = s_rank;
        cntEq = s_cnt;
        __syncthreads();
    }
    const float Tval = __uint_as_float(prefix);

    if (cntEq > rank) {
        // jax tie rule: keep `rank` tied entries with smallest column j.
        if (tid == 0) {
            for (int c = 0; c < cnt; c++)
                if (__float_as_uint(s_val[c]) == prefix) s_val[c] = -2.0f;
            for (int it = 0; it < rank; it++) {
                int bestc = -1, bestj = 0x7FFFFFFF;
                for (int c = 0; c < cnt; c++)
                    if (s_val[c] == -2.0f && (int)s_cand[c] < bestj) {
                        bestj = s_cand[c]; bestc = c;
                    }
                s_val[bestc] = Tval;
            }
            for (int c = 0; c < cnt; c++)
                if (s_val[c] == -2.0f) s_val[c] = -1.0f;
        }
        __syncthreads();
    }

    for (int c = tid; c < cnt; c += SK_THREADS) {
        const float v = s_val[c];
        if (v >= Tval) out[abase + s_cand[c]] = v;
    }
}

// ---------------------------------------------------------------------------
// Kernel 4c: full-exact fallback for sentinel rows (early-exit otherwise).
// ---------------------------------------------------------------------------
#define FB_SMEM (NNODES * 4 + NHEDGES * 4 + 256 * 4 + 64)

__global__ void __launch_bounds__(256, 2) fallback_kernel(
    const int*   __restrict__ ccnt,
    const float* __restrict__ H,
    float*       __restrict__ out,
    int N, int Kd)
{
    const int row = blockIdx.x;
    if (ccnt[row] != SENTINEL) return;

    extern __shared__ __align__(16) unsigned char sm[];
    float*    s_row  = reinterpret_cast<float*>(sm);                        // [N]
    float*    s_hrow = reinterpret_cast<float*>(sm + NNODES * 4);           // [512]
    unsigned* s_hist = reinterpret_cast<unsigned*>(sm + NNODES * 4 + NHEDGES * 4);
    unsigned* s_wsum = s_hist + 256;
    unsigned* s_wexc = s_wsum + 8;
    __shared__ int s_b, s_rank, s_cnt;

    const int tid = threadIdx.x;
    const size_t abase = (size_t)row * N;

    if (tid < Kd / 4)
        reinterpret_cast<float4*>(s_hrow)[tid] =
            reinterpret_cast<const float4*>(H + (size_t)row * Kd)[tid];
    __syncthreads();

    for (int j = tid; j < N; j += 256) {
        const float4* b4 = reinterpret_cast<const float4*>(H + (size_t)j * Kd);
        float acc = 0.0f;
#pragma unroll 4
        for (int k4 = 0; k4 < NHEDGES / 4; k4++) {
            const float4 bv = __ldg(&b4[k4]);
            const float4 av = *reinterpret_cast<const float4*>(&s_hrow[k4 * 4]);
            acc = fmaf(av.x, bv.x, acc);
            acc = fmaf(av.y, bv.y, acc);
            acc = fmaf(av.z, bv.z, acc);
            acc = fmaf(av.w, bv.w, acc);
        }
        s_row[j] = acc;
    }
    __syncthreads();

    unsigned prefix = 0u;
    int rank = TOPK, cntEq = 0;
    for (int shift = 24; shift >= 0; shift -= 8) {
        s_hist[tid] = 0u;
        __syncthreads();
        const unsigned hm = (shift == 24) ? 0u : (0xFFFFFFFFu << (shift + 8));
        for (int j = tid; j < N; j += 256) {
            const unsigned k = __float_as_uint(s_row[j]);
            if ((k & hm) == prefix)
                atomicAdd(&s_hist[(k >> shift) & 0xFFu], 1u);
        }
        __syncthreads();
        select256_fn(s_hist, s_wsum, s_wexc, &s_b, &s_rank, &s_cnt, rank, tid);
        prefix |= ((unsigned)s_b << shift);
        rank  = s_rank;
        cntEq = s_cnt;
        __syncthreads();
    }
    const float Tval = __uint_as_float(prefix);

    if (cntEq > rank) {
        if (tid == 0) {
            int kept = 0;
            for (int j = 0; j < N; j++) {
                if (__float_as_uint(s_row[j]) == prefix) {
                    kept++;
                    if (kept > rank) s_row[j] = -1.0f;
                }
            }
        }
        __syncthreads();
    }

    for (int j = tid; j < N; j += 256) {
        const float v = s_row[j];
        out[abase + j] = (v >= Tval) ? v : 0.0f;
    }
}

// ---------------------------------------------------------------------------
// kernel_launch
// ---------------------------------------------------------------------------
extern "C" void kernel_launch(void* const* d_in, const int* in_sizes, int n_in,
                              void* d_out, int out_size)
{
    (void)in_sizes; (void)n_in; (void)out_size;

    const int*   idx   = (const int*)  d_in[0];
    const float* embn  = (const float*)d_in[1];
    const float* embhe = (const float*)d_in[2];
    const float* W1    = (const float*)d_in[3];
    const float* b1    = (const float*)d_in[4];
    const float* W2    = (const float*)d_in[5];
    const float* b2    = (const float*)d_in[6];
    float*       out   = (float*)d_out;

    float *p_nv1 = nullptr, *p_nv2 = nullptr, *p_H = nullptr;
    __half *p_Hhf = nullptr, *p_Ahf = nullptr;
    unsigned short *p_cand = nullptr;
    int *p_ccnt = nullptr;
    cudaGetSymbolAddress((void**)&p_nv1,  g_nv1);
    cudaGetSymbolAddress((void**)&p_nv2,  g_nv2);
    cudaGetSymbolAddress((void**)&p_H,    g_H);
    cudaGetSymbolAddress((void**)&p_Hhf,  g_Hhf);
    cudaGetSymbolAddress((void**)&p_Ahf,  g_Ahf);
    cudaGetSymbolAddress((void**)&p_cand, g_cand);
    cudaGetSymbolAddress((void**)&p_ccnt, g_ccnt);

    cudaFuncSetAttribute(nodevec_kernel,
                         cudaFuncAttributeMaxDynamicSharedMemorySize, NV_SMEM);
    cudaFuncSetAttribute(approx_mma_kernel,
                         cudaFuncAttributeMaxDynamicSharedMemorySize, ASMEM);
    cudaFuncSetAttribute(cand_kernel,
                         cudaFuncAttributeMaxDynamicSharedMemorySize, CK_SMEM);
    cudaFuncSetAttribute(select_kernel,
                         cudaFuncAttributeMaxDynamicSharedMemorySize, SK_SMEM);
    cudaFuncSetAttribute(fallback_kernel,
                         cudaFuncAttributeMaxDynamicSharedMemorySize, FB_SMEM);

    // 1) nodevecs
    nodevec_kernel<<<NNODES / NV_ROWS, EDIM, NV_SMEM>>>(embn, idx, W1, b1,
                                                        p_nv1, NNODES);
    nodevec_kernel<<<NHEDGES / NV_ROWS, EDIM, NV_SMEM>>>(embhe, nullptr, W2, b2,
                                                         p_nv2, NHEDGES);

    // 2) H (fp32, frozen bit-path) + fp16 copy
    {
        dim3 grid((NHEDGES + GT_TM - 1) / GT_TM, (NNODES + GT_TM - 1) / GT_TM);
        h_gemm_kernel<<<grid, 256>>>(p_nv1, p_nv2, p_H, p_Hhf,
                                     NNODES, NHEDGES, EDIM);
    }

    // 3) approx adj = fp16(Hhf @ Hhf^T), K-chunk 64
    {
        const int nt = (NNODES + GT_TM - 1) / GT_TM;
        dim3 grid(nt, nt);
        approx_mma_kernel<<<grid, 256, ASMEM>>>(p_Hhf, p_Ahf, NNODES, NHEDGES);
    }

    // 4) certified top-32 pipeline: candidates -> exact select -> fallback
    cand_kernel<<<NNODES, CK_THREADS, CK_SMEM>>>(p_Ahf, out, p_cand, p_ccnt,
                                                 NNODES);
    select_kernel<<<NNODES, SK_THREADS, SK_SMEM>>>(p_cand, p_ccnt, p_H, out,
                                                   NNODES, NHEDGES);
    fallback_kernel<<<NNODES, 256, FB_SMEM>>>(p_ccnt, p_H, out,
                                              NNODES, NHEDGES);
}